// round 1
// baseline (speedup 1.0000x reference)
#include <cuda_runtime.h>
#include <math.h>

// ---------------- problem constants ----------------
#define BATCH 32
#define HIMG  56
#define CDIM  384
#define NTOK  49          // 7*7 tokens per window
#define NWIN  64          // 8*8 windows per image
#define NROWS 100352      // BATCH * NWIN * NTOK
#define C3    1152
#define HIDD  1536
#define HEADS 12
#define HD    32
#define SHIFT 3

// ---------------- scratch (static device, no allocs) ----------------
__device__ float g_xw [(size_t)NROWS * CDIM]; // LN1+shift+partition output
__device__ float g_qkv[(size_t)NROWS * C3];   // qkv
__device__ float g_att[(size_t)NROWS * CDIM]; // attention output (window layout)
__device__ float g_xn2[(size_t)NROWS * CDIM]; // LN2 output
__device__ float g_hid[(size_t)NROWS * HIDD]; // MLP hidden

// ---------------- block reduce ----------------
__device__ __forceinline__ float blockReduceSum128(float v, float* sh) {
    #pragma unroll
    for (int o = 16; o > 0; o >>= 1) v += __shfl_xor_sync(0xffffffffu, v, o);
    int warp = threadIdx.x >> 5, lane = threadIdx.x & 31;
    if (lane == 0) sh[warp] = v;
    __syncthreads();
    float r;
    if (warp == 0) {
        float t = (lane < 4) ? sh[lane] : 0.f;
        #pragma unroll
        for (int o = 2; o > 0; o >>= 1) t += __shfl_xor_sync(0xffffffffu, t, o);
        if (lane == 0) sh[0] = t;
    }
    __syncthreads();
    r = sh[0];
    __syncthreads();   // protect sh for reuse
    return r;
}

// ---------------- LN1 + cyclic shift + window partition ----------------
// one block (128 thr) per output token row m in window layout
__global__ __launch_bounds__(128) void k_ln1(const float* __restrict__ x,
                                             const float* __restrict__ w,
                                             const float* __restrict__ b,
                                             float* __restrict__ dst_all) {
    __shared__ float sh[32];
    int m   = blockIdx.x;
    int win = m / NTOK, n = m % NTOK;
    int bb = win >> 6, wi = win & 63;
    int wr = wi >> 3, wc = wi & 7;
    int rs = wr * 7 + n / 7, cs = wc * 7 + n % 7;     // shifted coords
    int r  = (rs + SHIFT) % HIMG, c = (cs + SHIFT) % HIMG; // original coords
    const float* src = x + ((size_t)bb * (HIMG * HIMG) + r * HIMG + c) * CDIM;
    int t = threadIdx.x;
    float v0 = src[t], v1 = src[t + 128], v2 = src[t + 256];
    float s  = blockReduceSum128(v0 + v1 + v2, sh);
    float s2 = blockReduceSum128(v0 * v0 + v1 * v1 + v2 * v2, sh);
    float mean = s * (1.f / CDIM);
    float var  = s2 * (1.f / CDIM) - mean * mean;
    float rstd = rsqrtf(var + 1e-5f);
    float* dst = dst_all + (size_t)m * CDIM;
    dst[t]       = (v0 - mean) * rstd * w[t]       + b[t];
    dst[t + 128] = (v1 - mean) * rstd * w[t + 128] + b[t + 128];
    dst[t + 256] = (v2 - mean) * rstd * w[t + 256] + b[t + 256];
}

// ---------------- LN2 (plain rows) ----------------
__global__ __launch_bounds__(128) void k_ln2(const float* __restrict__ x2,
                                             const float* __restrict__ w,
                                             const float* __restrict__ b,
                                             float* __restrict__ dst_all) {
    __shared__ float sh[32];
    int m = blockIdx.x;
    const float* src = x2 + (size_t)m * CDIM;
    int t = threadIdx.x;
    float v0 = src[t], v1 = src[t + 128], v2 = src[t + 256];
    float s  = blockReduceSum128(v0 + v1 + v2, sh);
    float s2 = blockReduceSum128(v0 * v0 + v1 * v1 + v2 * v2, sh);
    float mean = s * (1.f / CDIM);
    float var  = s2 * (1.f / CDIM) - mean * mean;
    float rstd = rsqrtf(var + 1e-5f);
    float* dst = dst_all + (size_t)m * CDIM;
    dst[t]       = (v0 - mean) * rstd * w[t]       + b[t];
    dst[t + 128] = (v1 - mean) * rstd * w[t + 128] + b[t + 128];
    dst[t + 256] = (v2 - mean) * rstd * w[t + 256] + b[t + 256];
}

// ---------------- tiled SGEMM 128x128x8, 256 thr, 8x8 microtile ----------------
// EPI: 0 = bias store, 1 = bias+gelu store, 2 = bias + window-reverse/unshift
//      scatter + residual(res) store, 3 = bias + res add (row-major) store
template<int EPI>
__global__ __launch_bounds__(256) void k_sgemm(const float* __restrict__ A,
                                               const float* __restrict__ B,
                                               const float* __restrict__ bias,
                                               float* __restrict__ Cout,
                                               int K, int N,
                                               const float* __restrict__ res) {
    __shared__ __align__(16) float As[8][128];
    __shared__ __align__(16) float Bs[8][128];
    int tid = threadIdx.x;
    const float* Ab = A + (size_t)blockIdx.y * 128 * K;
    const float* Bb = B + blockIdx.x * 128;
    float acc[8][8];
    #pragma unroll
    for (int i = 0; i < 8; i++)
        #pragma unroll
        for (int j = 0; j < 8; j++) acc[i][j] = 0.f;

    int aRow = tid >> 1, aCol = (tid & 1) * 4;
    int bRow = tid >> 5, bCol = (tid & 31) * 4;
    int tm = (tid >> 4) << 3, tn = (tid & 15) << 3;

    for (int k0 = 0; k0 < K; k0 += 8) {
        float4 a4 = *(const float4*)(Ab + (size_t)aRow * K + k0 + aCol);
        As[aCol + 0][aRow] = a4.x;
        As[aCol + 1][aRow] = a4.y;
        As[aCol + 2][aRow] = a4.z;
        As[aCol + 3][aRow] = a4.w;
        *(float4*)(&Bs[bRow][bCol]) = *(const float4*)(Bb + (size_t)(k0 + bRow) * N + bCol);
        __syncthreads();
        #pragma unroll
        for (int k = 0; k < 8; k++) {
            float ra[8], rb[8];
            #pragma unroll
            for (int i = 0; i < 8; i++) ra[i] = As[k][tm + i];
            #pragma unroll
            for (int j = 0; j < 8; j++) rb[j] = Bs[k][tn + j];
            #pragma unroll
            for (int i = 0; i < 8; i++)
                #pragma unroll
                for (int j = 0; j < 8; j++) acc[i][j] += ra[i] * rb[j];
        }
        __syncthreads();
    }

    int colBase = blockIdx.x * 128 + tn;
    size_t rowBase = (size_t)blockIdx.y * 128 + tm;
    #pragma unroll
    for (int i = 0; i < 8; i++) {
        size_t row = rowBase + i;
        size_t dstRow = 0;
        if (EPI == 2) {
            int win = (int)(row / NTOK), n = (int)(row % NTOK);
            int bb = win >> 6, wi = win & 63;
            int wr = wi >> 3, wc = wi & 7;
            int rs = wr * 7 + n / 7, cs = wc * 7 + n % 7;
            int r  = (rs + SHIFT) % HIMG, cgl = (cs + SHIFT) % HIMG;
            dstRow = ((size_t)bb * (HIMG * HIMG) + r * HIMG + cgl) * CDIM;
        }
        #pragma unroll
        for (int j = 0; j < 8; j++) {
            int col = colBase + j;
            float v = acc[i][j] + bias[col];
            if (EPI == 0) {
                Cout[row * N + col] = v;
            } else if (EPI == 1) {
                Cout[row * N + col] = 0.5f * v * (1.0f + erff(v * 0.70710678118654752f));
            } else if (EPI == 2) {
                Cout[dstRow + col] = res[dstRow + col] + v;
            } else {
                size_t o = row * N + col;
                Cout[o] = res[o] + v;
            }
        }
    }
}

// ---------------- windowed attention: one block per (window, head) ----------------
__global__ __launch_bounds__(256) void k_attn(const float* __restrict__ qkv,
                                              const float* __restrict__ rpb,
                                              float* __restrict__ out) {
    __shared__ __align__(16) float q [NTOK][HD];
    __shared__ __align__(16) float kk[NTOK][HD];
    __shared__ __align__(16) float vv[NTOK][HD];
    __shared__ float s[NTOK][NTOK + 1];
    __shared__ int   lab[NTOK];

    int w = blockIdx.x;      // 0..2047
    int h = blockIdx.y;      // 0..11
    int tid = threadIdx.x;
    const float scale = 0.17677669529663689f; // 32^-0.5

    size_t base = (size_t)w * NTOK * C3 + h * HD;
    for (int idx = tid; idx < NTOK * HD; idx += 256) {
        int n = idx >> 5, d = idx & 31;
        size_t rb = base + (size_t)n * C3 + d;
        q [n][d] = qkv[rb] * scale;
        kk[n][d] = qkv[rb + CDIM];
        vv[n][d] = qkv[rb + 2 * CDIM];
    }
    if (tid < NTOK) {
        int wi = w & 63, wr = wi >> 3, wc = wi & 7;
        int rs = wr * 7 + tid / 7, cs = wc * 7 + tid % 7;
        int rr = (rs < HIMG - 7) ? 0 : ((rs < HIMG - SHIFT) ? 1 : 2);
        int cc = (cs < HIMG - 7) ? 0 : ((cs < HIMG - SHIFT) ? 1 : 2);
        lab[tid] = rr * 3 + cc;
    }
    __syncthreads();

    // scores + bias + mask
    for (int idx = tid; idx < NTOK * NTOK; idx += 256) {
        int i = idx / NTOK, j = idx % NTOK;
        const float4* qa = (const float4*)q[i];
        const float4* kb = (const float4*)kk[j];
        float acc = 0.f;
        #pragma unroll
        for (int t = 0; t < HD / 4; t++) {
            float4 a = qa[t], bq = kb[t];
            acc += a.x * bq.x + a.y * bq.y + a.z * bq.z + a.w * bq.w;
        }
        int ri = i / 7, ci = i % 7, rj = j / 7, cj = j % 7;
        int bidx = (ri - rj + 6) * 13 + (ci - cj + 6);
        acc += rpb[bidx * HEADS + h];
        if (lab[i] != lab[j]) acc -= 100.0f;
        s[i][j] = acc;
    }
    __syncthreads();

    // softmax: one warp per row, rows strided by 8
    int warp = tid >> 5, lane = tid & 31;
    for (int i = warp; i < NTOK; i += 8) {
        float v0 = s[i][lane];
        float v1 = (lane + 32 < NTOK) ? s[i][lane + 32] : -1e30f;
        float mx = fmaxf(v0, v1);
        #pragma unroll
        for (int o = 16; o > 0; o >>= 1) mx = fmaxf(mx, __shfl_xor_sync(0xffffffffu, mx, o));
        float e0 = __expf(v0 - mx);
        float e1 = (lane + 32 < NTOK) ? __expf(v1 - mx) : 0.f;
        float sum = e0 + e1;
        #pragma unroll
        for (int o = 16; o > 0; o >>= 1) sum += __shfl_xor_sync(0xffffffffu, sum, o);
        float inv = 1.f / sum;
        s[i][lane] = e0 * inv;
        if (lane + 32 < NTOK) s[i][lane + 32] = e1 * inv;
    }
    __syncthreads();

    // P @ V
    for (int idx = tid; idx < NTOK * HD; idx += 256) {
        int i = idx >> 5, d = idx & 31;
        float acc = 0.f;
        #pragma unroll
        for (int j = 0; j < NTOK; j++) acc += s[i][j] * vv[j][d];
        out[((size_t)w * NTOK + i) * CDIM + h * HD + d] = acc;
    }
}

// ---------------- launch ----------------
extern "C" void kernel_launch(void* const* d_in, const int* in_sizes, int n_in,
                              void* d_out, int out_size) {
    const float* x      = (const float*)d_in[0];
    const float* n1w    = (const float*)d_in[1];
    const float* n1b    = (const float*)d_in[2];
    const float* qkvw   = (const float*)d_in[3];
    const float* qkvb   = (const float*)d_in[4];
    const float* rpb    = (const float*)d_in[5];
    const float* projw  = (const float*)d_in[6];
    const float* projb  = (const float*)d_in[7];
    const float* n2w    = (const float*)d_in[8];
    const float* n2b    = (const float*)d_in[9];
    const float* fc1w   = (const float*)d_in[10];
    const float* fc1b   = (const float*)d_in[11];
    const float* fc2w   = (const float*)d_in[12];
    const float* fc2b   = (const float*)d_in[13];
    float* out = (float*)d_out;

    float *p_xw, *p_qkv, *p_att, *p_xn2, *p_hid;
    cudaGetSymbolAddress((void**)&p_xw,  g_xw);
    cudaGetSymbolAddress((void**)&p_qkv, g_qkv);
    cudaGetSymbolAddress((void**)&p_att, g_att);
    cudaGetSymbolAddress((void**)&p_xn2, g_xn2);
    cudaGetSymbolAddress((void**)&p_hid, g_hid);

    // 1) LN1 + shift + partition
    k_ln1<<<NROWS, 128>>>(x, n1w, n1b, p_xw);
    // 2) qkv = xw @ qkv_w + b        (100352 x 1152, K=384)
    k_sgemm<0><<<dim3(C3 / 128, NROWS / 128), 256>>>(p_xw, qkvw, qkvb, p_qkv, CDIM, C3, nullptr);
    // 3) windowed attention
    k_attn<<<dim3(NROWS / NTOK, HEADS), 256>>>(p_qkv, rpb, p_att);
    // 4) proj + window reverse + unshift + residual -> d_out holds x2
    k_sgemm<2><<<dim3(CDIM / 128, NROWS / 128), 256>>>(p_att, projw, projb, out, CDIM, CDIM, x);
    // 5) LN2
    k_ln2<<<NROWS, 128>>>(out, n2w, n2b, p_xn2);
    // 6) fc1 + gelu                  (100352 x 1536, K=384)
    k_sgemm<1><<<dim3(HIDD / 128, NROWS / 128), 256>>>(p_xn2, fc1w, fc1b, p_hid, CDIM, HIDD, nullptr);
    // 7) fc2 + residual into d_out   (100352 x 384, K=1536)
    k_sgemm<3><<<dim3(CDIM / 128, NROWS / 128), 256>>>(p_hid, fc2w, fc2b, out, HIDD, CDIM, out);
}

// round 2
// speedup vs baseline: 1.8543x; 1.8543x over previous
#include <cuda_runtime.h>
#include <math.h>

// ---------------- problem constants ----------------
#define BATCH 32
#define HIMG  56
#define CDIM  384
#define NTOK  49          // 7*7 tokens per window
#define NWIN  64          // 8*8 windows per image
#define NROWS 100352      // BATCH * NWIN * NTOK
#define C3    1152
#define HIDD  1536
#define HEADS 12
#define HD    32
#define SHIFT 3

// ---------------- scratch (static device, no allocs) ----------------
__device__ float g_xw [(size_t)NROWS * CDIM]; // LN1+shift+partition output
__device__ float g_qkv[(size_t)NROWS * C3];   // qkv
__device__ float g_att[(size_t)NROWS * CDIM]; // attention output (window layout)
__device__ float g_xn2[(size_t)NROWS * CDIM]; // LN2 output
__device__ float g_hid[(size_t)NROWS * HIDD]; // MLP hidden

// ---------------- block reduce ----------------
__device__ __forceinline__ float blockReduceSum128(float v, float* sh) {
    #pragma unroll
    for (int o = 16; o > 0; o >>= 1) v += __shfl_xor_sync(0xffffffffu, v, o);
    int warp = threadIdx.x >> 5, lane = threadIdx.x & 31;
    if (lane == 0) sh[warp] = v;
    __syncthreads();
    float r;
    if (warp == 0) {
        float t = (lane < 4) ? sh[lane] : 0.f;
        #pragma unroll
        for (int o = 2; o > 0; o >>= 1) t += __shfl_xor_sync(0xffffffffu, t, o);
        if (lane == 0) sh[0] = t;
    }
    __syncthreads();
    r = sh[0];
    __syncthreads();
    return r;
}

// ---------------- LN1 + cyclic shift + window partition ----------------
__global__ __launch_bounds__(128) void k_ln1(const float* __restrict__ x,
                                             const float* __restrict__ w,
                                             const float* __restrict__ b,
                                             float* __restrict__ dst_all) {
    __shared__ float sh[32];
    int m   = blockIdx.x;
    int win = m / NTOK, n = m % NTOK;
    int bb = win >> 6, wi = win & 63;
    int wr = wi >> 3, wc = wi & 7;
    int rs = wr * 7 + n / 7, cs = wc * 7 + n % 7;
    int r  = (rs + SHIFT) % HIMG, c = (cs + SHIFT) % HIMG;
    const float* src = x + ((size_t)bb * (HIMG * HIMG) + r * HIMG + c) * CDIM;
    int t = threadIdx.x;
    float v0 = src[t], v1 = src[t + 128], v2 = src[t + 256];
    float s  = blockReduceSum128(v0 + v1 + v2, sh);
    float s2 = blockReduceSum128(v0 * v0 + v1 * v1 + v2 * v2, sh);
    float mean = s * (1.f / CDIM);
    float var  = s2 * (1.f / CDIM) - mean * mean;
    float rstd = rsqrtf(var + 1e-5f);
    float* dst = dst_all + (size_t)m * CDIM;
    dst[t]       = (v0 - mean) * rstd * w[t]       + b[t];
    dst[t + 128] = (v1 - mean) * rstd * w[t + 128] + b[t + 128];
    dst[t + 256] = (v2 - mean) * rstd * w[t + 256] + b[t + 256];
}

// ---------------- LN2 (plain rows) ----------------
__global__ __launch_bounds__(128) void k_ln2(const float* __restrict__ x2,
                                             const float* __restrict__ w,
                                             const float* __restrict__ b,
                                             float* __restrict__ dst_all) {
    __shared__ float sh[32];
    int m = blockIdx.x;
    const float* src = x2 + (size_t)m * CDIM;
    int t = threadIdx.x;
    float v0 = src[t], v1 = src[t + 128], v2 = src[t + 256];
    float s  = blockReduceSum128(v0 + v1 + v2, sh);
    float s2 = blockReduceSum128(v0 * v0 + v1 * v1 + v2 * v2, sh);
    float mean = s * (1.f / CDIM);
    float var  = s2 * (1.f / CDIM) - mean * mean;
    float rstd = rsqrtf(var + 1e-5f);
    float* dst = dst_all + (size_t)m * CDIM;
    dst[t]       = (v0 - mean) * rstd * w[t]       + b[t];
    dst[t + 128] = (v1 - mean) * rstd * w[t + 128] + b[t + 128];
    dst[t + 256] = (v2 - mean) * rstd * w[t + 256] + b[t + 256];
}

// ---------------- tf32 helpers ----------------
__device__ __forceinline__ unsigned f2tf(float f) {
    unsigned u;
    asm("cvt.rna.tf32.f32 %0, %1;" : "=r"(u) : "f"(f));
    return u;
}

__device__ __forceinline__ void mma_tf32(float c[4], const unsigned a[4], const unsigned b[2]) {
    asm volatile("mma.sync.aligned.m16n8k8.row.col.f32.tf32.tf32.f32 "
                 "{%0,%1,%2,%3}, {%4,%5,%6,%7}, {%8,%9}, {%0,%1,%2,%3};"
                 : "+f"(c[0]), "+f"(c[1]), "+f"(c[2]), "+f"(c[3])
                 : "r"(a[0]), "r"(a[1]), "r"(a[2]), "r"(a[3]),
                   "r"(b[0]), "r"(b[1]));
}

// ---------------- TF32 tensor-core GEMM 128x128x16, 256 thr (8 warps 2x4) ----
// EPI: 0 = bias, 1 = bias+gelu, 2 = bias + window-reverse/unshift + residual
//      scatter, 3 = bias + residual (row-major)
#define SPAD 136
template<int EPI>
__global__ __launch_bounds__(256) void k_tgemm(const float* __restrict__ A,
                                               const float* __restrict__ B,
                                               const float* __restrict__ bias,
                                               float* __restrict__ Cout,
                                               int K, int N,
                                               const float* __restrict__ res) {
    __shared__ __align__(16) unsigned As[16][SPAD];
    __shared__ __align__(16) unsigned Bs[16][SPAD];
    int tid = threadIdx.x;
    int warp = tid >> 5, lane = tid & 31;
    int gid = lane >> 2, tig = lane & 3;
    int mW = (warp >> 2) * 64;     // warp row offset within 128
    int nW = (warp & 3) * 32;      // warp col offset within 128

    const float* Ab = A + (size_t)blockIdx.y * 128 * K;
    const float* Bb = B + blockIdx.x * 128;

    float acc[4][4][4];
    #pragma unroll
    for (int mi = 0; mi < 4; mi++)
        #pragma unroll
        for (int ni = 0; ni < 4; ni++)
            #pragma unroll
            for (int r = 0; r < 4; r++) acc[mi][ni][r] = 0.f;

    int aRow = tid >> 1, aCol = (tid & 1) * 8;
    int bRow = tid >> 4, bCol = (tid & 15) * 8;

    for (int k0 = 0; k0 < K; k0 += 16) {
        // load A tile (128x16), transpose to As[k][m], cvt tf32
        {
            const float* p = Ab + (size_t)aRow * K + k0 + aCol;
            float4 x0 = *(const float4*)p;
            float4 x1 = *(const float4*)(p + 4);
            As[aCol + 0][aRow] = f2tf(x0.x);
            As[aCol + 1][aRow] = f2tf(x0.y);
            As[aCol + 2][aRow] = f2tf(x0.z);
            As[aCol + 3][aRow] = f2tf(x0.w);
            As[aCol + 4][aRow] = f2tf(x1.x);
            As[aCol + 5][aRow] = f2tf(x1.y);
            As[aCol + 6][aRow] = f2tf(x1.z);
            As[aCol + 7][aRow] = f2tf(x1.w);
        }
        // load B tile (16x128), cvt tf32
        {
            const float* p = Bb + (size_t)(k0 + bRow) * N + bCol;
            float4 x0 = *(const float4*)p;
            float4 x1 = *(const float4*)(p + 4);
            uint4 y0 = make_uint4(f2tf(x0.x), f2tf(x0.y), f2tf(x0.z), f2tf(x0.w));
            uint4 y1 = make_uint4(f2tf(x1.x), f2tf(x1.y), f2tf(x1.z), f2tf(x1.w));
            *(uint4*)(&Bs[bRow][bCol])     = y0;
            *(uint4*)(&Bs[bRow][bCol + 4]) = y1;
        }
        __syncthreads();

        #pragma unroll
        for (int ks = 0; ks < 16; ks += 8) {
            unsigned a[4][4], b[4][2];
            #pragma unroll
            for (int mi = 0; mi < 4; mi++) {
                int m0 = mW + mi * 16 + gid;
                a[mi][0] = As[ks + tig][m0];
                a[mi][1] = As[ks + tig][m0 + 8];
                a[mi][2] = As[ks + tig + 4][m0];
                a[mi][3] = As[ks + tig + 4][m0 + 8];
            }
            #pragma unroll
            for (int ni = 0; ni < 4; ni++) {
                int n0 = nW + ni * 8 + gid;
                b[ni][0] = Bs[ks + tig][n0];
                b[ni][1] = Bs[ks + tig + 4][n0];
            }
            #pragma unroll
            for (int mi = 0; mi < 4; mi++)
                #pragma unroll
                for (int ni = 0; ni < 4; ni++)
                    mma_tf32(acc[mi][ni], a[mi], b[ni]);
        }
        __syncthreads();
    }

    // ---------------- epilogue ----------------
    size_t rowBase = (size_t)blockIdx.y * 128 + mW;
    int colBase = blockIdx.x * 128 + nW;
    #pragma unroll
    for (int mi = 0; mi < 4; mi++) {
        #pragma unroll
        for (int half = 0; half < 2; half++) {
            size_t row = rowBase + mi * 16 + gid + half * 8;
            size_t dstRow = 0;
            if (EPI == 2) {
                int win = (int)(row / NTOK), n = (int)(row % NTOK);
                int bb = win >> 6, wi = win & 63;
                int wr = wi >> 3, wc = wi & 7;
                int rs = wr * 7 + n / 7, cs = wc * 7 + n % 7;
                int r  = (rs + SHIFT) % HIMG, cg = (cs + SHIFT) % HIMG;
                dstRow = ((size_t)bb * (HIMG * HIMG) + r * HIMG + cg) * CDIM;
            }
            #pragma unroll
            for (int ni = 0; ni < 4; ni++) {
                int col = colBase + ni * 8 + tig * 2;
                float v0 = acc[mi][ni][half * 2]     + bias[col];
                float v1 = acc[mi][ni][half * 2 + 1] + bias[col + 1];
                if (EPI == 0) {
                    *(float2*)(&Cout[row * N + col]) = make_float2(v0, v1);
                } else if (EPI == 1) {
                    v0 = 0.5f * v0 * (1.0f + erff(v0 * 0.70710678118654752f));
                    v1 = 0.5f * v1 * (1.0f + erff(v1 * 0.70710678118654752f));
                    *(float2*)(&Cout[row * N + col]) = make_float2(v0, v1);
                } else if (EPI == 2) {
                    float2 rr = *(const float2*)(&res[dstRow + col]);
                    *(float2*)(&Cout[dstRow + col]) = make_float2(rr.x + v0, rr.y + v1);
                } else {
                    size_t o = row * N + col;
                    float2 rr = *(const float2*)(&Cout[o]);
                    (void)rr;
                    float2 rv = *(const float2*)(&res[o]);
                    *(float2*)(&Cout[o]) = make_float2(rv.x + v0, rv.y + v1);
                }
            }
        }
    }
}

// ---------------- windowed attention: one block per (window, head) ----------------
__global__ __launch_bounds__(256) void k_attn(const float* __restrict__ qkv,
                                              const float* __restrict__ rpb,
                                              float* __restrict__ out) {
    __shared__ __align__(16) float q [NTOK][HD];
    __shared__ __align__(16) float kk[NTOK][HD];
    __shared__ __align__(16) float vv[NTOK][HD];
    __shared__ float s[NTOK][NTOK + 1];
    __shared__ int   lab[NTOK];

    int w = blockIdx.x;
    int h = blockIdx.y;
    int tid = threadIdx.x;
    const float scale = 0.17677669529663689f; // 32^-0.5

    size_t base = (size_t)w * NTOK * C3 + h * HD;
    for (int idx = tid; idx < NTOK * HD; idx += 256) {
        int n = idx >> 5, d = idx & 31;
        size_t rb = base + (size_t)n * C3 + d;
        q [n][d] = qkv[rb] * scale;
        kk[n][d] = qkv[rb + CDIM];
        vv[n][d] = qkv[rb + 2 * CDIM];
    }
    if (tid < NTOK) {
        int wi = w & 63, wr = wi >> 3, wc = wi & 7;
        int rs = wr * 7 + tid / 7, cs = wc * 7 + tid % 7;
        int rr = (rs < HIMG - 7) ? 0 : ((rs < HIMG - SHIFT) ? 1 : 2);
        int cc = (cs < HIMG - 7) ? 0 : ((cs < HIMG - SHIFT) ? 1 : 2);
        lab[tid] = rr * 3 + cc;
    }
    __syncthreads();

    for (int idx = tid; idx < NTOK * NTOK; idx += 256) {
        int i = idx / NTOK, j = idx % NTOK;
        const float4* qa = (const float4*)q[i];
        const float4* kb = (const float4*)kk[j];
        float acc = 0.f;
        #pragma unroll
        for (int t = 0; t < HD / 4; t++) {
            float4 a = qa[t], bq = kb[t];
            acc += a.x * bq.x + a.y * bq.y + a.z * bq.z + a.w * bq.w;
        }
        int ri = i / 7, ci = i % 7, rj = j / 7, cj = j % 7;
        int bidx = (ri - rj + 6) * 13 + (ci - cj + 6);
        acc += rpb[bidx * HEADS + h];
        if (lab[i] != lab[j]) acc -= 100.0f;
        s[i][j] = acc;
    }
    __syncthreads();

    int warp = tid >> 5, lane = tid & 31;
    for (int i = warp; i < NTOK; i += 8) {
        float v0 = s[i][lane];
        float v1 = (lane + 32 < NTOK) ? s[i][lane + 32] : -1e30f;
        float mx = fmaxf(v0, v1);
        #pragma unroll
        for (int o = 16; o > 0; o >>= 1) mx = fmaxf(mx, __shfl_xor_sync(0xffffffffu, mx, o));
        float e0 = __expf(v0 - mx);
        float e1 = (lane + 32 < NTOK) ? __expf(v1 - mx) : 0.f;
        float sum = e0 + e1;
        #pragma unroll
        for (int o = 16; o > 0; o >>= 1) sum += __shfl_xor_sync(0xffffffffu, sum, o);
        float inv = 1.f / sum;
        s[i][lane] = e0 * inv;
        if (lane + 32 < NTOK) s[i][lane + 32] = e1 * inv;
    }
    __syncthreads();

    for (int idx = tid; idx < NTOK * HD; idx += 256) {
        int i = idx >> 5, d = idx & 31;
        float acc = 0.f;
        #pragma unroll
        for (int j = 0; j < NTOK; j++) acc += s[i][j] * vv[j][d];
        out[((size_t)w * NTOK + i) * CDIM + h * HD + d] = acc;
    }
}

// ---------------- launch ----------------
extern "C" void kernel_launch(void* const* d_in, const int* in_sizes, int n_in,
                              void* d_out, int out_size) {
    const float* x      = (const float*)d_in[0];
    const float* n1w    = (const float*)d_in[1];
    const float* n1b    = (const float*)d_in[2];
    const float* qkvw   = (const float*)d_in[3];
    const float* qkvb   = (const float*)d_in[4];
    const float* rpb    = (const float*)d_in[5];
    const float* projw  = (const float*)d_in[6];
    const float* projb  = (const float*)d_in[7];
    const float* n2w    = (const float*)d_in[8];
    const float* n2b    = (const float*)d_in[9];
    const float* fc1w   = (const float*)d_in[10];
    const float* fc1b   = (const float*)d_in[11];
    const float* fc2w   = (const float*)d_in[12];
    const float* fc2b   = (const float*)d_in[13];
    float* out = (float*)d_out;

    float *p_xw, *p_qkv, *p_att, *p_xn2, *p_hid;
    cudaGetSymbolAddress((void**)&p_xw,  g_xw);
    cudaGetSymbolAddress((void**)&p_qkv, g_qkv);
    cudaGetSymbolAddress((void**)&p_att, g_att);
    cudaGetSymbolAddress((void**)&p_xn2, g_xn2);
    cudaGetSymbolAddress((void**)&p_hid, g_hid);

    // 1) LN1 + shift + partition
    k_ln1<<<NROWS, 128>>>(x, n1w, n1b, p_xw);
    // 2) qkv = xw @ qkv_w + b        (100352 x 1152, K=384)
    k_tgemm<0><<<dim3(C3 / 128, NROWS / 128), 256>>>(p_xw, qkvw, qkvb, p_qkv, CDIM, C3, nullptr);
    // 3) windowed attention
    k_attn<<<dim3(NROWS / NTOK, HEADS), 256>>>(p_qkv, rpb, p_att);
    // 4) proj + window reverse + unshift + residual -> d_out holds x2
    k_tgemm<2><<<dim3(CDIM / 128, NROWS / 128), 256>>>(p_att, projw, projb, out, CDIM, CDIM, x);
    // 5) LN2
    k_ln2<<<NROWS, 128>>>(out, n2w, n2b, p_xn2);
    // 6) fc1 + gelu                  (100352 x 1536, K=384)
    k_tgemm<1><<<dim3(HIDD / 128, NROWS / 128), 256>>>(p_xn2, fc1w, fc1b, p_hid, CDIM, HIDD, nullptr);
    // 7) fc2 + residual into d_out   (100352 x 384, K=1536)
    k_tgemm<3><<<dim3(CDIM / 128, NROWS / 128), 256>>>(p_hid, fc2w, fc2b, out, HIDD, CDIM, out);
}

// round 4
// speedup vs baseline: 2.0682x; 1.1153x over previous
#include <cuda_runtime.h>
#include <math.h>
#include <stdint.h>

// ---------------- problem constants ----------------
#define BATCH 32
#define HIMG  56
#define CDIM  384
#define NTOK  49
#define NWIN  64
#define NROWS 100352
#define C3    1152
#define HIDD  1536
#define HEADS 12
#define HD    32
#define SHIFT 3

// ---------------- scratch ----------------
__device__ float g_xw [(size_t)NROWS * CDIM];
__device__ float g_qkv[(size_t)NROWS * C3];
__device__ float g_att[(size_t)NROWS * CDIM];
__device__ float g_xn2[(size_t)NROWS * CDIM];
__device__ float g_hid[(size_t)NROWS * HIDD];
__device__ float g_wr [1769472]; // tf32-rounded weights, original [K][N] layout

#define WR_QKV 0
#define WR_PROJ 442368
#define WR_FC1 589824
#define WR_FC2 1179648

// ---------------- helpers ----------------
__device__ __forceinline__ unsigned f2tf(float f) {
    unsigned u; asm("cvt.rna.tf32.f32 %0, %1;" : "=r"(u) : "f"(f)); return u;
}
__device__ __forceinline__ float tfr(float f) { return __uint_as_float(f2tf(f)); }

__device__ __forceinline__ uint32_t s2u(const void* p) {
    uint32_t a;
    asm("{ .reg .u64 t; cvta.to.shared.u64 t, %1; cvt.u32.u64 %0, t; }" : "=r"(a) : "l"(p));
    return a;
}
__device__ __forceinline__ void cp16(uint32_t dst, const void* src) {
    asm volatile("cp.async.cg.shared.global [%0], [%1], 16;" :: "r"(dst), "l"(src));
}
__device__ __forceinline__ void mma_tf32(float c[4], const unsigned a[4], const unsigned b[2]) {
    asm volatile("mma.sync.aligned.m16n8k8.row.col.f32.tf32.tf32.f32 "
                 "{%0,%1,%2,%3}, {%4,%5,%6,%7}, {%8,%9}, {%0,%1,%2,%3};"
                 : "+f"(c[0]), "+f"(c[1]), "+f"(c[2]), "+f"(c[3])
                 : "r"(a[0]), "r"(a[1]), "r"(a[2]), "r"(a[3]),
                   "r"(b[0]), "r"(b[1]));
}

// ---------------- weight tf32 rounding (elementwise, [K][N] kept) ------------
__global__ __launch_bounds__(256) void k_round(const float* __restrict__ s,
                                               float* __restrict__ d, int n) {
    int i = blockIdx.x * 256 + threadIdx.x;
    if (i < n) d[i] = tfr(s[i]);
}

// ---------------- block reduce ----------------
__device__ __forceinline__ float blockReduceSum128(float v, float* sh) {
    #pragma unroll
    for (int o = 16; o > 0; o >>= 1) v += __shfl_xor_sync(0xffffffffu, v, o);
    int warp = threadIdx.x >> 5, lane = threadIdx.x & 31;
    if (lane == 0) sh[warp] = v;
    __syncthreads();
    float r;
    if (warp == 0) {
        float t = (lane < 4) ? sh[lane] : 0.f;
        #pragma unroll
        for (int o = 2; o > 0; o >>= 1) t += __shfl_xor_sync(0xffffffffu, t, o);
        if (lane == 0) sh[0] = t;
    }
    __syncthreads();
    r = sh[0];
    __syncthreads();
    return r;
}

// ---------------- LN1 + shift + partition (tf32-rounded out) ----------------
__global__ __launch_bounds__(128) void k_ln1(const float* __restrict__ x,
                                             const float* __restrict__ w,
                                             const float* __restrict__ b,
                                             float* __restrict__ dst_all) {
    __shared__ float sh[32];
    int m = blockIdx.x;
    int win = m / NTOK, n = m % NTOK;
    int bb = win >> 6, wi = win & 63;
    int wr = wi >> 3, wc = wi & 7;
    int rs = wr * 7 + n / 7, cs = wc * 7 + n % 7;
    int r = (rs + SHIFT) % HIMG, c = (cs + SHIFT) % HIMG;
    const float* src = x + ((size_t)bb * (HIMG * HIMG) + r * HIMG + c) * CDIM;
    int t = threadIdx.x;
    float v0 = src[t], v1 = src[t + 128], v2 = src[t + 256];
    float s  = blockReduceSum128(v0 + v1 + v2, sh);
    float s2 = blockReduceSum128(v0 * v0 + v1 * v1 + v2 * v2, sh);
    float mean = s * (1.f / CDIM);
    float var  = s2 * (1.f / CDIM) - mean * mean;
    float rstd = rsqrtf(var + 1e-5f);
    float* dst = dst_all + (size_t)m * CDIM;
    dst[t]       = tfr((v0 - mean) * rstd * w[t]       + b[t]);
    dst[t + 128] = tfr((v1 - mean) * rstd * w[t + 128] + b[t + 128]);
    dst[t + 256] = tfr((v2 - mean) * rstd * w[t + 256] + b[t + 256]);
}

__global__ __launch_bounds__(128) void k_ln2(const float* __restrict__ x2,
                                             const float* __restrict__ w,
                                             const float* __restrict__ b,
                                             float* __restrict__ dst_all) {
    __shared__ float sh[32];
    int m = blockIdx.x;
    const float* src = x2 + (size_t)m * CDIM;
    int t = threadIdx.x;
    float v0 = src[t], v1 = src[t + 128], v2 = src[t + 256];
    float s  = blockReduceSum128(v0 + v1 + v2, sh);
    float s2 = blockReduceSum128(v0 * v0 + v1 * v1 + v2 * v2, sh);
    float mean = s * (1.f / CDIM);
    float var  = s2 * (1.f / CDIM) - mean * mean;
    float rstd = rsqrtf(var + 1e-5f);
    float* dst = dst_all + (size_t)m * CDIM;
    dst[t]       = tfr((v0 - mean) * rstd * w[t]       + b[t]);
    dst[t + 128] = tfr((v1 - mean) * rstd * w[t + 128] + b[t + 128]);
    dst[t + 256] = tfr((v2 - mean) * rstd * w[t + 256] + b[t + 256]);
}

// ---------------- TF32 mma.sync GEMM: block 256x128, warp 64x64, cp.async ---
// A[M][K] row-major (pre-rounded tf32 bits), B[K][N] row-major (pre-rounded)
// EPI: 0=bias, 1=bias+gelu(+round), 2=bias+reverse/unshift+residual, 3=bias+residual
#define ASTRIDE 20
#define BSTRIDE 136
#define A_STAGE (256 * ASTRIDE)      // floats
#define B_STAGE (16 * BSTRIDE)
#define DSMEM_BYTES ((2 * A_STAGE + 2 * B_STAGE) * 4)

template<int EPI>
__global__ __launch_bounds__(256) void k_mma(const float* __restrict__ A,
                                             const float* __restrict__ Bg,
                                             const float* __restrict__ bias,
                                             float* __restrict__ Cout,
                                             int K, int N,
                                             const float* __restrict__ res) {
    extern __shared__ float smem[];
    float* sA = smem;                  // [2][256][ASTRIDE]
    float* sB = smem + 2 * A_STAGE;    // [2][16][BSTRIDE]
    uint32_t uA = s2u(sA), uB = s2u(sB);

    int tid = threadIdx.x, wid = tid >> 5, lane = tid & 31;
    int gid = lane >> 2, tig = lane & 3;
    int mW = (wid >> 1) * 64;   // 0,64,128,192
    int nW = (wid & 1) * 64;    // 0,64

    size_t rowBase = (size_t)blockIdx.y * 256;
    int colB = blockIdx.x * 128;
    const float* Ab = A + rowBase * K;

    float acc[4][8][4];
    #pragma unroll
    for (int mi = 0; mi < 4; mi++)
        #pragma unroll
        for (int ni = 0; ni < 8; ni++)
            #pragma unroll
            for (int r = 0; r < 4; r++) acc[mi][ni][r] = 0.f;

    int S = K >> 4;

    #define ISSUE(s, buf) { int k0 = (s) << 4; \
        _Pragma("unroll") for (int i = 0; i < 4; i++) { \
            int ch = tid + i * 256; int r = ch >> 2, c = ch & 3; \
            cp16(uA + ((buf) * A_STAGE + r * ASTRIDE + c * 4) * 4, \
                 Ab + (size_t)r * K + k0 + c * 4); } \
        _Pragma("unroll") for (int i = 0; i < 2; i++) { \
            int ch = tid + i * 256; int r = ch >> 5, c = ch & 31; \
            cp16(uB + ((buf) * B_STAGE + r * BSTRIDE + c * 4) * 4, \
                 Bg + (size_t)(k0 + r) * N + colB + c * 4); } \
        asm volatile("cp.async.commit_group;" ::: "memory"); }

    ISSUE(0, 0);
    ISSUE(1, 1);

    for (int s = 0; s < S; s++) {
        int buf = s & 1;
        asm volatile("cp.async.wait_group 1;" ::: "memory");
        __syncthreads();
        const float* A_s = sA + buf * A_STAGE;
        const float* B_s = sB + buf * B_STAGE;
        #pragma unroll
        for (int ks = 0; ks < 16; ks += 8) {
            unsigned bfr[8][2];
            #pragma unroll
            for (int ni = 0; ni < 8; ni++) {
                int n0 = nW + ni * 8 + gid;
                bfr[ni][0] = __float_as_uint(B_s[(ks + tig) * BSTRIDE + n0]);
                bfr[ni][1] = __float_as_uint(B_s[(ks + tig + 4) * BSTRIDE + n0]);
            }
            #pragma unroll
            for (int mi = 0; mi < 4; mi++) {
                int m0 = mW + mi * 16 + gid;
                unsigned afr[4];
                afr[0] = __float_as_uint(A_s[m0 * ASTRIDE + ks + tig]);
                afr[1] = __float_as_uint(A_s[(m0 + 8) * ASTRIDE + ks + tig]);
                afr[2] = __float_as_uint(A_s[m0 * ASTRIDE + ks + tig + 4]);
                afr[3] = __float_as_uint(A_s[(m0 + 8) * ASTRIDE + ks + tig + 4]);
                #pragma unroll
                for (int ni = 0; ni < 8; ni++)
                    mma_tf32(acc[mi][ni], afr, bfr[ni]);
            }
        }
        __syncthreads();
        if (s + 2 < S) { ISSUE(s + 2, buf); }
        else { asm volatile("cp.async.commit_group;" ::: "memory"); }
    }
    #undef ISSUE
    asm volatile("cp.async.wait_group 0;" ::: "memory");

    // ---------------- epilogue straight from registers ----------------
    float2 bb2[8];
    #pragma unroll
    for (int ni = 0; ni < 8; ni++)
        bb2[ni] = *(const float2*)(bias + colB + nW + ni * 8 + 2 * tig);

    #pragma unroll
    for (int mi = 0; mi < 4; mi++) {
        #pragma unroll
        for (int half = 0; half < 2; half++) {
            size_t row = rowBase + mW + mi * 16 + gid + half * 8;
            size_t dstRow = 0;
            if (EPI == 2) {
                int win = (int)(row / NTOK), n = (int)(row % NTOK);
                int bbt = win >> 6, wi = win & 63;
                int wr = wi >> 3, wc = wi & 7;
                int rs = wr * 7 + n / 7, cs = wc * 7 + n % 7;
                int rr = (rs + SHIFT) % HIMG, cg = (cs + SHIFT) % HIMG;
                dstRow = ((size_t)bbt * (HIMG * HIMG) + rr * HIMG + cg) * CDIM;
            }
            #pragma unroll
            for (int ni = 0; ni < 8; ni++) {
                int col = colB + nW + ni * 8 + 2 * tig;
                float v0 = acc[mi][ni][half * 2]     + bb2[ni].x;
                float v1 = acc[mi][ni][half * 2 + 1] + bb2[ni].y;
                if (EPI == 0) {
                    *(float2*)(&Cout[row * N + col]) = make_float2(v0, v1);
                } else if (EPI == 1) {
                    v0 = tfr(0.5f * v0 * (1.0f + erff(v0 * 0.70710678118654752f)));
                    v1 = tfr(0.5f * v1 * (1.0f + erff(v1 * 0.70710678118654752f)));
                    *(float2*)(&Cout[row * N + col]) = make_float2(v0, v1);
                } else if (EPI == 2) {
                    float2 rv = *(const float2*)(&res[dstRow + col]);
                    *(float2*)(&Cout[dstRow + col]) = make_float2(rv.x + v0, rv.y + v1);
                } else {
                    size_t o = row * N + col;
                    float2 rv = *(const float2*)(&res[o]);
                    *(float2*)(&Cout[o]) = make_float2(rv.x + v0, rv.y + v1);
                }
            }
        }
    }
}

// ---------------- windowed attention ----------------
__global__ __launch_bounds__(256) void k_attn(const float* __restrict__ qkv,
                                              const float* __restrict__ rpb,
                                              float* __restrict__ out) {
    __shared__ __align__(16) float q [NTOK][HD];
    __shared__ __align__(16) float kk[NTOK][HD];
    __shared__ __align__(16) float vv[NTOK][HD];
    __shared__ float s[NTOK][NTOK + 1];
    __shared__ int lab[NTOK];

    int w = blockIdx.x, h = blockIdx.y, tid = threadIdx.x;
    const float scale = 0.17677669529663689f;

    size_t base = (size_t)w * NTOK * C3 + h * HD;
    for (int idx = tid; idx < NTOK * HD; idx += 256) {
        int n = idx >> 5, d = idx & 31;
        size_t rb = base + (size_t)n * C3 + d;
        q [n][d] = qkv[rb] * scale;
        kk[n][d] = qkv[rb + CDIM];
        vv[n][d] = qkv[rb + 2 * CDIM];
    }
    if (tid < NTOK) {
        int wi = w & 63, wr = wi >> 3, wc = wi & 7;
        int rs = wr * 7 + tid / 7, cs = wc * 7 + tid % 7;
        int rr = (rs < HIMG - 7) ? 0 : ((rs < HIMG - SHIFT) ? 1 : 2);
        int cc = (cs < HIMG - 7) ? 0 : ((cs < HIMG - SHIFT) ? 1 : 2);
        lab[tid] = rr * 3 + cc;
    }
    __syncthreads();

    for (int idx = tid; idx < NTOK * NTOK; idx += 256) {
        int i = idx / NTOK, j = idx % NTOK;
        const float4* qa = (const float4*)q[i];
        const float4* kb = (const float4*)kk[j];
        float acc = 0.f;
        #pragma unroll
        for (int t = 0; t < HD / 4; t++) {
            float4 a = qa[t], bq = kb[t];
            acc += a.x * bq.x + a.y * bq.y + a.z * bq.z + a.w * bq.w;
        }
        int ri = i / 7, ci = i % 7, rj = j / 7, cj = j % 7;
        int bidx = (ri - rj + 6) * 13 + (ci - cj + 6);
        acc += rpb[bidx * HEADS + h];
        if (lab[i] != lab[j]) acc -= 100.0f;
        s[i][j] = acc;
    }
    __syncthreads();

    int warp = tid >> 5, lane = tid & 31;
    for (int i = warp; i < NTOK; i += 8) {
        float v0 = s[i][lane];
        float v1 = (lane + 32 < NTOK) ? s[i][lane + 32] : -1e30f;
        float mx = fmaxf(v0, v1);
        #pragma unroll
        for (int o = 16; o > 0; o >>= 1) mx = fmaxf(mx, __shfl_xor_sync(0xffffffffu, mx, o));
        float e0 = __expf(v0 - mx);
        float e1 = (lane + 32 < NTOK) ? __expf(v1 - mx) : 0.f;
        float sum = e0 + e1;
        #pragma unroll
        for (int o = 16; o > 0; o >>= 1) sum += __shfl_xor_sync(0xffffffffu, sum, o);
        float inv = 1.f / sum;
        s[i][lane] = e0 * inv;
        if (lane + 32 < NTOK) s[i][lane + 32] = e1 * inv;
    }
    __syncthreads();

    for (int idx = tid; idx < NTOK * HD; idx += 256) {
        int i = idx >> 5, d = idx & 31;
        float acc = 0.f;
        #pragma unroll
        for (int j = 0; j < NTOK; j++) acc += s[i][j] * vv[j][d];
        out[((size_t)w * NTOK + i) * CDIM + h * HD + d] = tfr(acc);
    }
}

// ---------------- launch ----------------
extern "C" void kernel_launch(void* const* d_in, const int* in_sizes, int n_in,
                              void* d_out, int out_size) {
    const float* x     = (const float*)d_in[0];
    const float* n1w   = (const float*)d_in[1];
    const float* n1b   = (const float*)d_in[2];
    const float* qkvw  = (const float*)d_in[3];
    const float* qkvb  = (const float*)d_in[4];
    const float* rpb   = (const float*)d_in[5];
    const float* projw = (const float*)d_in[6];
    const float* projb = (const float*)d_in[7];
    const float* n2w   = (const float*)d_in[8];
    const float* n2b   = (const float*)d_in[9];
    const float* fc1w  = (const float*)d_in[10];
    const float* fc1b  = (const float*)d_in[11];
    const float* fc2w  = (const float*)d_in[12];
    const float* fc2b  = (const float*)d_in[13];
    float* out = (float*)d_out;

    float *p_xw, *p_qkv, *p_att, *p_xn2, *p_hid, *p_wr;
    cudaGetSymbolAddress((void**)&p_xw,  g_xw);
    cudaGetSymbolAddress((void**)&p_qkv, g_qkv);
    cudaGetSymbolAddress((void**)&p_att, g_att);
    cudaGetSymbolAddress((void**)&p_xn2, g_xn2);
    cudaGetSymbolAddress((void**)&p_hid, g_hid);
    cudaGetSymbolAddress((void**)&p_wr,  g_wr);

    cudaFuncSetAttribute(k_mma<0>, cudaFuncAttributeMaxDynamicSharedMemorySize, DSMEM_BYTES);
    cudaFuncSetAttribute(k_mma<1>, cudaFuncAttributeMaxDynamicSharedMemorySize, DSMEM_BYTES);
    cudaFuncSetAttribute(k_mma<2>, cudaFuncAttributeMaxDynamicSharedMemorySize, DSMEM_BYTES);
    cudaFuncSetAttribute(k_mma<3>, cudaFuncAttributeMaxDynamicSharedMemorySize, DSMEM_BYTES);

    // 0) weight tf32 rounding (layout unchanged)
    k_round<<<(442368 + 255) / 256, 256>>>(qkvw, p_wr + WR_QKV, 442368);
    k_round<<<(147456 + 255) / 256, 256>>>(projw, p_wr + WR_PROJ, 147456);
    k_round<<<(589824 + 255) / 256, 256>>>(fc1w, p_wr + WR_FC1, 589824);
    k_round<<<(589824 + 255) / 256, 256>>>(fc2w, p_wr + WR_FC2, 589824);

    // 1) LN1 + shift + partition
    k_ln1<<<NROWS, 128>>>(x, n1w, n1b, p_xw);
    // 2) qkv
    k_mma<0><<<dim3(C3 / 128, NROWS / 256), 256, DSMEM_BYTES>>>(
        p_xw, p_wr + WR_QKV, qkvb, p_qkv, CDIM, C3, nullptr);
    // 3) attention
    k_attn<<<dim3(NROWS / NTOK, HEADS), 256>>>(p_qkv, rpb, p_att);
    // 4) proj + reverse/unshift + residual -> out holds x2
    k_mma<2><<<dim3(CDIM / 128, NROWS / 256), 256, DSMEM_BYTES>>>(
        p_att, p_wr + WR_PROJ, projb, out, CDIM, CDIM, x);
    // 5) LN2
    k_ln2<<<NROWS, 128>>>(out, n2w, n2b, p_xn2);
    // 6) fc1 + gelu
    k_mma<1><<<dim3(HIDD / 128, NROWS / 256), 256, DSMEM_BYTES>>>(
        p_xn2, p_wr + WR_FC1, fc1b, p_hid, CDIM, HIDD, nullptr);
    // 7) fc2 + residual
    k_mma<3><<<dim3(CDIM / 128, NROWS / 256), 256, DSMEM_BYTES>>>(
        p_hid, p_wr + WR_FC2, fc2b, out, HIDD, CDIM, out);
}

// round 5
// speedup vs baseline: 2.9090x; 1.4066x over previous
#include <cuda_runtime.h>
#include <math.h>
#include <stdint.h>

// ---------------- problem constants ----------------
#define BATCH 32
#define HIMG  56
#define CDIM  384
#define NTOK  49
#define NWIN  64
#define NROWS 100352
#define C3    1152
#define HIDD  1536
#define HEADS 12
#define HD    32
#define SHIFT 3

// ---------------- scratch ----------------
__device__ float g_xw [(size_t)NROWS * CDIM];
__device__ float g_qkv[(size_t)NROWS * C3];
__device__ float g_att[(size_t)NROWS * CDIM];
__device__ float g_xn2[(size_t)NROWS * CDIM];
__device__ float g_hid[(size_t)NROWS * HIDD];
__device__ float g_wr [1769472]; // tf32-rounded weights, original [K][N] layout

#define WR_QKV 0
#define WR_PROJ 442368
#define WR_FC1 589824
#define WR_FC2 1179648

// ---------------- helpers ----------------
__device__ __forceinline__ unsigned f2tf(float f) {
    unsigned u; asm("cvt.rna.tf32.f32 %0, %1;" : "=r"(u) : "f"(f)); return u;
}
__device__ __forceinline__ float tfr(float f) { return __uint_as_float(f2tf(f)); }

__device__ __forceinline__ uint32_t s2u(const void* p) {
    uint32_t a;
    asm("{ .reg .u64 t; cvta.to.shared.u64 t, %1; cvt.u32.u64 %0, t; }" : "=r"(a) : "l"(p));
    return a;
}
__device__ __forceinline__ void cp16(uint32_t dst, const void* src) {
    asm volatile("cp.async.cg.shared.global [%0], [%1], 16;" :: "r"(dst), "l"(src));
}
__device__ __forceinline__ void mma_tf32(float c[4], const unsigned a[4], const unsigned b[2]) {
    asm volatile("mma.sync.aligned.m16n8k8.row.col.f32.tf32.tf32.f32 "
                 "{%0,%1,%2,%3}, {%4,%5,%6,%7}, {%8,%9}, {%0,%1,%2,%3};"
                 : "+f"(c[0]), "+f"(c[1]), "+f"(c[2]), "+f"(c[3])
                 : "r"(a[0]), "r"(a[1]), "r"(a[2]), "r"(a[3]),
                   "r"(b[0]), "r"(b[1]));
}

// ---------------- weight tf32 rounding (elementwise, [K][N] kept) ------------
__global__ __launch_bounds__(256) void k_round(const float* __restrict__ s,
                                               float* __restrict__ d, int n) {
    int i = blockIdx.x * 256 + threadIdx.x;
    if (i < n) d[i] = tfr(s[i]);
}

// ---------------- block reduce ----------------
__device__ __forceinline__ float blockReduceSum128(float v, float* sh) {
    #pragma unroll
    for (int o = 16; o > 0; o >>= 1) v += __shfl_xor_sync(0xffffffffu, v, o);
    int warp = threadIdx.x >> 5, lane = threadIdx.x & 31;
    if (lane == 0) sh[warp] = v;
    __syncthreads();
    float r;
    if (warp == 0) {
        float t = (lane < 4) ? sh[lane] : 0.f;
        #pragma unroll
        for (int o = 2; o > 0; o >>= 1) t += __shfl_xor_sync(0xffffffffu, t, o);
        if (lane == 0) sh[0] = t;
    }
    __syncthreads();
    r = sh[0];
    __syncthreads();
    return r;
}

// ---------------- LN1 + shift + partition (tf32-rounded out) ----------------
__global__ __launch_bounds__(128) void k_ln1(const float* __restrict__ x,
                                             const float* __restrict__ w,
                                             const float* __restrict__ b,
                                             float* __restrict__ dst_all) {
    __shared__ float sh[32];
    int m = blockIdx.x;
    int win = m / NTOK, n = m % NTOK;
    int bb = win >> 6, wi = win & 63;
    int wr = wi >> 3, wc = wi & 7;
    int rs = wr * 7 + n / 7, cs = wc * 7 + n % 7;
    int r = (rs + SHIFT) % HIMG, c = (cs + SHIFT) % HIMG;
    const float* src = x + ((size_t)bb * (HIMG * HIMG) + r * HIMG + c) * CDIM;
    int t = threadIdx.x;
    float v0 = src[t], v1 = src[t + 128], v2 = src[t + 256];
    float s  = blockReduceSum128(v0 + v1 + v2, sh);
    float s2 = blockReduceSum128(v0 * v0 + v1 * v1 + v2 * v2, sh);
    float mean = s * (1.f / CDIM);
    float var  = s2 * (1.f / CDIM) - mean * mean;
    float rstd = rsqrtf(var + 1e-5f);
    float* dst = dst_all + (size_t)m * CDIM;
    dst[t]       = tfr((v0 - mean) * rstd * w[t]       + b[t]);
    dst[t + 128] = tfr((v1 - mean) * rstd * w[t + 128] + b[t + 128]);
    dst[t + 256] = tfr((v2 - mean) * rstd * w[t + 256] + b[t + 256]);
}

__global__ __launch_bounds__(128) void k_ln2(const float* __restrict__ x2,
                                             const float* __restrict__ w,
                                             const float* __restrict__ b,
                                             float* __restrict__ dst_all) {
    __shared__ float sh[32];
    int m = blockIdx.x;
    const float* src = x2 + (size_t)m * CDIM;
    int t = threadIdx.x;
    float v0 = src[t], v1 = src[t + 128], v2 = src[t + 256];
    float s  = blockReduceSum128(v0 + v1 + v2, sh);
    float s2 = blockReduceSum128(v0 * v0 + v1 * v1 + v2 * v2, sh);
    float mean = s * (1.f / CDIM);
    float var  = s2 * (1.f / CDIM) - mean * mean;
    float rstd = rsqrtf(var + 1e-5f);
    float* dst = dst_all + (size_t)m * CDIM;
    dst[t]       = tfr((v0 - mean) * rstd * w[t]       + b[t]);
    dst[t + 128] = tfr((v1 - mean) * rstd * w[t + 128] + b[t + 128]);
    dst[t + 256] = tfr((v2 - mean) * rstd * w[t + 256] + b[t + 256]);
}

// ---------------- TF32 mma.sync GEMM: block 256x128, warp 64x64, cp.async x3 -
#define ASTRIDE 20
#define BSTRIDE 136
#define A_STAGE (256 * ASTRIDE)
#define B_STAGE (16 * BSTRIDE)
#define DSMEM_BYTES ((3 * A_STAGE + 3 * B_STAGE) * 4)

template<int EPI>
__global__ __launch_bounds__(256) void k_mma(const float* __restrict__ A,
                                             const float* __restrict__ Bg,
                                             const float* __restrict__ bias,
                                             float* __restrict__ Cout,
                                             int K, int N,
                                             const float* __restrict__ res) {
    extern __shared__ float smem[];
    float* sA = smem;                  // [3][256][ASTRIDE]
    float* sB = smem + 3 * A_STAGE;    // [3][16][BSTRIDE]
    uint32_t uA = s2u(sA), uB = s2u(sB);

    int tid = threadIdx.x, wid = tid >> 5, lane = tid & 31;
    int gid = lane >> 2, tig = lane & 3;
    int mW = (wid >> 1) * 64;
    int nW = (wid & 1) * 64;

    size_t rowBase = (size_t)blockIdx.y * 256;
    int colB = blockIdx.x * 128;
    const float* Ab = A + rowBase * K;

    float acc[4][8][4];
    #pragma unroll
    for (int mi = 0; mi < 4; mi++)
        #pragma unroll
        for (int ni = 0; ni < 8; ni++)
            #pragma unroll
            for (int r = 0; r < 4; r++) acc[mi][ni][r] = 0.f;

    int S = K >> 4;

    #define ISSUE(s, buf) { int k0 = (s) << 4; \
        _Pragma("unroll") for (int i = 0; i < 4; i++) { \
            int ch = tid + i * 256; int r = ch >> 2, c = ch & 3; \
            cp16(uA + ((buf) * A_STAGE + r * ASTRIDE + c * 4) * 4, \
                 Ab + (size_t)r * K + k0 + c * 4); } \
        _Pragma("unroll") for (int i = 0; i < 2; i++) { \
            int ch = tid + i * 256; int r = ch >> 5, c = ch & 31; \
            cp16(uB + ((buf) * B_STAGE + r * BSTRIDE + c * 4) * 4, \
                 Bg + (size_t)(k0 + r) * N + colB + c * 4); } \
        asm volatile("cp.async.commit_group;" ::: "memory"); }

    ISSUE(0, 0); ISSUE(1, 1); ISSUE(2, 2);

    for (int s = 0; s < S; s++) {
        int buf = s % 3;
        asm volatile("cp.async.wait_group 2;" ::: "memory");
        __syncthreads();
        const float* A_s = sA + buf * A_STAGE;
        const float* B_s = sB + buf * B_STAGE;
        #pragma unroll
        for (int ks = 0; ks < 16; ks += 8) {
            unsigned bfr[8][2];
            #pragma unroll
            for (int ni = 0; ni < 8; ni++) {
                int n0 = nW + ni * 8 + gid;
                bfr[ni][0] = __float_as_uint(B_s[(ks + tig) * BSTRIDE + n0]);
                bfr[ni][1] = __float_as_uint(B_s[(ks + tig + 4) * BSTRIDE + n0]);
            }
            #pragma unroll
            for (int mi = 0; mi < 4; mi++) {
                int m0 = mW + mi * 16 + gid;
                unsigned afr[4];
                afr[0] = __float_as_uint(A_s[m0 * ASTRIDE + ks + tig]);
                afr[1] = __float_as_uint(A_s[(m0 + 8) * ASTRIDE + ks + tig]);
                afr[2] = __float_as_uint(A_s[m0 * ASTRIDE + ks + tig + 4]);
                afr[3] = __float_as_uint(A_s[(m0 + 8) * ASTRIDE + ks + tig + 4]);
                #pragma unroll
                for (int ni = 0; ni < 8; ni++)
                    mma_tf32(acc[mi][ni], afr, bfr[ni]);
            }
        }
        __syncthreads();
        if (s + 3 < S) { ISSUE(s + 3, buf); }
        else { asm volatile("cp.async.commit_group;" ::: "memory"); }
    }
    #undef ISSUE
    asm volatile("cp.async.wait_group 0;" ::: "memory");

    // ---------------- epilogue straight from registers ----------------
    float2 bb2[8];
    #pragma unroll
    for (int ni = 0; ni < 8; ni++)
        bb2[ni] = *(const float2*)(bias + colB + nW + ni * 8 + 2 * tig);

    #pragma unroll
    for (int mi = 0; mi < 4; mi++) {
        #pragma unroll
        for (int half = 0; half < 2; half++) {
            size_t row = rowBase + mW + mi * 16 + gid + half * 8;
            size_t dstRow = 0;
            if (EPI == 2) {
                int win = (int)(row / NTOK), n = (int)(row % NTOK);
                int bbt = win >> 6, wi = win & 63;
                int wr = wi >> 3, wc = wi & 7;
                int rs = wr * 7 + n / 7, cs = wc * 7 + n % 7;
                int rr = (rs + SHIFT) % HIMG, cg = (cs + SHIFT) % HIMG;
                dstRow = ((size_t)bbt * (HIMG * HIMG) + rr * HIMG + cg) * CDIM;
            }
            #pragma unroll
            for (int ni = 0; ni < 8; ni++) {
                int col = colB + nW + ni * 8 + 2 * tig;
                float v0 = acc[mi][ni][half * 2]     + bb2[ni].x;
                float v1 = acc[mi][ni][half * 2 + 1] + bb2[ni].y;
                if (EPI == 0) {
                    *(float2*)(&Cout[row * N + col]) = make_float2(v0, v1);
                } else if (EPI == 1) {
                    v0 = tfr(0.5f * v0 * (1.0f + erff(v0 * 0.70710678118654752f)));
                    v1 = tfr(0.5f * v1 * (1.0f + erff(v1 * 0.70710678118654752f)));
                    *(float2*)(&Cout[row * N + col]) = make_float2(v0, v1);
                } else if (EPI == 2) {
                    float2 rv = *(const float2*)(&res[dstRow + col]);
                    *(float2*)(&Cout[dstRow + col]) = make_float2(rv.x + v0, rv.y + v1);
                } else {
                    size_t o = row * N + col;
                    float2 rv = *(const float2*)(&res[o]);
                    *(float2*)(&Cout[o]) = make_float2(rv.x + v0, rv.y + v1);
                }
            }
        }
    }
}

// ---------------- windowed attention (conflict-free padded smem) -------------
#define PAD 36
__global__ __launch_bounds__(256) void k_attn(const float* __restrict__ qkv,
                                              const float* __restrict__ rpb,
                                              float* __restrict__ out) {
    __shared__ __align__(16) float q [NTOK][PAD];
    __shared__ __align__(16) float kk[NTOK][PAD];
    __shared__ __align__(16) float vv[NTOK][PAD];
    __shared__ float s[NTOK][NTOK + 1];
    __shared__ float sbias[169];
    __shared__ int lab[NTOK];

    int w = blockIdx.x, h = blockIdx.y, tid = threadIdx.x;
    const float scale = 0.17677669529663689f;

    size_t base = (size_t)w * NTOK * C3 + h * HD;
    // load q/k/v as float4, conflict-free writes (bank start 4n+4t distinct/phase)
    for (int idx = tid; idx < NTOK * 8; idx += 256) {
        int n = idx >> 3, t4 = (idx & 7) * 4;
        const float* rbq = qkv + base + (size_t)n * C3 + t4;
        float4 a = *(const float4*)rbq;
        a.x *= scale; a.y *= scale; a.z *= scale; a.w *= scale;
        *(float4*)&q[n][t4] = a;
        *(float4*)&kk[n][t4] = *(const float4*)(rbq + CDIM);
        *(float4*)&vv[n][t4] = *(const float4*)(rbq + 2 * CDIM);
    }
    if (tid < 169) sbias[tid] = rpb[tid * HEADS + h];
    if (tid >= 192 && tid < 192 + NTOK) {
        int n = tid - 192;
        int wi = w & 63, wr = wi >> 3, wc = wi & 7;
        int rs = wr * 7 + n / 7, cs = wc * 7 + n % 7;
        int rr = (rs < HIMG - 7) ? 0 : ((rs < HIMG - SHIFT) ? 1 : 2);
        int cc = (cs < HIMG - 7) ? 0 : ((cs < HIMG - SHIFT) ? 1 : 2);
        lab[n] = rr * 3 + cc;
    }
    __syncthreads();

    // scores + bias + mask
    for (int idx = tid; idx < NTOK * NTOK; idx += 256) {
        int i = idx / NTOK, j = idx % NTOK;
        float acc = 0.f;
        #pragma unroll
        for (int t = 0; t < HD / 4; t++) {
            float4 a = *(const float4*)&q[i][4 * t];
            float4 bq = *(const float4*)&kk[j][4 * t];
            acc += a.x * bq.x + a.y * bq.y + a.z * bq.z + a.w * bq.w;
        }
        int ri = i / 7, ci = i % 7, rj = j / 7, cj = j % 7;
        acc += sbias[(ri - rj + 6) * 13 + (ci - cj + 6)];
        if (lab[i] != lab[j]) acc -= 100.0f;
        s[i][j] = acc;
    }
    __syncthreads();

    // softmax: one warp per row
    int warp = tid >> 5, lane = tid & 31;
    for (int i = warp; i < NTOK; i += 8) {
        float v0 = s[i][lane];
        float v1 = (lane + 32 < NTOK) ? s[i][lane + 32] : -1e30f;
        float mx = fmaxf(v0, v1);
        #pragma unroll
        for (int o = 16; o > 0; o >>= 1) mx = fmaxf(mx, __shfl_xor_sync(0xffffffffu, mx, o));
        float e0 = __expf(v0 - mx);
        float e1 = (lane + 32 < NTOK) ? __expf(v1 - mx) : 0.f;
        float sum = e0 + e1;
        #pragma unroll
        for (int o = 16; o > 0; o >>= 1) sum += __shfl_xor_sync(0xffffffffu, sum, o);
        float inv = 1.f / sum;
        s[i][lane] = e0 * inv;
        if (lane + 32 < NTOK) s[i][lane + 32] = e1 * inv;
    }
    __syncthreads();

    // P @ V, float4 accumulators, conflict-free vv reads
    for (int idx = tid; idx < NTOK * 8; idx += 256) {
        int i = idx >> 3, t4 = (idx & 7) * 4;
        float4 acc = make_float4(0.f, 0.f, 0.f, 0.f);
        #pragma unroll 7
        for (int j = 0; j < NTOK; j++) {
            float sj = s[i][j];
            float4 v4 = *(const float4*)&vv[j][t4];
            acc.x += sj * v4.x; acc.y += sj * v4.y;
            acc.z += sj * v4.z; acc.w += sj * v4.w;
        }
        acc.x = tfr(acc.x); acc.y = tfr(acc.y);
        acc.z = tfr(acc.z); acc.w = tfr(acc.w);
        *(float4*)&out[((size_t)w * NTOK + i) * CDIM + h * HD + t4] = acc;
    }
}

// ---------------- launch ----------------
extern "C" void kernel_launch(void* const* d_in, const int* in_sizes, int n_in,
                              void* d_out, int out_size) {
    const float* x     = (const float*)d_in[0];
    const float* n1w   = (const float*)d_in[1];
    const float* n1b   = (const float*)d_in[2];
    const float* qkvw  = (const float*)d_in[3];
    const float* qkvb  = (const float*)d_in[4];
    const float* rpb   = (const float*)d_in[5];
    const float* projw = (const float*)d_in[6];
    const float* projb = (const float*)d_in[7];
    const float* n2w   = (const float*)d_in[8];
    const float* n2b   = (const float*)d_in[9];
    const float* fc1w  = (const float*)d_in[10];
    const float* fc1b  = (const float*)d_in[11];
    const float* fc2w  = (const float*)d_in[12];
    const float* fc2b  = (const float*)d_in[13];
    float* out = (float*)d_out;

    float *p_xw, *p_qkv, *p_att, *p_xn2, *p_hid, *p_wr;
    cudaGetSymbolAddress((void**)&p_xw,  g_xw);
    cudaGetSymbolAddress((void**)&p_qkv, g_qkv);
    cudaGetSymbolAddress((void**)&p_att, g_att);
    cudaGetSymbolAddress((void**)&p_xn2, g_xn2);
    cudaGetSymbolAddress((void**)&p_hid, g_hid);
    cudaGetSymbolAddress((void**)&p_wr,  g_wr);

    cudaFuncSetAttribute(k_mma<0>, cudaFuncAttributeMaxDynamicSharedMemorySize, DSMEM_BYTES);
    cudaFuncSetAttribute(k_mma<1>, cudaFuncAttributeMaxDynamicSharedMemorySize, DSMEM_BYTES);
    cudaFuncSetAttribute(k_mma<2>, cudaFuncAttributeMaxDynamicSharedMemorySize, DSMEM_BYTES);
    cudaFuncSetAttribute(k_mma<3>, cudaFuncAttributeMaxDynamicSharedMemorySize, DSMEM_BYTES);

    // 0) weight tf32 rounding
    k_round<<<(442368 + 255) / 256, 256>>>(qkvw, p_wr + WR_QKV, 442368);
    k_round<<<(147456 + 255) / 256, 256>>>(projw, p_wr + WR_PROJ, 147456);
    k_round<<<(589824 + 255) / 256, 256>>>(fc1w, p_wr + WR_FC1, 589824);
    k_round<<<(589824 + 255) / 256, 256>>>(fc2w, p_wr + WR_FC2, 589824);

    // 1) LN1 + shift + partition
    k_ln1<<<NROWS, 128>>>(x, n1w, n1b, p_xw);
    // 2) qkv
    k_mma<0><<<dim3(C3 / 128, NROWS / 256), 256, DSMEM_BYTES>>>(
        p_xw, p_wr + WR_QKV, qkvb, p_qkv, CDIM, C3, nullptr);
    // 3) attention
    k_attn<<<dim3(NROWS / NTOK, HEADS), 256>>>(p_qkv, rpb, p_att);
    // 4) proj + reverse/unshift + residual -> out holds x2
    k_mma<2><<<dim3(CDIM / 128, NROWS / 256), 256, DSMEM_BYTES>>>(
        p_att, p_wr + WR_PROJ, projb, out, CDIM, CDIM, x);
    // 5) LN2
    k_ln2<<<NROWS, 128>>>(out, n2w, n2b, p_xn2);
    // 6) fc1 + gelu
    k_mma<1><<<dim3(HIDD / 128, NROWS / 256), 256, DSMEM_BYTES>>>(
        p_xn2, p_wr + WR_FC1, fc1b, p_hid, CDIM, HIDD, nullptr);
    // 7) fc2 + residual
    k_mma<3><<<dim3(CDIM / 128, NROWS / 256), 256, DSMEM_BYTES>>>(
        p_hid, p_wr + WR_FC2, fc2b, out, HIDD, CDIM, out);
}

// round 6
// speedup vs baseline: 3.0543x; 1.0500x over previous
#include <cuda_runtime.h>
#include <math.h>
#include <stdint.h>

// ---------------- problem constants ----------------
#define BATCH 32
#define HIMG  56
#define CDIM  384
#define NTOK  49
#define NWIN  64
#define NROWS 100352
#define C3    1152
#define HIDD  1536
#define HEADS 12
#define HD    32
#define SHIFT 3

// ---------------- scratch ----------------
__device__ float g_xw [(size_t)NROWS * CDIM];
__device__ float g_qkv[(size_t)NROWS * C3];
__device__ float g_att[(size_t)NROWS * CDIM];
__device__ float g_xn2[(size_t)NROWS * CDIM];
__device__ float g_hid[(size_t)NROWS * HIDD];
__device__ float g_wr [1769472];

#define WR_QKV 0
#define WR_PROJ 442368
#define WR_FC1 589824
#define WR_FC2 1179648

// ---------------- helpers ----------------
__device__ __forceinline__ unsigned f2tf(float f) {
    unsigned u; asm("cvt.rna.tf32.f32 %0, %1;" : "=r"(u) : "f"(f)); return u;
}
__device__ __forceinline__ float tfr(float f) { return __uint_as_float(f2tf(f)); }

__device__ __forceinline__ uint32_t s2u(const void* p) {
    uint32_t a;
    asm("{ .reg .u64 t; cvta.to.shared.u64 t, %1; cvt.u32.u64 %0, t; }" : "=r"(a) : "l"(p));
    return a;
}
__device__ __forceinline__ void cp16(uint32_t dst, const void* src) {
    asm volatile("cp.async.cg.shared.global [%0], [%1], 16;" :: "r"(dst), "l"(src));
}
__device__ __forceinline__ void mma_tf32(float c[4], const unsigned a[4], const unsigned b[2]) {
    asm volatile("mma.sync.aligned.m16n8k8.row.col.f32.tf32.tf32.f32 "
                 "{%0,%1,%2,%3}, {%4,%5,%6,%7}, {%8,%9}, {%0,%1,%2,%3};"
                 : "+f"(c[0]), "+f"(c[1]), "+f"(c[2]), "+f"(c[3])
                 : "r"(a[0]), "r"(a[1]), "r"(a[2]), "r"(a[3]),
                   "r"(b[0]), "r"(b[1]));
}

// ---------------- merged weight tf32 rounding ----------------
__global__ __launch_bounds__(256) void k_round4(const float* __restrict__ w0,
                                                const float* __restrict__ w1,
                                                const float* __restrict__ w2,
                                                const float* __restrict__ w3,
                                                float* __restrict__ d) {
    int i = blockIdx.x * 256 + threadIdx.x;
    if (i >= 1769472) return;
    float v;
    if (i < 442368)       v = w0[i];
    else if (i < 589824)  v = w1[i - 442368];
    else if (i < 1179648) v = w2[i - 589824];
    else                  v = w3[i - 1179648];
    d[i] = tfr(v);
}

// ---------------- warp-per-row LN (+optional gather for LN1) ----------------
// 128 thr = 4 warps = 4 rows per block
template<int GATHER>
__global__ __launch_bounds__(128) void k_ln(const float* __restrict__ x,
                                            const float* __restrict__ w,
                                            const float* __restrict__ b,
                                            float* __restrict__ dst_all) {
    int warp = threadIdx.x >> 5, lane = threadIdx.x & 31;
    int m = blockIdx.x * 4 + warp;
    const float* src;
    if (GATHER) {
        int win = m / NTOK, n = m % NTOK;
        int bb = win >> 6, wi = win & 63;
        int wr = wi >> 3, wc = wi & 7;
        int rs = wr * 7 + n / 7, cs = wc * 7 + n % 7;
        int r = (rs + SHIFT) % HIMG, c = (cs + SHIFT) % HIMG;
        src = x + ((size_t)bb * (HIMG * HIMG) + r * HIMG + c) * CDIM;
    } else {
        src = x + (size_t)m * CDIM;
    }
    float4 v[3];
    #pragma unroll
    for (int i = 0; i < 3; i++) v[i] = *(const float4*)(src + i * 128 + lane * 4);
    float s = 0.f, s2 = 0.f;
    #pragma unroll
    for (int i = 0; i < 3; i++) {
        s  += v[i].x + v[i].y + v[i].z + v[i].w;
        s2 += v[i].x * v[i].x + v[i].y * v[i].y + v[i].z * v[i].z + v[i].w * v[i].w;
    }
    #pragma unroll
    for (int o = 16; o > 0; o >>= 1) {
        s  += __shfl_xor_sync(0xffffffffu, s, o);
        s2 += __shfl_xor_sync(0xffffffffu, s2, o);
    }
    float mean = s * (1.f / CDIM);
    float rstd = rsqrtf(s2 * (1.f / CDIM) - mean * mean + 1e-5f);
    float* dst = dst_all + (size_t)m * CDIM;
    #pragma unroll
    for (int i = 0; i < 3; i++) {
        float4 wv = *(const float4*)(w + i * 128 + lane * 4);
        float4 bv = *(const float4*)(b + i * 128 + lane * 4);
        float4 o4;
        o4.x = tfr((v[i].x - mean) * rstd * wv.x + bv.x);
        o4.y = tfr((v[i].y - mean) * rstd * wv.y + bv.y);
        o4.z = tfr((v[i].z - mean) * rstd * wv.z + bv.z);
        o4.w = tfr((v[i].w - mean) * rstd * wv.w + bv.w);
        *(float4*)(dst + i * 128 + lane * 4) = o4;
    }
}

// ---------------- TF32 mma.sync GEMM: 256x128, warp 64x64, 4-buf cp.async ---
#define ASTRIDE 20
#define BSTRIDE 136
#define A_STAGE (256 * ASTRIDE)
#define B_STAGE (16 * BSTRIDE)
#define NSTG 4
#define DSMEM_BYTES ((NSTG * A_STAGE + NSTG * B_STAGE) * 4)

template<int EPI>
__global__ __launch_bounds__(256) void k_mma(const float* __restrict__ A,
                                             const float* __restrict__ Bg,
                                             const float* __restrict__ bias,
                                             float* __restrict__ Cout,
                                             int K, int N,
                                             const float* __restrict__ res) {
    extern __shared__ float smem[];
    float* sA = smem;                     // [NSTG][256][ASTRIDE]
    float* sB = smem + NSTG * A_STAGE;    // [NSTG][16][BSTRIDE]
    uint32_t uA = s2u(sA), uB = s2u(sB);

    int tid = threadIdx.x, wid = tid >> 5, lane = tid & 31;
    int gid = lane >> 2, tig = lane & 3;
    int mW = (wid >> 1) * 64;
    int nW = (wid & 1) * 64;

    size_t rowBase = (size_t)blockIdx.y * 256;
    int colB = blockIdx.x * 128;
    const float* Ab = A + rowBase * K;

    float acc[4][8][4];
    #pragma unroll
    for (int mi = 0; mi < 4; mi++)
        #pragma unroll
        for (int ni = 0; ni < 8; ni++)
            #pragma unroll
            for (int r = 0; r < 4; r++) acc[mi][ni][r] = 0.f;

    int S = K >> 4;

    #define ISSUE(s, buf) { int k0 = (s) << 4; \
        _Pragma("unroll") for (int i = 0; i < 4; i++) { \
            int ch = tid + i * 256; int r = ch >> 2, c = ch & 3; \
            cp16(uA + ((buf) * A_STAGE + r * ASTRIDE + c * 4) * 4, \
                 Ab + (size_t)r * K + k0 + c * 4); } \
        _Pragma("unroll") for (int i = 0; i < 2; i++) { \
            int ch = tid + i * 256; int r = ch >> 5, c = ch & 31; \
            cp16(uB + ((buf) * B_STAGE + r * BSTRIDE + c * 4) * 4, \
                 Bg + (size_t)(k0 + r) * N + colB + c * 4); } \
        asm volatile("cp.async.commit_group;" ::: "memory"); }

    ISSUE(0, 0); ISSUE(1, 1); ISSUE(2, 2);

    for (int s = 0; s < S; s++) {
        int buf = s & (NSTG - 1);
        asm volatile("cp.async.wait_group 2;" ::: "memory");
        __syncthreads();
        // issue next stage into buffer freed one iteration ago (distinct from buf)
        if (s + 3 < S) { ISSUE(s + 3, (s + 3) & (NSTG - 1)); }
        else { asm volatile("cp.async.commit_group;" ::: "memory"); }

        const float* A_s = sA + buf * A_STAGE;
        const float* B_s = sB + buf * B_STAGE;
        // load ALL fragments for the 16-k stage, then run 64 MMAs back-to-back
        unsigned bfr[2][8][2], afr[2][4][4];
        #pragma unroll
        for (int kh = 0; kh < 2; kh++) {
            int ks = kh * 8;
            #pragma unroll
            for (int ni = 0; ni < 8; ni++) {
                int n0 = nW + ni * 8 + gid;
                bfr[kh][ni][0] = __float_as_uint(B_s[(ks + tig) * BSTRIDE + n0]);
                bfr[kh][ni][1] = __float_as_uint(B_s[(ks + tig + 4) * BSTRIDE + n0]);
            }
            #pragma unroll
            for (int mi = 0; mi < 4; mi++) {
                int m0 = mW + mi * 16 + gid;
                afr[kh][mi][0] = __float_as_uint(A_s[m0 * ASTRIDE + ks + tig]);
                afr[kh][mi][1] = __float_as_uint(A_s[(m0 + 8) * ASTRIDE + ks + tig]);
                afr[kh][mi][2] = __float_as_uint(A_s[m0 * ASTRIDE + ks + tig + 4]);
                afr[kh][mi][3] = __float_as_uint(A_s[(m0 + 8) * ASTRIDE + ks + tig + 4]);
            }
        }
        #pragma unroll
        for (int kh = 0; kh < 2; kh++)
            #pragma unroll
            for (int mi = 0; mi < 4; mi++)
                #pragma unroll
                for (int ni = 0; ni < 8; ni++)
                    mma_tf32(acc[mi][ni], afr[kh][mi], bfr[kh][ni]);
    }
    #undef ISSUE
    asm volatile("cp.async.wait_group 0;" ::: "memory");

    // ---------------- epilogue ----------------
    float2 bb2[8];
    #pragma unroll
    for (int ni = 0; ni < 8; ni++)
        bb2[ni] = *(const float2*)(bias + colB + nW + ni * 8 + 2 * tig);

    #pragma unroll
    for (int mi = 0; mi < 4; mi++) {
        #pragma unroll
        for (int half = 0; half < 2; half++) {
            size_t row = rowBase + mW + mi * 16 + gid + half * 8;
            size_t dstRow = 0;
            if (EPI == 2) {
                int win = (int)(row / NTOK), n = (int)(row % NTOK);
                int bbt = win >> 6, wi = win & 63;
                int wr = wi >> 3, wc = wi & 7;
                int rs = wr * 7 + n / 7, cs = wc * 7 + n % 7;
                int rr = (rs + SHIFT) % HIMG, cg = (cs + SHIFT) % HIMG;
                dstRow = ((size_t)bbt * (HIMG * HIMG) + rr * HIMG + cg) * CDIM;
            }
            #pragma unroll
            for (int ni = 0; ni < 8; ni++) {
                int col = colB + nW + ni * 8 + 2 * tig;
                float v0 = acc[mi][ni][half * 2]     + bb2[ni].x;
                float v1 = acc[mi][ni][half * 2 + 1] + bb2[ni].y;
                if (EPI == 0) {
                    *(float2*)(&Cout[row * N + col]) = make_float2(v0, v1);
                } else if (EPI == 1) {
                    v0 = tfr(0.5f * v0 * (1.0f + erff(v0 * 0.70710678118654752f)));
                    v1 = tfr(0.5f * v1 * (1.0f + erff(v1 * 0.70710678118654752f)));
                    *(float2*)(&Cout[row * N + col]) = make_float2(v0, v1);
                } else if (EPI == 2) {
                    float2 rv = *(const float2*)(&res[dstRow + col]);
                    *(float2*)(&Cout[dstRow + col]) = make_float2(rv.x + v0, rv.y + v1);
                } else {
                    size_t o = row * N + col;
                    float2 rv = *(const float2*)(&res[o]);
                    *(float2*)(&Cout[o]) = make_float2(rv.x + v0, rv.y + v1);
                }
            }
        }
    }
}

// ---------------- windowed attention (conflict-free padded smem) -------------
#define PAD 36
__global__ __launch_bounds__(256) void k_attn(const float* __restrict__ qkv,
                                              const float* __restrict__ rpb,
                                              float* __restrict__ out) {
    __shared__ __align__(16) float q [NTOK][PAD];
    __shared__ __align__(16) float kk[NTOK][PAD];
    __shared__ __align__(16) float vv[NTOK][PAD];
    __shared__ float s[NTOK][NTOK + 1];
    __shared__ float sbias[169];
    __shared__ int lab[NTOK];

    int w = blockIdx.x, h = blockIdx.y, tid = threadIdx.x;
    const float scale = 0.17677669529663689f;

    size_t base = (size_t)w * NTOK * C3 + h * HD;
    for (int idx = tid; idx < NTOK * 8; idx += 256) {
        int n = idx >> 3, t4 = (idx & 7) * 4;
        const float* rbq = qkv + base + (size_t)n * C3 + t4;
        float4 a = *(const float4*)rbq;
        a.x *= scale; a.y *= scale; a.z *= scale; a.w *= scale;
        *(float4*)&q[n][t4] = a;
        *(float4*)&kk[n][t4] = *(const float4*)(rbq + CDIM);
        *(float4*)&vv[n][t4] = *(const float4*)(rbq + 2 * CDIM);
    }
    if (tid < 169) sbias[tid] = rpb[tid * HEADS + h];
    if (tid >= 192 && tid < 192 + NTOK) {
        int n = tid - 192;
        int wi = w & 63, wr = wi >> 3, wc = wi & 7;
        int rs = wr * 7 + n / 7, cs = wc * 7 + n % 7;
        int rr = (rs < HIMG - 7) ? 0 : ((rs < HIMG - SHIFT) ? 1 : 2);
        int cc = (cs < HIMG - 7) ? 0 : ((cs < HIMG - SHIFT) ? 1 : 2);
        lab[n] = rr * 3 + cc;
    }
    __syncthreads();

    for (int idx = tid; idx < NTOK * NTOK; idx += 256) {
        int i = idx / NTOK, j = idx % NTOK;
        float acc = 0.f;
        #pragma unroll
        for (int t = 0; t < HD / 4; t++) {
            float4 a = *(const float4*)&q[i][4 * t];
            float4 bq = *(const float4*)&kk[j][4 * t];
            acc += a.x * bq.x + a.y * bq.y + a.z * bq.z + a.w * bq.w;
        }
        int ri = i / 7, ci = i % 7, rj = j / 7, cj = j % 7;
        acc += sbias[(ri - rj + 6) * 13 + (ci - cj + 6)];
        if (lab[i] != lab[j]) acc -= 100.0f;
        s[i][j] = acc;
    }
    __syncthreads();

    int warp = tid >> 5, lane = tid & 31;
    for (int i = warp; i < NTOK; i += 8) {
        float v0 = s[i][lane];
        float v1 = (lane + 32 < NTOK) ? s[i][lane + 32] : -1e30f;
        float mx = fmaxf(v0, v1);
        #pragma unroll
        for (int o = 16; o > 0; o >>= 1) mx = fmaxf(mx, __shfl_xor_sync(0xffffffffu, mx, o));
        float e0 = __expf(v0 - mx);
        float e1 = (lane + 32 < NTOK) ? __expf(v1 - mx) : 0.f;
        float sum = e0 + e1;
        #pragma unroll
        for (int o = 16; o > 0; o >>= 1) sum += __shfl_xor_sync(0xffffffffu, sum, o);
        float inv = 1.f / sum;
        s[i][lane] = e0 * inv;
        if (lane + 32 < NTOK) s[i][lane + 32] = e1 * inv;
    }
    __syncthreads();

    for (int idx = tid; idx < NTOK * 8; idx += 256) {
        int i = idx >> 3, t4 = (idx & 7) * 4;
        float4 acc = make_float4(0.f, 0.f, 0.f, 0.f);
        #pragma unroll 7
        for (int j = 0; j < NTOK; j++) {
            float sj = s[i][j];
            float4 v4 = *(const float4*)&vv[j][t4];
            acc.x += sj * v4.x; acc.y += sj * v4.y;
            acc.z += sj * v4.z; acc.w += sj * v4.w;
        }
        acc.x = tfr(acc.x); acc.y = tfr(acc.y);
        acc.z = tfr(acc.z); acc.w = tfr(acc.w);
        *(float4*)&out[((size_t)w * NTOK + i) * CDIM + h * HD + t4] = acc;
    }
}

// ---------------- launch ----------------
extern "C" void kernel_launch(void* const* d_in, const int* in_sizes, int n_in,
                              void* d_out, int out_size) {
    const float* x     = (const float*)d_in[0];
    const float* n1w   = (const float*)d_in[1];
    const float* n1b   = (const float*)d_in[2];
    const float* qkvw  = (const float*)d_in[3];
    const float* qkvb  = (const float*)d_in[4];
    const float* rpb   = (const float*)d_in[5];
    const float* projw = (const float*)d_in[6];
    const float* projb = (const float*)d_in[7];
    const float* n2w   = (const float*)d_in[8];
    const float* n2b   = (const float*)d_in[9];
    const float* fc1w  = (const float*)d_in[10];
    const float* fc1b  = (const float*)d_in[11];
    const float* fc2w  = (const float*)d_in[12];
    const float* fc2b  = (const float*)d_in[13];
    float* out = (float*)d_out;

    float *p_xw, *p_qkv, *p_att, *p_xn2, *p_hid, *p_wr;
    cudaGetSymbolAddress((void**)&p_xw,  g_xw);
    cudaGetSymbolAddress((void**)&p_qkv, g_qkv);
    cudaGetSymbolAddress((void**)&p_att, g_att);
    cudaGetSymbolAddress((void**)&p_xn2, g_xn2);
    cudaGetSymbolAddress((void**)&p_hid, g_hid);
    cudaGetSymbolAddress((void**)&p_wr,  g_wr);

    cudaFuncSetAttribute(k_mma<0>, cudaFuncAttributeMaxDynamicSharedMemorySize, DSMEM_BYTES);
    cudaFuncSetAttribute(k_mma<1>, cudaFuncAttributeMaxDynamicSharedMemorySize, DSMEM_BYTES);
    cudaFuncSetAttribute(k_mma<2>, cudaFuncAttributeMaxDynamicSharedMemorySize, DSMEM_BYTES);
    cudaFuncSetAttribute(k_mma<3>, cudaFuncAttributeMaxDynamicSharedMemorySize, DSMEM_BYTES);

    // 0) weight tf32 rounding (single launch)
    k_round4<<<(1769472 + 255) / 256, 256>>>(qkvw, projw, fc1w, fc2w, p_wr);
    // 1) LN1 + shift + partition
    k_ln<1><<<NROWS / 4, 128>>>(x, n1w, n1b, p_xw);
    // 2) qkv
    k_mma<0><<<dim3(C3 / 128, NROWS / 256), 256, DSMEM_BYTES>>>(
        p_xw, p_wr + WR_QKV, qkvb, p_qkv, CDIM, C3, nullptr);
    // 3) attention
    k_attn<<<dim3(NROWS / NTOK, HEADS), 256>>>(p_qkv, rpb, p_att);
    // 4) proj + reverse/unshift + residual -> out holds x2
    k_mma<2><<<dim3(CDIM / 128, NROWS / 256), 256, DSMEM_BYTES>>>(
        p_att, p_wr + WR_PROJ, projb, out, CDIM, CDIM, x);
    // 5) LN2
    k_ln<0><<<NROWS / 4, 128>>>(out, n2w, n2b, p_xn2);
    // 6) fc1 + gelu
    k_mma<1><<<dim3(HIDD / 128, NROWS / 256), 256, DSMEM_BYTES>>>(
        p_xn2, p_wr + WR_FC1, fc1b, p_hid, CDIM, HIDD, nullptr);
    // 7) fc2 + residual
    k_mma<3><<<dim3(CDIM / 128, NROWS / 256), 256, DSMEM_BYTES>>>(
        p_hid, p_wr + WR_FC2, fc2b, out, HIDD, CDIM, out);
}

// round 9
// speedup vs baseline: 3.5438x; 1.1603x over previous
#include <cuda_runtime.h>
#include <math.h>
#include <stdint.h>

// ---------------- problem constants ----------------
#define BATCH 32
#define HIMG  56
#define CDIM  384
#define NTOK  49
#define NWIN  64
#define NROWS 100352
#define C3    1152
#define HIDD  1536
#define HEADS 12
#define HD    32
#define SHIFT 3

// ---------------- scratch ----------------
__device__ float g_xw [(size_t)NROWS * CDIM];
__device__ float g_qkv[(size_t)NROWS * C3];
__device__ float g_att[(size_t)NROWS * CDIM];
__device__ float g_xn2[(size_t)NROWS * CDIM];
__device__ float g_hid[(size_t)NROWS * HIDD];
__device__ float g_wr [1769472];

#define WR_QKV 0
#define WR_PROJ 442368
#define WR_FC1 589824
#define WR_FC2 1179648

// ---------------- helpers ----------------
__device__ __forceinline__ unsigned f2tf(float f) {
    unsigned u; asm("cvt.rna.tf32.f32 %0, %1;" : "=r"(u) : "f"(f)); return u;
}
__device__ __forceinline__ float tfr(float f) { return __uint_as_float(f2tf(f)); }

__device__ __forceinline__ uint32_t s2u(const void* p) {
    uint32_t a;
    asm("{ .reg .u64 t; cvta.to.shared.u64 t, %1; cvt.u32.u64 %0, t; }" : "=r"(a) : "l"(p));
    return a;
}
__device__ __forceinline__ void cp16(uint32_t dst, const void* src) {
    asm volatile("cp.async.cg.shared.global [%0], [%1], 16;" :: "r"(dst), "l"(src));
}
__device__ __forceinline__ void mma_tf32(float c[4], const unsigned a[4], const unsigned b[2]) {
    asm volatile("mma.sync.aligned.m16n8k8.row.col.f32.tf32.tf32.f32 "
                 "{%0,%1,%2,%3}, {%4,%5,%6,%7}, {%8,%9}, {%0,%1,%2,%3};"
                 : "+f"(c[0]), "+f"(c[1]), "+f"(c[2]), "+f"(c[3])
                 : "r"(a[0]), "r"(a[1]), "r"(a[2]), "r"(a[3]),
                   "r"(b[0]), "r"(b[1]));
}

// ---------------- merged weight tf32 rounding ----------------
__global__ __launch_bounds__(256) void k_round4(const float* __restrict__ w0,
                                                const float* __restrict__ w1,
                                                const float* __restrict__ w2,
                                                const float* __restrict__ w3,
                                                float* __restrict__ d) {
    int i = blockIdx.x * 256 + threadIdx.x;
    if (i >= 1769472) return;
    float v;
    if (i < 442368)       v = w0[i];
    else if (i < 589824)  v = w1[i - 442368];
    else if (i < 1179648) v = w2[i - 589824];
    else                  v = w3[i - 1179648];
    d[i] = tfr(v);
}

// ---------------- warp-per-row LN (+optional gather for LN1) ----------------
template<int GATHER>
__global__ __launch_bounds__(128) void k_ln(const float* __restrict__ x,
                                            const float* __restrict__ w,
                                            const float* __restrict__ b,
                                            float* __restrict__ dst_all) {
    int warp = threadIdx.x >> 5, lane = threadIdx.x & 31;
    int m = blockIdx.x * 4 + warp;
    const float* src;
    if (GATHER) {
        int win = m / NTOK, n = m % NTOK;
        int bb = win >> 6, wi = win & 63;
        int wr = wi >> 3, wc = wi & 7;
        int rs = wr * 7 + n / 7, cs = wc * 7 + n % 7;
        int r = (rs + SHIFT) % HIMG, c = (cs + SHIFT) % HIMG;
        src = x + ((size_t)bb * (HIMG * HIMG) + r * HIMG + c) * CDIM;
    } else {
        src = x + (size_t)m * CDIM;
    }
    float4 v[3];
    #pragma unroll
    for (int i = 0; i < 3; i++) v[i] = *(const float4*)(src + i * 128 + lane * 4);
    float s = 0.f, s2 = 0.f;
    #pragma unroll
    for (int i = 0; i < 3; i++) {
        s  += v[i].x + v[i].y + v[i].z + v[i].w;
        s2 += v[i].x * v[i].x + v[i].y * v[i].y + v[i].z * v[i].z + v[i].w * v[i].w;
    }
    #pragma unroll
    for (int o = 16; o > 0; o >>= 1) {
        s  += __shfl_xor_sync(0xffffffffu, s, o);
        s2 += __shfl_xor_sync(0xffffffffu, s2, o);
    }
    float mean = s * (1.f / CDIM);
    float rstd = rsqrtf(s2 * (1.f / CDIM) - mean * mean + 1e-5f);
    float* dst = dst_all + (size_t)m * CDIM;
    #pragma unroll
    for (int i = 0; i < 3; i++) {
        float4 wv = *(const float4*)(w + i * 128 + lane * 4);
        float4 bv = *(const float4*)(b + i * 128 + lane * 4);
        float4 o4;
        o4.x = tfr((v[i].x - mean) * rstd * wv.x + bv.x);
        o4.y = tfr((v[i].y - mean) * rstd * wv.y + bv.y);
        o4.z = tfr((v[i].z - mean) * rstd * wv.z + bv.z);
        o4.w = tfr((v[i].w - mean) * rstd * wv.w + bv.w);
        *(float4*)(dst + i * 128 + lane * 4) = o4;
    }
}

// ---------------- TF32 mma.sync GEMM: 256x128, warp 64x64, 4-buf cp.async ---
#define ASTRIDE 20
#define BSTRIDE 136
#define A_STAGE (256 * ASTRIDE)
#define B_STAGE (16 * BSTRIDE)
#define NSTG 4
#define DSMEM_BYTES ((NSTG * A_STAGE + NSTG * B_STAGE) * 4)

template<int EPI>
__global__ __launch_bounds__(256) void k_mma(const float* __restrict__ A,
                                             const float* __restrict__ Bg,
                                             const float* __restrict__ bias,
                                             float* __restrict__ Cout,
                                             int K, int N,
                                             const float* __restrict__ res) {
    extern __shared__ float smem[];
    float* sA = smem;
    float* sB = smem + NSTG * A_STAGE;
    uint32_t uA = s2u(sA), uB = s2u(sB);

    int tid = threadIdx.x, wid = tid >> 5, lane = tid & 31;
    int gid = lane >> 2, tig = lane & 3;
    int mW = (wid >> 1) * 64;
    int nW = (wid & 1) * 64;

    size_t rowBase = (size_t)blockIdx.y * 256;
    int colB = blockIdx.x * 128;
    const float* Ab = A + rowBase * K;

    float acc[4][8][4];
    #pragma unroll
    for (int mi = 0; mi < 4; mi++)
        #pragma unroll
        for (int ni = 0; ni < 8; ni++)
            #pragma unroll
            for (int r = 0; r < 4; r++) acc[mi][ni][r] = 0.f;

    int S = K >> 4;

    #define ISSUE(s, buf) { int k0 = (s) << 4; \
        _Pragma("unroll") for (int i = 0; i < 4; i++) { \
            int ch = tid + i * 256; int r = ch >> 2, c = ch & 3; \
            cp16(uA + ((buf) * A_STAGE + r * ASTRIDE + c * 4) * 4, \
                 Ab + (size_t)r * K + k0 + c * 4); } \
        _Pragma("unroll") for (int i = 0; i < 2; i++) { \
            int ch = tid + i * 256; int r = ch >> 5, c = ch & 31; \
            cp16(uB + ((buf) * B_STAGE + r * BSTRIDE + c * 4) * 4, \
                 Bg + (size_t)(k0 + r) * N + colB + c * 4); } \
        asm volatile("cp.async.commit_group;" ::: "memory"); }

    ISSUE(0, 0); ISSUE(1, 1); ISSUE(2, 2);

    for (int s = 0; s < S; s++) {
        int buf = s & (NSTG - 1);
        asm volatile("cp.async.wait_group 2;" ::: "memory");
        __syncthreads();
        if (s + 3 < S) { ISSUE(s + 3, (s + 3) & (NSTG - 1)); }
        else { asm volatile("cp.async.commit_group;" ::: "memory"); }

        const float* A_s = sA + buf * A_STAGE;
        const float* B_s = sB + buf * B_STAGE;
        unsigned bfr[2][8][2], afr[2][4][4];
        #pragma unroll
        for (int kh = 0; kh < 2; kh++) {
            int ks = kh * 8;
            #pragma unroll
            for (int ni = 0; ni < 8; ni++) {
                int n0 = nW + ni * 8 + gid;
                bfr[kh][ni][0] = __float_as_uint(B_s[(ks + tig) * BSTRIDE + n0]);
                bfr[kh][ni][1] = __float_as_uint(B_s[(ks + tig + 4) * BSTRIDE + n0]);
            }
            #pragma unroll
            for (int mi = 0; mi < 4; mi++) {
                int m0 = mW + mi * 16 + gid;
                afr[kh][mi][0] = __float_as_uint(A_s[m0 * ASTRIDE + ks + tig]);
                afr[kh][mi][1] = __float_as_uint(A_s[(m0 + 8) * ASTRIDE + ks + tig]);
                afr[kh][mi][2] = __float_as_uint(A_s[m0 * ASTRIDE + ks + tig + 4]);
                afr[kh][mi][3] = __float_as_uint(A_s[(m0 + 8) * ASTRIDE + ks + tig + 4]);
            }
        }
        #pragma unroll
        for (int kh = 0; kh < 2; kh++)
            #pragma unroll
            for (int mi = 0; mi < 4; mi++)
                #pragma unroll
                for (int ni = 0; ni < 8; ni++)
                    mma_tf32(acc[mi][ni], afr[kh][mi], bfr[kh][ni]);
    }
    #undef ISSUE
    asm volatile("cp.async.wait_group 0;" ::: "memory");

    float2 bb2[8];
    #pragma unroll
    for (int ni = 0; ni < 8; ni++)
        bb2[ni] = *(const float2*)(bias + colB + nW + ni * 8 + 2 * tig);

    #pragma unroll
    for (int mi = 0; mi < 4; mi++) {
        #pragma unroll
        for (int half = 0; half < 2; half++) {
            size_t row = rowBase + mW + mi * 16 + gid + half * 8;
            size_t dstRow = 0;
            if (EPI == 2) {
                int win = (int)(row / NTOK), n = (int)(row % NTOK);
                int bbt = win >> 6, wi = win & 63;
                int wr = wi >> 3, wc = wi & 7;
                int rs = wr * 7 + n / 7, cs = wc * 7 + n % 7;
                int rr = (rs + SHIFT) % HIMG, cg = (cs + SHIFT) % HIMG;
                dstRow = ((size_t)bbt * (HIMG * HIMG) + rr * HIMG + cg) * CDIM;
            }
            #pragma unroll
            for (int ni = 0; ni < 8; ni++) {
                int col = colB + nW + ni * 8 + 2 * tig;
                float v0 = acc[mi][ni][half * 2]     + bb2[ni].x;
                float v1 = acc[mi][ni][half * 2 + 1] + bb2[ni].y;
                if (EPI == 0) {
                    *(float2*)(&Cout[row * N + col]) = make_float2(v0, v1);
                } else if (EPI == 1) {
                    v0 = tfr(0.5f * v0 * (1.0f + erff(v0 * 0.70710678118654752f)));
                    v1 = tfr(0.5f * v1 * (1.0f + erff(v1 * 0.70710678118654752f)));
                    *(float2*)(&Cout[row * N + col]) = make_float2(v0, v1);
                } else if (EPI == 2) {
                    float2 rv = *(const float2*)(&res[dstRow + col]);
                    *(float2*)(&Cout[dstRow + col]) = make_float2(rv.x + v0, rv.y + v1);
                } else {
                    size_t o = row * N + col;
                    float2 rv = *(const float2*)(&res[o]);
                    *(float2*)(&Cout[o]) = make_float2(rv.x + v0, rv.y + v1);
                }
            }
        }
    }
}

// ---------------- windowed attention via mma.sync -----------------
// block = (window, head), 128 threads = 4 warps; warp w owns m-tile rows 16w..16w+15
#define PAD 36
#define PS 57
__global__ __launch_bounds__(128) void k_attn(const float* __restrict__ qkv,
                                              const float* __restrict__ rpb,
                                              float* __restrict__ out) {
    __shared__ __align__(16) float qs[64][PAD];
    __shared__ __align__(16) float ks[56][PAD];
    __shared__ __align__(16) float vv[56][PAD];
    __shared__ float ps[64][PS];
    __shared__ float sbias[169];

    int w = blockIdx.x, h = blockIdx.y, tid = threadIdx.x;
    int wid = tid >> 5, lane = tid & 31;
    int gid = lane >> 2, tig = lane & 3;
    const float scale = 0.17677669529663689f;

    // ---- load q/k/v rows 0..48, zero pad rows ----
    size_t base = (size_t)w * NTOK * C3 + h * HD;
    for (int idx = tid; idx < NTOK * 8; idx += 128) {
        int n = idx >> 3, t4 = (idx & 7) * 4;
        const float* rbq = qkv + base + (size_t)n * C3 + t4;
        float4 a = *(const float4*)rbq;
        a.x *= scale; a.y *= scale; a.z *= scale; a.w *= scale;
        *(float4*)&qs[n][t4] = a;
        *(float4*)&ks[n][t4] = *(const float4*)(rbq + CDIM);
        *(float4*)&vv[n][t4] = *(const float4*)(rbq + 2 * CDIM);
    }
    for (int idx = tid; idx < 15 * 8; idx += 128) {
        int n = 49 + (idx >> 3), t4 = (idx & 7) * 4;
        *(float4*)&qs[n][t4] = make_float4(0.f, 0.f, 0.f, 0.f);
        if (n < 56) {
            *(float4*)&ks[n][t4] = make_float4(0.f, 0.f, 0.f, 0.f);
            *(float4*)&vv[n][t4] = make_float4(0.f, 0.f, 0.f, 0.f);
        }
    }
    for (int i = tid; i < 169; i += 128) sbias[i] = rpb[i * HEADS + h];
    __syncthreads();

    // ---- phase 1: S = Q @ K^T (warp m-tile 16, N=56, K=32) ----
    int m0 = wid * 16;
    float acc[7][4];
    #pragma unroll
    for (int ni = 0; ni < 7; ni++)
        #pragma unroll
        for (int r = 0; r < 4; r++) acc[ni][r] = 0.f;

    #pragma unroll
    for (int kk4 = 0; kk4 < 4; kk4++) {
        int k0 = kk4 * 8;
        unsigned a[4];
        a[0] = __float_as_uint(qs[m0 + gid][k0 + tig]);
        a[1] = __float_as_uint(qs[m0 + gid + 8][k0 + tig]);
        a[2] = __float_as_uint(qs[m0 + gid][k0 + tig + 4]);
        a[3] = __float_as_uint(qs[m0 + gid + 8][k0 + tig + 4]);
        #pragma unroll
        for (int ni = 0; ni < 7; ni++) {
            unsigned b[2];
            b[0] = __float_as_uint(ks[ni * 8 + gid][k0 + tig]);
            b[1] = __float_as_uint(ks[ni * 8 + gid][k0 + tig + 4]);
            mma_tf32(acc[ni], a, b);
        }
    }

    // ---- bias + mask + softmax in fragments ----
    int wi = w & 63, wr = wi >> 3, wc = wi & 7;
    int r1 = m0 + gid, r2 = r1 + 8;
    int ri1 = r1 / 7, ci1 = r1 % 7, ri2 = r2 / 7, ci2 = r2 % 7;
    int rs1 = wr * 7 + ri1, cs1 = wc * 7 + ci1;
    int rs2 = wr * 7 + ri2, cs2 = wc * 7 + ci2;
    int lab1 = ((rs1 < HIMG - 7) ? 0 : ((rs1 < HIMG - SHIFT) ? 1 : 2)) * 3
             + ((cs1 < HIMG - 7) ? 0 : ((cs1 < HIMG - SHIFT) ? 1 : 2));
    int lab2 = ((rs2 < HIMG - 7) ? 0 : ((rs2 < HIMG - SHIFT) ? 1 : 2)) * 3
             + ((cs2 < HIMG - 7) ? 0 : ((cs2 < HIMG - SHIFT) ? 1 : 2));

    float v1[14], v2[14];
    float mx1 = -1e30f, mx2 = -1e30f;
    #pragma unroll
    for (int ni = 0; ni < 7; ni++) {
        #pragma unroll
        for (int bb = 0; bb < 2; bb++) {
            int j = ni * 8 + 2 * tig + bb;
            float t1 = -1e30f, t2 = -1e30f;
            if (j < NTOK) {
                int rj = j / 7, cj = j % 7;
                int rsj = wr * 7 + rj, csj = wc * 7 + cj;
                int labj = ((rsj < HIMG - 7) ? 0 : ((rsj < HIMG - SHIFT) ? 1 : 2)) * 3
                         + ((csj < HIMG - 7) ? 0 : ((csj < HIMG - SHIFT) ? 1 : 2));
                if (r1 < NTOK) {
                    t1 = acc[ni][bb] + sbias[(ri1 - rj + 6) * 13 + (ci1 - cj + 6)];
                    if (lab1 != labj) t1 -= 100.0f;
                }
                if (r2 < NTOK) {
                    t2 = acc[ni][2 + bb] + sbias[(ri2 - rj + 6) * 13 + (ci2 - cj + 6)];
                    if (lab2 != labj) t2 -= 100.0f;
                }
            }
            v1[ni * 2 + bb] = t1; v2[ni * 2 + bb] = t2;
            mx1 = fmaxf(mx1, t1); mx2 = fmaxf(mx2, t2);
        }
    }
    #pragma unroll
    for (int o = 1; o < 4; o <<= 1) {
        mx1 = fmaxf(mx1, __shfl_xor_sync(0xffffffffu, mx1, o));
        mx2 = fmaxf(mx2, __shfl_xor_sync(0xffffffffu, mx2, o));
    }
    float s1 = 0.f, s2 = 0.f;
    #pragma unroll
    for (int t = 0; t < 14; t++) {
        v1[t] = __expf(v1[t] - mx1); s1 += v1[t];
        v2[t] = __expf(v2[t] - mx2); s2 += v2[t];
    }
    #pragma unroll
    for (int o = 1; o < 4; o <<= 1) {
        s1 += __shfl_xor_sync(0xffffffffu, s1, o);
        s2 += __shfl_xor_sync(0xffffffffu, s2, o);
    }
    float inv1 = 1.f / s1, inv2 = 1.f / s2;
    #pragma unroll
    for (int ni = 0; ni < 7; ni++) {
        int j = ni * 8 + 2 * tig;
        ps[r1][j]     = v1[ni * 2]     * inv1;
        ps[r1][j + 1] = v1[ni * 2 + 1] * inv1;
        ps[r2][j]     = v2[ni * 2]     * inv2;
        ps[r2][j + 1] = v2[ni * 2 + 1] * inv2;
    }
    __syncwarp();

    // ---- phase 2: O = P @ V (M=16/warp, N=32, K=56) ----
    float oacc[4][4];
    #pragma unroll
    for (int ni = 0; ni < 4; ni++)
        #pragma unroll
        for (int r = 0; r < 4; r++) oacc[ni][r] = 0.f;

    #pragma unroll
    for (int kk7 = 0; kk7 < 7; kk7++) {
        int k0 = kk7 * 8;
        unsigned a[4];
        a[0] = f2tf(ps[m0 + gid][k0 + tig]);
        a[1] = f2tf(ps[m0 + gid + 8][k0 + tig]);
        a[2] = f2tf(ps[m0 + gid][k0 + tig + 4]);
        a[3] = f2tf(ps[m0 + gid + 8][k0 + tig + 4]);
        #pragma unroll
        for (int ni = 0; ni < 4; ni++) {
            unsigned b[2];
            b[0] = __float_as_uint(vv[k0 + tig][ni * 8 + gid]);
            b[1] = __float_as_uint(vv[k0 + tig + 4][ni * 8 + gid]);
            mma_tf32(oacc[ni], a, b);
        }
    }

    // ---- store O ----
    #pragma unroll
    for (int half = 0; half < 2; half++) {
        int r = (half == 0) ? r1 : r2;
        if (r < NTOK) {
            float* op = out + ((size_t)w * NTOK + r) * CDIM + h * HD;
            #pragma unroll
            for (int ni = 0; ni < 4; ni++) {
                float x0 = tfr(oacc[ni][half * 2]);
                float x1 = tfr(oacc[ni][half * 2 + 1]);
                *(float2*)(op + ni * 8 + 2 * tig) = make_float2(x0, x1);
            }
        }
    }
}

// ---------------- launch ----------------
extern "C" void kernel_launch(void* const* d_in, const int* in_sizes, int n_in,
                              void* d_out, int out_size) {
    const float* x     = (const float*)d_in[0];
    const float* n1w   = (const float*)d_in[1];
    const float* n1b   = (const float*)d_in[2];
    const float* qkvw  = (const float*)d_in[3];
    const float* qkvb  = (const float*)d_in[4];
    const float* rpb   = (const float*)d_in[5];
    const float* projw = (const float*)d_in[6];
    const float* projb = (const float*)d_in[7];
    const float* n2w   = (const float*)d_in[8];
    const float* n2b   = (const float*)d_in[9];
    const float* fc1w  = (const float*)d_in[10];
    const float* fc1b  = (const float*)d_in[11];
    const float* fc2w  = (const float*)d_in[12];
    const float* fc2b  = (const float*)d_in[13];
    float* out = (float*)d_out;

    float *p_xw, *p_qkv, *p_att, *p_xn2, *p_hid, *p_wr;
    cudaGetSymbolAddress((void**)&p_xw,  g_xw);
    cudaGetSymbolAddress((void**)&p_qkv, g_qkv);
    cudaGetSymbolAddress((void**)&p_att, g_att);
    cudaGetSymbolAddress((void**)&p_xn2, g_xn2);
    cudaGetSymbolAddress((void**)&p_hid, g_hid);
    cudaGetSymbolAddress((void**)&p_wr,  g_wr);

    cudaFuncSetAttribute(k_mma<0>, cudaFuncAttributeMaxDynamicSharedMemorySize, DSMEM_BYTES);
    cudaFuncSetAttribute(k_mma<1>, cudaFuncAttributeMaxDynamicSharedMemorySize, DSMEM_BYTES);
    cudaFuncSetAttribute(k_mma<2>, cudaFuncAttributeMaxDynamicSharedMemorySize, DSMEM_BYTES);
    cudaFuncSetAttribute(k_mma<3>, cudaFuncAttributeMaxDynamicSharedMemorySize, DSMEM_BYTES);

    // 0) weight tf32 rounding (single launch)
    k_round4<<<(1769472 + 255) / 256, 256>>>(qkvw, projw, fc1w, fc2w, p_wr);
    // 1) LN1 + shift + partition
    k_ln<1><<<NROWS / 4, 128>>>(x, n1w, n1b, p_xw);
    // 2) qkv
    k_mma<0><<<dim3(C3 / 128, NROWS / 256), 256, DSMEM_BYTES>>>(
        p_xw, p_wr + WR_QKV, qkvb, p_qkv, CDIM, C3, nullptr);
    // 3) attention (tensor-core)
    k_attn<<<dim3(NROWS / NTOK, HEADS), 128>>>(p_qkv, rpb, p_att);
    // 4) proj + reverse/unshift + residual -> out holds x2
    k_mma<2><<<dim3(CDIM / 128, NROWS / 256), 256, DSMEM_BYTES>>>(
        p_att, p_wr + WR_PROJ, projb, out, CDIM, CDIM, x);
    // 5) LN2
    k_ln<0><<<NROWS / 4, 128>>>(out, n2w, n2b, p_xn2);
    // 6) fc1 + gelu
    k_mma<1><<<dim3(HIDD / 128, NROWS / 256), 256, DSMEM_BYTES>>>(
        p_xn2, p_wr + WR_FC1, fc1b, p_hid, CDIM, HIDD, nullptr);
    // 7) fc2 + residual
    k_mma<3><<<dim3(CDIM / 128, NROWS / 256), 256, DSMEM_BYTES>>>(
        p_hid, p_wr + WR_FC2, fc2b, out, HIDD, CDIM, out);
}

// round 10
// speedup vs baseline: 3.7689x; 1.0635x over previous
#include <cuda_runtime.h>
#include <math.h>
#include <stdint.h>

// ---------------- problem constants ----------------
#define BATCH 32
#define HIMG  56
#define CDIM  384
#define NTOK  49
#define NWIN  64
#define NROWS 100352
#define C3    1152
#define HIDD  1536
#define HEADS 12
#define HD    32
#define SHIFT 3

// ---------------- scratch ----------------
__device__ float g_xw [(size_t)NROWS * CDIM];
__device__ float g_qkv[(size_t)NROWS * C3];
__device__ float g_att[(size_t)NROWS * CDIM];
__device__ float g_xn2[(size_t)NROWS * CDIM];
__device__ float g_hid[(size_t)NROWS * HIDD];
__device__ float g_wr [1769472];

#define WR_QKV 0
#define WR_PROJ 442368
#define WR_FC1 589824
#define WR_FC2 1179648

// ---------------- helpers ----------------
__device__ __forceinline__ unsigned f2tf(float f) {
    unsigned u; asm("cvt.rna.tf32.f32 %0, %1;" : "=r"(u) : "f"(f)); return u;
}
__device__ __forceinline__ float tfr(float f) { return __uint_as_float(f2tf(f)); }

__device__ __forceinline__ uint32_t s2u(const void* p) {
    uint32_t a;
    asm("{ .reg .u64 t; cvta.to.shared.u64 t, %1; cvt.u32.u64 %0, t; }" : "=r"(a) : "l"(p));
    return a;
}
__device__ __forceinline__ void cp16(uint32_t dst, const void* src) {
    asm volatile("cp.async.cg.shared.global [%0], [%1], 16;" :: "r"(dst), "l"(src));
}
__device__ __forceinline__ void mma_tf32(float c[4], const unsigned a[4], const unsigned b[2]) {
    asm volatile("mma.sync.aligned.m16n8k8.row.col.f32.tf32.tf32.f32 "
                 "{%0,%1,%2,%3}, {%4,%5,%6,%7}, {%8,%9}, {%0,%1,%2,%3};"
                 : "+f"(c[0]), "+f"(c[1]), "+f"(c[2]), "+f"(c[3])
                 : "r"(a[0]), "r"(a[1]), "r"(a[2]), "r"(a[3]),
                   "r"(b[0]), "r"(b[1]));
}

// ---------------- merged weight tf32 rounding ----------------
__global__ __launch_bounds__(256) void k_round4(const float* __restrict__ w0,
                                                const float* __restrict__ w1,
                                                const float* __restrict__ w2,
                                                const float* __restrict__ w3,
                                                float* __restrict__ d) {
    int i = blockIdx.x * 256 + threadIdx.x;
    if (i >= 1769472) return;
    float v;
    if (i < 442368)       v = w0[i];
    else if (i < 589824)  v = w1[i - 442368];
    else if (i < 1179648) v = w2[i - 589824];
    else                  v = w3[i - 1179648];
    d[i] = tfr(v);
}

// ---------------- warp-per-row LN (+optional gather for LN1) ----------------
template<int GATHER>
__global__ __launch_bounds__(128) void k_ln(const float* __restrict__ x,
                                            const float* __restrict__ w,
                                            const float* __restrict__ b,
                                            float* __restrict__ dst_all) {
    int warp = threadIdx.x >> 5, lane = threadIdx.x & 31;
    int m = blockIdx.x * 4 + warp;
    const float* src;
    if (GATHER) {
        int win = m / NTOK, n = m % NTOK;
        int bb = win >> 6, wi = win & 63;
        int wr = wi >> 3, wc = wi & 7;
        int rs = wr * 7 + n / 7, cs = wc * 7 + n % 7;
        int r = (rs + SHIFT) % HIMG, c = (cs + SHIFT) % HIMG;
        src = x + ((size_t)bb * (HIMG * HIMG) + r * HIMG + c) * CDIM;
    } else {
        src = x + (size_t)m * CDIM;
    }
    float4 v[3];
    #pragma unroll
    for (int i = 0; i < 3; i++) v[i] = *(const float4*)(src + i * 128 + lane * 4);
    float s = 0.f, s2 = 0.f;
    #pragma unroll
    for (int i = 0; i < 3; i++) {
        s  += v[i].x + v[i].y + v[i].z + v[i].w;
        s2 += v[i].x * v[i].x + v[i].y * v[i].y + v[i].z * v[i].z + v[i].w * v[i].w;
    }
    #pragma unroll
    for (int o = 16; o > 0; o >>= 1) {
        s  += __shfl_xor_sync(0xffffffffu, s, o);
        s2 += __shfl_xor_sync(0xffffffffu, s2, o);
    }
    float mean = s * (1.f / CDIM);
    float rstd = rsqrtf(s2 * (1.f / CDIM) - mean * mean + 1e-5f);
    float* dst = dst_all + (size_t)m * CDIM;
    #pragma unroll
    for (int i = 0; i < 3; i++) {
        float4 wv = *(const float4*)(w + i * 128 + lane * 4);
        float4 bv = *(const float4*)(b + i * 128 + lane * 4);
        float4 o4;
        o4.x = tfr((v[i].x - mean) * rstd * wv.x + bv.x);
        o4.y = tfr((v[i].y - mean) * rstd * wv.y + bv.y);
        o4.z = tfr((v[i].z - mean) * rstd * wv.z + bv.z);
        o4.w = tfr((v[i].w - mean) * rstd * wv.w + bv.w);
        *(float4*)(dst + i * 128 + lane * 4) = o4;
    }
}

// ---------------- TF32 mma.sync GEMM: 128x128, warp 64x32, 4-buf, 2 CTA/SM --
#define ASTRIDE 20
#define BSTRIDE 136
#define A_STAGE (128 * ASTRIDE)
#define B_STAGE (16 * BSTRIDE)
#define NSTG 4
#define DSMEM_BYTES ((NSTG * A_STAGE + NSTG * B_STAGE) * 4)

template<int EPI>
__global__ __launch_bounds__(256, 2) void k_mma(const float* __restrict__ A,
                                                const float* __restrict__ Bg,
                                                const float* __restrict__ bias,
                                                float* __restrict__ Cout,
                                                int K, int N,
                                                const float* __restrict__ res) {
    extern __shared__ float smem[];
    float* sA = smem;                     // [NSTG][128][ASTRIDE]
    float* sB = smem + NSTG * A_STAGE;    // [NSTG][16][BSTRIDE]
    uint32_t uA = s2u(sA), uB = s2u(sB);

    int tid = threadIdx.x, wid = tid >> 5, lane = tid & 31;
    int gid = lane >> 2, tig = lane & 3;
    int mW = (wid >> 2) * 64;   // 0,64
    int nW = (wid & 3) * 32;    // 0,32,64,96

    size_t rowBase = (size_t)blockIdx.y * 128;
    int colB = blockIdx.x * 128;
    const float* Ab = A + rowBase * K;

    float acc[4][4][4];
    #pragma unroll
    for (int mi = 0; mi < 4; mi++)
        #pragma unroll
        for (int ni = 0; ni < 4; ni++)
            #pragma unroll
            for (int r = 0; r < 4; r++) acc[mi][ni][r] = 0.f;

    int S = K >> 4;

    #define ISSUE(s, buf) { int k0 = (s) << 4; \
        _Pragma("unroll") for (int i = 0; i < 2; i++) { \
            int ch = tid + i * 256; int r = ch >> 2, c = ch & 3; \
            cp16(uA + ((buf) * A_STAGE + r * ASTRIDE + c * 4) * 4, \
                 Ab + (size_t)r * K + k0 + c * 4); } \
        _Pragma("unroll") for (int i = 0; i < 2; i++) { \
            int ch = tid + i * 256; int r = ch >> 5, c = ch & 31; \
            cp16(uB + ((buf) * B_STAGE + r * BSTRIDE + c * 4) * 4, \
                 Bg + (size_t)(k0 + r) * N + colB + c * 4); } \
        asm volatile("cp.async.commit_group;" ::: "memory"); }

    ISSUE(0, 0); ISSUE(1, 1); ISSUE(2, 2);

    for (int s = 0; s < S; s++) {
        int buf = s & (NSTG - 1);
        asm volatile("cp.async.wait_group 2;" ::: "memory");
        __syncthreads();
        if (s + 3 < S) { ISSUE(s + 3, (s + 3) & (NSTG - 1)); }
        else { asm volatile("cp.async.commit_group;" ::: "memory"); }

        const float* A_s = sA + buf * A_STAGE;
        const float* B_s = sB + buf * B_STAGE;
        #pragma unroll
        for (int kh = 0; kh < 2; kh++) {
            int ks = kh * 8;
            unsigned bfr[4][2], afr[4][4];
            #pragma unroll
            for (int ni = 0; ni < 4; ni++) {
                int n0 = nW + ni * 8 + gid;
                bfr[ni][0] = __float_as_uint(B_s[(ks + tig) * BSTRIDE + n0]);
                bfr[ni][1] = __float_as_uint(B_s[(ks + tig + 4) * BSTRIDE + n0]);
            }
            #pragma unroll
            for (int mi = 0; mi < 4; mi++) {
                int m0 = mW + mi * 16 + gid;
                afr[mi][0] = __float_as_uint(A_s[m0 * ASTRIDE + ks + tig]);
                afr[mi][1] = __float_as_uint(A_s[(m0 + 8) * ASTRIDE + ks + tig]);
                afr[mi][2] = __float_as_uint(A_s[m0 * ASTRIDE + ks + tig + 4]);
                afr[mi][3] = __float_as_uint(A_s[(m0 + 8) * ASTRIDE + ks + tig + 4]);
            }
            #pragma unroll
            for (int mi = 0; mi < 4; mi++)
                #pragma unroll
                for (int ni = 0; ni < 4; ni++)
                    mma_tf32(acc[mi][ni], afr[mi], bfr[ni]);
        }
    }
    #undef ISSUE
    asm volatile("cp.async.wait_group 0;" ::: "memory");

    // ---------------- epilogue ----------------
    float2 bb2[4];
    #pragma unroll
    for (int ni = 0; ni < 4; ni++)
        bb2[ni] = *(const float2*)(bias + colB + nW + ni * 8 + 2 * tig);

    #pragma unroll
    for (int mi = 0; mi < 4; mi++) {
        #pragma unroll
        for (int half = 0; half < 2; half++) {
            size_t row = rowBase + mW + mi * 16 + gid + half * 8;
            size_t dstRow = 0;
            if (EPI == 2) {
                int win = (int)(row / NTOK), n = (int)(row % NTOK);
                int bbt = win >> 6, wi = win & 63;
                int wr = wi >> 3, wc = wi & 7;
                int rs = wr * 7 + n / 7, cs = wc * 7 + n % 7;
                int rr = (rs + SHIFT) % HIMG, cg = (cs + SHIFT) % HIMG;
                dstRow = ((size_t)bbt * (HIMG * HIMG) + rr * HIMG + cg) * CDIM;
            }
            #pragma unroll
            for (int ni = 0; ni < 4; ni++) {
                int col = colB + nW + ni * 8 + 2 * tig;
                float v0 = acc[mi][ni][half * 2]     + bb2[ni].x;
                float v1 = acc[mi][ni][half * 2 + 1] + bb2[ni].y;
                if (EPI == 0) {
                    *(float2*)(&Cout[row * N + col]) = make_float2(v0, v1);
                } else if (EPI == 1) {
                    v0 = tfr(0.5f * v0 * (1.0f + erff(v0 * 0.70710678118654752f)));
                    v1 = tfr(0.5f * v1 * (1.0f + erff(v1 * 0.70710678118654752f)));
                    *(float2*)(&Cout[row * N + col]) = make_float2(v0, v1);
                } else if (EPI == 2) {
                    float2 rv = *(const float2*)(&res[dstRow + col]);
                    *(float2*)(&Cout[dstRow + col]) = make_float2(rv.x + v0, rv.y + v1);
                } else {
                    size_t o = row * N + col;
                    float2 rv = *(const float2*)(&res[o]);
                    *(float2*)(&Cout[o]) = make_float2(rv.x + v0, rv.y + v1);
                }
            }
        }
    }
}

// ---------------- windowed attention via mma.sync -----------------
#define PAD 36
#define PS 57
__global__ __launch_bounds__(128) void k_attn(const float* __restrict__ qkv,
                                              const float* __restrict__ rpb,
                                              float* __restrict__ out) {
    __shared__ __align__(16) float qs[64][PAD];
    __shared__ __align__(16) float ks[56][PAD];
    __shared__ __align__(16) float vv[56][PAD];
    __shared__ float ps[64][PS];
    __shared__ float sbias[169];

    int w = blockIdx.x, h = blockIdx.y, tid = threadIdx.x;
    int wid = tid >> 5, lane = tid & 31;
    int gid = lane >> 2, tig = lane & 3;
    const float scale = 0.17677669529663689f;

    size_t base = (size_t)w * NTOK * C3 + h * HD;
    for (int idx = tid; idx < NTOK * 8; idx += 128) {
        int n = idx >> 3, t4 = (idx & 7) * 4;
        const float* rbq = qkv + base + (size_t)n * C3 + t4;
        float4 a = *(const float4*)rbq;
        a.x *= scale; a.y *= scale; a.z *= scale; a.w *= scale;
        *(float4*)&qs[n][t4] = a;
        *(float4*)&ks[n][t4] = *(const float4*)(rbq + CDIM);
        *(float4*)&vv[n][t4] = *(const float4*)(rbq + 2 * CDIM);
    }
    for (int idx = tid; idx < 15 * 8; idx += 128) {
        int n = 49 + (idx >> 3), t4 = (idx & 7) * 4;
        *(float4*)&qs[n][t4] = make_float4(0.f, 0.f, 0.f, 0.f);
        if (n < 56) {
            *(float4*)&ks[n][t4] = make_float4(0.f, 0.f, 0.f, 0.f);
            *(float4*)&vv[n][t4] = make_float4(0.f, 0.f, 0.f, 0.f);
        }
    }
    for (int i = tid; i < 169; i += 128) sbias[i] = rpb[i * HEADS + h];
    __syncthreads();

    int m0 = wid * 16;
    float acc[7][4];
    #pragma unroll
    for (int ni = 0; ni < 7; ni++)
        #pragma unroll
        for (int r = 0; r < 4; r++) acc[ni][r] = 0.f;

    #pragma unroll
    for (int kk4 = 0; kk4 < 4; kk4++) {
        int k0 = kk4 * 8;
        unsigned a[4];
        a[0] = __float_as_uint(qs[m0 + gid][k0 + tig]);
        a[1] = __float_as_uint(qs[m0 + gid + 8][k0 + tig]);
        a[2] = __float_as_uint(qs[m0 + gid][k0 + tig + 4]);
        a[3] = __float_as_uint(qs[m0 + gid + 8][k0 + tig + 4]);
        #pragma unroll
        for (int ni = 0; ni < 7; ni++) {
            unsigned b[2];
            b[0] = __float_as_uint(ks[ni * 8 + gid][k0 + tig]);
            b[1] = __float_as_uint(ks[ni * 8 + gid][k0 + tig + 4]);
            mma_tf32(acc[ni], a, b);
        }
    }

    int wi = w & 63, wr = wi >> 3, wc = wi & 7;
    int r1 = m0 + gid, r2 = r1 + 8;
    int ri1 = r1 / 7, ci1 = r1 % 7, ri2 = r2 / 7, ci2 = r2 % 7;
    int rs1 = wr * 7 + ri1, cs1 = wc * 7 + ci1;
    int rs2 = wr * 7 + ri2, cs2 = wc * 7 + ci2;
    int lab1 = ((rs1 < HIMG - 7) ? 0 : ((rs1 < HIMG - SHIFT) ? 1 : 2)) * 3
             + ((cs1 < HIMG - 7) ? 0 : ((cs1 < HIMG - SHIFT) ? 1 : 2));
    int lab2 = ((rs2 < HIMG - 7) ? 0 : ((rs2 < HIMG - SHIFT) ? 1 : 2)) * 3
             + ((cs2 < HIMG - 7) ? 0 : ((cs2 < HIMG - SHIFT) ? 1 : 2));

    float v1[14], v2[14];
    float mx1 = -1e30f, mx2 = -1e30f;
    #pragma unroll
    for (int ni = 0; ni < 7; ni++) {
        #pragma unroll
        for (int bb = 0; bb < 2; bb++) {
            int j = ni * 8 + 2 * tig + bb;
            float t1 = -1e30f, t2 = -1e30f;
            if (j < NTOK) {
                int rj = j / 7, cj = j % 7;
                int rsj = wr * 7 + rj, csj = wc * 7 + cj;
                int labj = ((rsj < HIMG - 7) ? 0 : ((rsj < HIMG - SHIFT) ? 1 : 2)) * 3
                         + ((csj < HIMG - 7) ? 0 : ((csj < HIMG - SHIFT) ? 1 : 2));
                if (r1 < NTOK) {
                    t1 = acc[ni][bb] + sbias[(ri1 - rj + 6) * 13 + (ci1 - cj + 6)];
                    if (lab1 != labj) t1 -= 100.0f;
                }
                if (r2 < NTOK) {
                    t2 = acc[ni][2 + bb] + sbias[(ri2 - rj + 6) * 13 + (ci2 - cj + 6)];
                    if (lab2 != labj) t2 -= 100.0f;
                }
            }
            v1[ni * 2 + bb] = t1; v2[ni * 2 + bb] = t2;
            mx1 = fmaxf(mx1, t1); mx2 = fmaxf(mx2, t2);
        }
    }
    #pragma unroll
    for (int o = 1; o < 4; o <<= 1) {
        mx1 = fmaxf(mx1, __shfl_xor_sync(0xffffffffu, mx1, o));
        mx2 = fmaxf(mx2, __shfl_xor_sync(0xffffffffu, mx2, o));
    }
    float s1 = 0.f, s2 = 0.f;
    #pragma unroll
    for (int t = 0; t < 14; t++) {
        v1[t] = __expf(v1[t] - mx1); s1 += v1[t];
        v2[t] = __expf(v2[t] - mx2); s2 += v2[t];
    }
    #pragma unroll
    for (int o = 1; o < 4; o <<= 1) {
        s1 += __shfl_xor_sync(0xffffffffu, s1, o);
        s2 += __shfl_xor_sync(0xffffffffu, s2, o);
    }
    float inv1 = 1.f / s1, inv2 = 1.f / s2;
    #pragma unroll
    for (int ni = 0; ni < 7; ni++) {
        int j = ni * 8 + 2 * tig;
        ps[r1][j]     = v1[ni * 2]     * inv1;
        ps[r1][j + 1] = v1[ni * 2 + 1] * inv1;
        ps[r2][j]     = v2[ni * 2]     * inv2;
        ps[r2][j + 1] = v2[ni * 2 + 1] * inv2;
    }
    __syncwarp();

    float oacc[4][4];
    #pragma unroll
    for (int ni = 0; ni < 4; ni++)
        #pragma unroll
        for (int r = 0; r < 4; r++) oacc[ni][r] = 0.f;

    #pragma unroll
    for (int kk7 = 0; kk7 < 7; kk7++) {
        int k0 = kk7 * 8;
        unsigned a[4];
        a[0] = f2tf(ps[m0 + gid][k0 + tig]);
        a[1] = f2tf(ps[m0 + gid + 8][k0 + tig]);
        a[2] = f2tf(ps[m0 + gid][k0 + tig + 4]);
        a[3] = f2tf(ps[m0 + gid + 8][k0 + tig + 4]);
        #pragma unroll
        for (int ni = 0; ni < 4; ni++) {
            unsigned b[2];
            b[0] = __float_as_uint(vv[k0 + tig][ni * 8 + gid]);
            b[1] = __float_as_uint(vv[k0 + tig + 4][ni * 8 + gid]);
            mma_tf32(oacc[ni], a, b);
        }
    }

    #pragma unroll
    for (int half = 0; half < 2; half++) {
        int r = (half == 0) ? r1 : r2;
        if (r < NTOK) {
            float* op = out + ((size_t)w * NTOK + r) * CDIM + h * HD;
            #pragma unroll
            for (int ni = 0; ni < 4; ni++) {
                float x0 = tfr(oacc[ni][half * 2]);
                float x1 = tfr(oacc[ni][half * 2 + 1]);
                *(float2*)(op + ni * 8 + 2 * tig) = make_float2(x0, x1);
            }
        }
    }
}

// ---------------- launch ----------------
extern "C" void kernel_launch(void* const* d_in, const int* in_sizes, int n_in,
                              void* d_out, int out_size) {
    const float* x     = (const float*)d_in[0];
    const float* n1w   = (const float*)d_in[1];
    const float* n1b   = (const float*)d_in[2];
    const float* qkvw  = (const float*)d_in[3];
    const float* qkvb  = (const float*)d_in[4];
    const float* rpb   = (const float*)d_in[5];
    const float* projw = (const float*)d_in[6];
    const float* projb = (const float*)d_in[7];
    const float* n2w   = (const float*)d_in[8];
    const float* n2b   = (const float*)d_in[9];
    const float* fc1w  = (const float*)d_in[10];
    const float* fc1b  = (const float*)d_in[11];
    const float* fc2w  = (const float*)d_in[12];
    const float* fc2b  = (const float*)d_in[13];
    float* out = (float*)d_out;

    float *p_xw, *p_qkv, *p_att, *p_xn2, *p_hid, *p_wr;
    cudaGetSymbolAddress((void**)&p_xw,  g_xw);
    cudaGetSymbolAddress((void**)&p_qkv, g_qkv);
    cudaGetSymbolAddress((void**)&p_att, g_att);
    cudaGetSymbolAddress((void**)&p_xn2, g_xn2);
    cudaGetSymbolAddress((void**)&p_hid, g_hid);
    cudaGetSymbolAddress((void**)&p_wr,  g_wr);

    cudaFuncSetAttribute(k_mma<0>, cudaFuncAttributeMaxDynamicSharedMemorySize, DSMEM_BYTES);
    cudaFuncSetAttribute(k_mma<1>, cudaFuncAttributeMaxDynamicSharedMemorySize, DSMEM_BYTES);
    cudaFuncSetAttribute(k_mma<2>, cudaFuncAttributeMaxDynamicSharedMemorySize, DSMEM_BYTES);
    cudaFuncSetAttribute(k_mma<3>, cudaFuncAttributeMaxDynamicSharedMemorySize, DSMEM_BYTES);

    // 0) weight tf32 rounding (single launch)
    k_round4<<<(1769472 + 255) / 256, 256>>>(qkvw, projw, fc1w, fc2w, p_wr);
    // 1) LN1 + shift + partition
    k_ln<1><<<NROWS / 4, 128>>>(x, n1w, n1b, p_xw);
    // 2) qkv
    k_mma<0><<<dim3(C3 / 128, NROWS / 128), 256, DSMEM_BYTES>>>(
        p_xw, p_wr + WR_QKV, qkvb, p_qkv, CDIM, C3, nullptr);
    // 3) attention (tensor-core)
    k_attn<<<dim3(NROWS / NTOK, HEADS), 128>>>(p_qkv, rpb, p_att);
    // 4) proj + reverse/unshift + residual -> out holds x2
    k_mma<2><<<dim3(CDIM / 128, NROWS / 128), 256, DSMEM_BYTES>>>(
        p_att, p_wr + WR_PROJ, projb, out, CDIM, CDIM, x);
    // 5) LN2
    k_ln<0><<<NROWS / 4, 128>>>(out, n2w, n2b, p_xn2);
    // 6) fc1 + gelu
    k_mma<1><<<dim3(HIDD / 128, NROWS / 128), 256, DSMEM_BYTES>>>(
        p_xn2, p_wr + WR_FC1, fc1b, p_hid, CDIM, HIDD, nullptr);
    // 7) fc2 + residual
    k_mma<3><<<dim3(CDIM / 128, NROWS / 128), 256, DSMEM_BYTES>>>(
        p_hid, p_wr + WR_FC2, fc2b, out, HIDD, CDIM, out);
}

// round 12
// speedup vs baseline: 3.7935x; 1.0065x over previous
#include <cuda_runtime.h>
#include <math.h>
#include <stdint.h>

// ---------------- problem constants ----------------
#define BATCH 32
#define HIMG  56
#define CDIM  384
#define NTOK  49
#define NWIN  64
#define NROWS 100352
#define C3    1152
#define HIDD  1536
#define HEADS 12
#define HD    32
#define SHIFT 3

// ---------------- scratch ----------------
// activations in k-permuted layout (perm within groups of 8: p(k)=2*(k%4)+(k/4))
__device__ float g_xw [(size_t)NROWS * CDIM];
__device__ float g_qkv[(size_t)NROWS * C3];    // natural (attention input)
__device__ float g_att[(size_t)NROWS * CDIM];  // permuted
__device__ float g_xn2[(size_t)NROWS * CDIM];  // permuted
__device__ float g_hid[(size_t)NROWS * HIDD];  // permuted
__device__ float g_wt [1769472];               // weights [n][k], k-permuted, tf32

#define WT_QKV 0
#define WT_PROJ 442368
#define WT_FC1 589824
#define WT_FC2 1179648

// ---------------- helpers ----------------
__device__ __forceinline__ unsigned f2tf(float f) {
    unsigned u; asm("cvt.rna.tf32.f32 %0, %1;" : "=r"(u) : "f"(f)); return u;
}
__device__ __forceinline__ float tfr(float f) { return __uint_as_float(f2tf(f)); }

__device__ __forceinline__ uint32_t s2u(const void* p) {
    uint32_t a;
    asm("{ .reg .u64 t; cvta.to.shared.u64 t, %1; cvt.u32.u64 %0, t; }" : "=r"(a) : "l"(p));
    return a;
}
__device__ __forceinline__ void cp16(uint32_t dst, const void* src) {
    asm volatile("cp.async.cg.shared.global [%0], [%1], 16;" :: "r"(dst), "l"(src));
}
__device__ __forceinline__ void mma_tf32(float c[4], const unsigned a[4], const unsigned b[2]) {
    asm volatile("mma.sync.aligned.m16n8k8.row.col.f32.tf32.tf32.f32 "
                 "{%0,%1,%2,%3}, {%4,%5,%6,%7}, {%8,%9}, {%0,%1,%2,%3};"
                 : "+f"(c[0]), "+f"(c[1]), "+f"(c[2]), "+f"(c[3])
                 : "r"(a[0]), "r"(a[1]), "r"(a[2]), "r"(a[3]),
                   "r"(b[0]), "r"(b[1]));
}

// ---------------- weight prep: W[K][N] -> WT[n][perm(k)], tf32-rounded -------
__global__ __launch_bounds__(256) void k_wprep(const float* __restrict__ src,
                                               float* __restrict__ dst, int K, int N) {
    __shared__ float t[32][33];
    int tx = threadIdx.x & 31, ty = threadIdx.x >> 5;
    int n0 = blockIdx.x * 32, k0 = blockIdx.y * 32;
    #pragma unroll
    for (int j = 0; j < 32; j += 8)
        t[ty + j][tx] = src[(size_t)(k0 + ty + j) * N + n0 + tx];
    __syncthreads();
    int kp = (tx & ~7) | (2 * (tx & 3) + ((tx >> 2) & 1));
    #pragma unroll
    for (int j = 0; j < 32; j += 8)
        dst[(size_t)(n0 + ty + j) * K + k0 + kp] = tfr(t[tx][ty + j]);
}

// ---------------- warp-per-row LN (+optional gather), permuted-k output ------
template<int GATHER>
__global__ __launch_bounds__(128) void k_ln(const float* __restrict__ x,
                                            const float* __restrict__ w,
                                            const float* __restrict__ b,
                                            float* __restrict__ dst_all) {
    int warp = threadIdx.x >> 5, lane = threadIdx.x & 31;
    int m = blockIdx.x * 4 + warp;
    const float* src;
    if (GATHER) {
        int win = m / NTOK, n = m % NTOK;
        int bb = win >> 6, wi = win & 63;
        int wr = wi >> 3, wc = wi & 7;
        int rs = wr * 7 + n / 7, cs = wc * 7 + n % 7;
        int r = (rs + SHIFT) % HIMG, c = (cs + SHIFT) % HIMG;
        src = x + ((size_t)bb * (HIMG * HIMG) + r * HIMG + c) * CDIM;
    } else {
        src = x + (size_t)m * CDIM;
    }
    float4 v[3];
    #pragma unroll
    for (int i = 0; i < 3; i++) v[i] = *(const float4*)(src + i * 128 + lane * 4);
    float s = 0.f, s2 = 0.f;
    #pragma unroll
    for (int i = 0; i < 3; i++) {
        s  += v[i].x + v[i].y + v[i].z + v[i].w;
        s2 += v[i].x * v[i].x + v[i].y * v[i].y + v[i].z * v[i].z + v[i].w * v[i].w;
    }
    #pragma unroll
    for (int o = 16; o > 0; o >>= 1) {
        s  += __shfl_xor_sync(0xffffffffu, s, o);
        s2 += __shfl_xor_sync(0xffffffffu, s2, o);
    }
    float mean = s * (1.f / CDIM);
    float rstd = rsqrtf(s2 * (1.f / CDIM) - mean * mean + 1e-5f);
    float* dst = dst_all + (size_t)m * CDIM;
    #pragma unroll
    for (int i = 0; i < 3; i++) {
        float4 wv = *(const float4*)(w + i * 128 + lane * 4);
        float4 bv = *(const float4*)(b + i * 128 + lane * 4);
        int c0 = i * 128 + lane * 4;
        int g = c0 & ~7, hh = (c0 >> 2) & 1;   // 4 consecutive cols -> p = 2j + hh
        dst[g + hh]     = tfr((v[i].x - mean) * rstd * wv.x + bv.x);
        dst[g + hh + 2] = tfr((v[i].y - mean) * rstd * wv.y + bv.y);
        dst[g + hh + 4] = tfr((v[i].z - mean) * rstd * wv.z + bv.z);
        dst[g + hh + 6] = tfr((v[i].w - mean) * rstd * wv.w + bv.w);
    }
}

// ---------------- TF32 GEMM: 128x128, warp 64x32, paired LDS.64, 2 CTA/SM ----
// A[M][K] permuted-k, BT[N][K] permuted-k. C = A @ BT^T (+epilogue)
// EPI: 0=bias(natural), 1=bias+gelu(permuted-k out), 2=bias+reverse+res, 3=bias+res
#define ASTR 24
#define A_ST (128 * ASTR)
#define B_ST (128 * ASTR)
#define NSTG 4
#define DSMEM_BYTES ((NSTG * A_ST + NSTG * B_ST) * 4)

template<int EPI>
__global__ __launch_bounds__(256, 2) void k_mma(const float* __restrict__ A,
                                                const float* __restrict__ BT,
                                                const float* __restrict__ bias,
                                                float* __restrict__ Cout,
                                                int K, int N,
                                                const float* __restrict__ res) {
    extern __shared__ float smem[];
    float* sA = smem;                    // [NSTG][128][ASTR]
    float* sB = smem + NSTG * A_ST;      // [NSTG][128][ASTR]
    uint32_t uA = s2u(sA), uB = s2u(sB);

    int tid = threadIdx.x, wid = tid >> 5, lane = tid & 31;
    int gid = lane >> 2, tig = lane & 3;
    int mW = (wid >> 2) * 64;
    int nW = (wid & 3) * 32;

    size_t rowBase = (size_t)blockIdx.y * 128;
    int colB = blockIdx.x * 128;
    const float* Ab = A + rowBase * K;
    const float* Bb = BT + (size_t)colB * K;

    float acc[4][4][4];
    #pragma unroll
    for (int mi = 0; mi < 4; mi++)
        #pragma unroll
        for (int ni = 0; ni < 4; ni++)
            #pragma unroll
            for (int r = 0; r < 4; r++) acc[mi][ni][r] = 0.f;

    int S = K >> 4;

    #define ISSUE(s, buf) { int k0 = (s) << 4; \
        _Pragma("unroll") for (int i = 0; i < 2; i++) { \
            int ch = tid + i * 256; int r = ch >> 2, c = ch & 3; \
            cp16(uA + ((buf) * A_ST + r * ASTR + c * 4) * 4, \
                 Ab + (size_t)r * K + k0 + c * 4); } \
        _Pragma("unroll") for (int i = 0; i < 2; i++) { \
            int ch = tid + i * 256; int r = ch >> 2, c = ch & 3; \
            cp16(uB + ((buf) * B_ST + r * ASTR + c * 4) * 4, \
                 Bb + (size_t)r * K + k0 + c * 4); } \
        asm volatile("cp.async.commit_group;" ::: "memory"); }

    ISSUE(0, 0); ISSUE(1, 1); ISSUE(2, 2);

    for (int s = 0; s < S; s++) {
        int buf = s & (NSTG - 1);
        asm volatile("cp.async.wait_group 2;" ::: "memory");
        __syncthreads();
        if (s + 3 < S) { ISSUE(s + 3, (s + 3) & (NSTG - 1)); }
        else { asm volatile("cp.async.commit_group;" ::: "memory"); }

        const float* A_s = sA + buf * A_ST;
        const float* B_s = sB + buf * B_ST;
        #pragma unroll
        for (int kh = 0; kh < 2; kh++) {
            int ksg = kh * 8 + 2 * tig;
            uint2 bfr[4];
            #pragma unroll
            for (int ni = 0; ni < 4; ni++)
                bfr[ni] = *(const uint2*)&B_s[(nW + ni * 8 + gid) * ASTR + ksg];
            unsigned afr[4][4];
            #pragma unroll
            for (int mi = 0; mi < 4; mi++) {
                uint2 t0 = *(const uint2*)&A_s[(mW + mi * 16 + gid) * ASTR + ksg];
                uint2 t1 = *(const uint2*)&A_s[(mW + mi * 16 + gid + 8) * ASTR + ksg];
                afr[mi][0] = t0.x; afr[mi][1] = t1.x;
                afr[mi][2] = t0.y; afr[mi][3] = t1.y;
            }
            #pragma unroll
            for (int mi = 0; mi < 4; mi++)
                #pragma unroll
                for (int ni = 0; ni < 4; ni++) {
                    unsigned bb[2] = { bfr[ni].x, bfr[ni].y };
                    mma_tf32(acc[mi][ni], afr[mi], bb);
                }
        }
    }
    #undef ISSUE
    asm volatile("cp.async.wait_group 0;" ::: "memory");

    // ---------------- epilogue ----------------
    float2 bb2[4];
    #pragma unroll
    for (int ni = 0; ni < 4; ni++)
        bb2[ni] = *(const float2*)(bias + colB + nW + ni * 8 + 2 * tig);

    int k8a = 2 * tig, k8b = 2 * tig + 1;
    int p0 = 2 * (k8a & 3) + (k8a >> 2);
    int p1 = 2 * (k8b & 3) + (k8b >> 2);

    #pragma unroll
    for (int mi = 0; mi < 4; mi++) {
        #pragma unroll
        for (int half = 0; half < 2; half++) {
            size_t row = rowBase + mW + mi * 16 + gid + half * 8;
            size_t dstRow = 0;
            if (EPI == 2) {
                int win = (int)(row / NTOK), n = (int)(row % NTOK);
                int bbt = win >> 6, wi = win & 63;
                int wr = wi >> 3, wc = wi & 7;
                int rs = wr * 7 + n / 7, cs = wc * 7 + n % 7;
                int rr = (rs + SHIFT) % HIMG, cg = (cs + SHIFT) % HIMG;
                dstRow = ((size_t)bbt * (HIMG * HIMG) + rr * HIMG + cg) * CDIM;
            }
            #pragma unroll
            for (int ni = 0; ni < 4; ni++) {
                int col = colB + nW + ni * 8 + 2 * tig;
                float v0 = acc[mi][ni][half * 2]     + bb2[ni].x;
                float v1 = acc[mi][ni][half * 2 + 1] + bb2[ni].y;
                if (EPI == 0) {
                    *(float2*)(&Cout[row * N + col]) = make_float2(v0, v1);
                } else if (EPI == 1) {
                    v0 = tfr(0.5f * v0 * (1.0f + erff(v0 * 0.70710678118654752f)));
                    v1 = tfr(0.5f * v1 * (1.0f + erff(v1 * 0.70710678118654752f)));
                    int gb = colB + nW + ni * 8;   // group base (mult of 8)
                    Cout[row * N + gb + p0] = v0;
                    Cout[row * N + gb + p1] = v1;
                } else if (EPI == 2) {
                    float2 rv = *(const float2*)(&res[dstRow + col]);
                    *(float2*)(&Cout[dstRow + col]) = make_float2(rv.x + v0, rv.y + v1);
                } else {
                    size_t o = row * N + col;
                    float2 rv = *(const float2*)(&res[o]);
                    *(float2*)(&Cout[o]) = make_float2(rv.x + v0, rv.y + v1);
                }
            }
        }
    }
}

// ---------------- windowed attention via mma.sync (permuted-k output) --------
#define PAD 36
#define PS 57
__global__ __launch_bounds__(128) void k_attn(const float* __restrict__ qkv,
                                              const float* __restrict__ rpb,
                                              float* __restrict__ out) {
    __shared__ __align__(16) float qs[64][PAD];
    __shared__ __align__(16) float ks[56][PAD];
    __shared__ __align__(16) float vv[56][PAD];
    __shared__ float ps[64][PS];
    __shared__ float sbias[169];

    int w = blockIdx.x, h = blockIdx.y, tid = threadIdx.x;
    int wid = tid >> 5, lane = tid & 31;
    int gid = lane >> 2, tig = lane & 3;
    const float scale = 0.17677669529663689f;

    size_t base = (size_t)w * NTOK * C3 + h * HD;
    for (int idx = tid; idx < NTOK * 8; idx += 128) {
        int n = idx >> 3, t4 = (idx & 7) * 4;
        const float* rbq = qkv + base + (size_t)n * C3 + t4;
        float4 a = *(const float4*)rbq;
        a.x *= scale; a.y *= scale; a.z *= scale; a.w *= scale;
        *(float4*)&qs[n][t4] = a;
        *(float4*)&ks[n][t4] = *(const float4*)(rbq + CDIM);
        *(float4*)&vv[n][t4] = *(const float4*)(rbq + 2 * CDIM);
    }
    for (int idx = tid; idx < 15 * 8; idx += 128) {
        int n = 49 + (idx >> 3), t4 = (idx & 7) * 4;
        *(float4*)&qs[n][t4] = make_float4(0.f, 0.f, 0.f, 0.f);
        if (n < 56) {
            *(float4*)&ks[n][t4] = make_float4(0.f, 0.f, 0.f, 0.f);
            *(float4*)&vv[n][t4] = make_float4(0.f, 0.f, 0.f, 0.f);
        }
    }
    for (int i = tid; i < 169; i += 128) sbias[i] = rpb[i * HEADS + h];
    __syncthreads();

    int m0 = wid * 16;
    float acc[7][4];
    #pragma unroll
    for (int ni = 0; ni < 7; ni++)
        #pragma unroll
        for (int r = 0; r < 4; r++) acc[ni][r] = 0.f;

    #pragma unroll
    for (int kk4 = 0; kk4 < 4; kk4++) {
        int k0 = kk4 * 8;
        unsigned a[4];
        a[0] = __float_as_uint(qs[m0 + gid][k0 + tig]);
        a[1] = __float_as_uint(qs[m0 + gid + 8][k0 + tig]);
        a[2] = __float_as_uint(qs[m0 + gid][k0 + tig + 4]);
        a[3] = __float_as_uint(qs[m0 + gid + 8][k0 + tig + 4]);
        #pragma unroll
        for (int ni = 0; ni < 7; ni++) {
            unsigned b[2];
            b[0] = __float_as_uint(ks[ni * 8 + gid][k0 + tig]);
            b[1] = __float_as_uint(ks[ni * 8 + gid][k0 + tig + 4]);
            mma_tf32(acc[ni], a, b);
        }
    }

    int wi = w & 63, wr = wi >> 3, wc = wi & 7;
    int r1 = m0 + gid, r2 = r1 + 8;
    int ri1 = r1 / 7, ci1 = r1 % 7, ri2 = r2 / 7, ci2 = r2 % 7;
    int rs1 = wr * 7 + ri1, cs1 = wc * 7 + ci1;
    int rs2 = wr * 7 + ri2, cs2 = wc * 7 + ci2;
    int lab1 = ((rs1 < HIMG - 7) ? 0 : ((rs1 < HIMG - SHIFT) ? 1 : 2)) * 3
             + ((cs1 < HIMG - 7) ? 0 : ((cs1 < HIMG - SHIFT) ? 1 : 2));
    int lab2 = ((rs2 < HIMG - 7) ? 0 : ((rs2 < HIMG - SHIFT) ? 1 : 2)) * 3
             + ((cs2 < HIMG - 7) ? 0 : ((cs2 < HIMG - SHIFT) ? 1 : 2));

    float v1[14], v2[14];
    float mx1 = -1e30f, mx2 = -1e30f;
    #pragma unroll
    for (int ni = 0; ni < 7; ni++) {
        #pragma unroll
        for (int bb = 0; bb < 2; bb++) {
            int j = ni * 8 + 2 * tig + bb;
            float t1 = -1e30f, t2 = -1e30f;
            if (j < NTOK) {
                int rj = j / 7, cj = j % 7;
                int rsj = wr * 7 + rj, csj = wc * 7 + cj;
                int labj = ((rsj < HIMG - 7) ? 0 : ((rsj < HIMG - SHIFT) ? 1 : 2)) * 3
                         + ((csj < HIMG - 7) ? 0 : ((csj < HIMG - SHIFT) ? 1 : 2));
                if (r1 < NTOK) {
                    t1 = acc[ni][bb] + sbias[(ri1 - rj + 6) * 13 + (ci1 - cj + 6)];
                    if (lab1 != labj) t1 -= 100.0f;
                }
                if (r2 < NTOK) {
                    t2 = acc[ni][2 + bb] + sbias[(ri2 - rj + 6) * 13 + (ci2 - cj + 6)];
                    if (lab2 != labj) t2 -= 100.0f;
                }
            }
            v1[ni * 2 + bb] = t1; v2[ni * 2 + bb] = t2;
            mx1 = fmaxf(mx1, t1); mx2 = fmaxf(mx2, t2);
        }
    }
    #pragma unroll
    for (int o = 1; o < 4; o <<= 1) {
        mx1 = fmaxf(mx1, __shfl_xor_sync(0xffffffffu, mx1, o));
        mx2 = fmaxf(mx2, __shfl_xor_sync(0xffffffffu, mx2, o));
    }
    float s1 = 0.f, s2 = 0.f;
    #pragma unroll
    for (int t = 0; t < 14; t++) {
        v1[t] = __expf(v1[t] - mx1); s1 += v1[t];
        v2[t] = __expf(v2[t] - mx2); s2 += v2[t];
    }
    #pragma unroll
    for (int o = 1; o < 4; o <<= 1) {
        s1 += __shfl_xor_sync(0xffffffffu, s1, o);
        s2 += __shfl_xor_sync(0xffffffffu, s2, o);
    }
    float inv1 = 1.f / s1, inv2 = 1.f / s2;
    #pragma unroll
    for (int ni = 0; ni < 7; ni++) {
        int j = ni * 8 + 2 * tig;
        ps[r1][j]     = v1[ni * 2]     * inv1;
        ps[r1][j + 1] = v1[ni * 2 + 1] * inv1;
        ps[r2][j]     = v2[ni * 2]     * inv2;
        ps[r2][j + 1] = v2[ni * 2 + 1] * inv2;
    }
    __syncwarp();

    float oacc[4][4];
    #pragma unroll
    for (int ni = 0; ni < 4; ni++)
        #pragma unroll
        for (int r = 0; r < 4; r++) oacc[ni][r] = 0.f;

    #pragma unroll
    for (int kk7 = 0; kk7 < 7; kk7++) {
        int k0 = kk7 * 8;
        unsigned a[4];
        a[0] = f2tf(ps[m0 + gid][k0 + tig]);
        a[1] = f2tf(ps[m0 + gid + 8][k0 + tig]);
        a[2] = f2tf(ps[m0 + gid][k0 + tig + 4]);
        a[3] = f2tf(ps[m0 + gid + 8][k0 + tig + 4]);
        #pragma unroll
        for (int ni = 0; ni < 4; ni++) {
            unsigned b[2];
            b[0] = __float_as_uint(vv[k0 + tig][ni * 8 + gid]);
            b[1] = __float_as_uint(vv[k0 + tig + 4][ni * 8 + gid]);
            mma_tf32(oacc[ni], a, b);
        }
    }

    // permuted-k store (att feeds proj's A-side)
    int k8a = 2 * tig, k8b = 2 * tig + 1;
    int p0 = 2 * (k8a & 3) + (k8a >> 2);
    int p1 = 2 * (k8b & 3) + (k8b >> 2);
    #pragma unroll
    for (int half = 0; half < 2; half++) {
        int r = (half == 0) ? r1 : r2;
        if (r < NTOK) {
            float* op = out + ((size_t)w * NTOK + r) * CDIM + h * HD;
            #pragma unroll
            for (int ni = 0; ni < 4; ni++) {
                op[ni * 8 + p0] = tfr(oacc[ni][half * 2]);
                op[ni * 8 + p1] = tfr(oacc[ni][half * 2 + 1]);
            }
        }
    }
}

// ---------------- launch ----------------
extern "C" void kernel_launch(void* const* d_in, const int* in_sizes, int n_in,
                              void* d_out, int out_size) {
    const float* x     = (const float*)d_in[0];
    const float* n1w   = (const float*)d_in[1];
    const float* n1b   = (const float*)d_in[2];
    const float* qkvw  = (const float*)d_in[3];
    const float* qkvb  = (const float*)d_in[4];
    const float* rpb   = (const float*)d_in[5];
    const float* projw = (const float*)d_in[6];
    const float* projb = (const float*)d_in[7];
    const float* n2w   = (const float*)d_in[8];
    const float* n2b   = (const float*)d_in[9];
    const float* fc1w  = (const float*)d_in[10];
    const float* fc1b  = (const float*)d_in[11];
    const float* fc2w  = (const float*)d_in[12];
    const float* fc2b  = (const float*)d_in[13];
    float* out = (float*)d_out;

    float *p_xw, *p_qkv, *p_att, *p_xn2, *p_hid, *p_wt;
    cudaGetSymbolAddress((void**)&p_xw,  g_xw);
    cudaGetSymbolAddress((void**)&p_qkv, g_qkv);
    cudaGetSymbolAddress((void**)&p_att, g_att);
    cudaGetSymbolAddress((void**)&p_xn2, g_xn2);
    cudaGetSymbolAddress((void**)&p_hid, g_hid);
    cudaGetSymbolAddress((void**)&p_wt,  g_wt);

    cudaFuncSetAttribute(k_mma<0>, cudaFuncAttributeMaxDynamicSharedMemorySize, DSMEM_BYTES);
    cudaFuncSetAttribute(k_mma<1>, cudaFuncAttributeMaxDynamicSharedMemorySize, DSMEM_BYTES);
    cudaFuncSetAttribute(k_mma<2>, cudaFuncAttributeMaxDynamicSharedMemorySize, DSMEM_BYTES);
    cudaFuncSetAttribute(k_mma<3>, cudaFuncAttributeMaxDynamicSharedMemorySize, DSMEM_BYTES);

    // 0) weight prep: transpose + k-permute + tf32 round
    k_wprep<<<dim3(C3 / 32, CDIM / 32), 256>>>(qkvw, p_wt + WT_QKV, CDIM, C3);
    k_wprep<<<dim3(CDIM / 32, CDIM / 32), 256>>>(projw, p_wt + WT_PROJ, CDIM, CDIM);
    k_wprep<<<dim3(HIDD / 32, CDIM / 32), 256>>>(fc1w, p_wt + WT_FC1, CDIM, HIDD);
    k_wprep<<<dim3(CDIM / 32, HIDD / 32), 256>>>(fc2w, p_wt + WT_FC2, HIDD, CDIM);

    // 1) LN1 + shift + partition (permuted-k out)
    k_ln<1><<<NROWS / 4, 128>>>(x, n1w, n1b, p_xw);
    // 2) qkv (natural out)
    k_mma<0><<<dim3(C3 / 128, NROWS / 128), 256, DSMEM_BYTES>>>(
        p_xw, p_wt + WT_QKV, qkvb, p_qkv, CDIM, C3, nullptr);
    // 3) attention (tensor-core, permuted-k out)
    k_attn<<<dim3(NROWS / NTOK, HEADS), 128>>>(p_qkv, rpb, p_att);
    // 4) proj + reverse/unshift + residual -> out holds x2 (natural)
    k_mma<2><<<dim3(CDIM / 128, NROWS / 128), 256, DSMEM_BYTES>>>(
        p_att, p_wt + WT_PROJ, projb, out, CDIM, CDIM, x);
    // 5) LN2 (permuted-k out)
    k_ln<0><<<NROWS / 4, 128>>>(out, n2w, n2b, p_xn2);
    // 6) fc1 + gelu (permuted-k out)
    k_mma<1><<<dim3(HIDD / 128, NROWS / 128), 256, DSMEM_BYTES>>>(
        p_xn2, p_wt + WT_FC1, fc1b, p_hid, CDIM, HIDD, nullptr);
    // 7) fc2 + residual (natural, final)
    k_mma<3><<<dim3(CDIM / 128, NROWS / 128), 256, DSMEM_BYTES>>>(
        p_hid, p_wt + WT_FC2, fc2b, out, HIDD, CDIM, out);
}

// round 13
// speedup vs baseline: 4.9650x; 1.3088x over previous
#include <cuda_runtime.h>
#include <cuda_fp16.h>
#include <math.h>
#include <stdint.h>

// ---------------- problem constants ----------------
#define BATCH 32
#define HIMG  56
#define CDIM  384
#define NTOK  49
#define NWIN  64
#define NROWS 100352
#define C3    1152
#define HIDD  1536
#define HEADS 12
#define HD    32
#define SHIFT 3

// ---------------- scratch (half activations for GEMM inputs) ----------------
__device__ __half g_xw [(size_t)NROWS * CDIM];
__device__ __half g_qkv[(size_t)NROWS * C3];
__device__ __half g_att[(size_t)NROWS * CDIM];
__device__ __half g_xn2[(size_t)NROWS * CDIM];
__device__ __half g_hid[(size_t)NROWS * HIDD];
__device__ __half g_wt [1769472];            // weights [n][k], fp16

#define WT_QKV 0
#define WT_PROJ 442368
#define WT_FC1 589824
#define WT_FC2 1179648

// ---------------- helpers ----------------
__device__ __forceinline__ unsigned f2tf(float f) {
    unsigned u; asm("cvt.rna.tf32.f32 %0, %1;" : "=r"(u) : "f"(f)); return u;
}
__device__ __forceinline__ uint32_t s2u(const void* p) {
    uint32_t a;
    asm("{ .reg .u64 t; cvta.to.shared.u64 t, %1; cvt.u32.u64 %0, t; }" : "=r"(a) : "l"(p));
    return a;
}
__device__ __forceinline__ void cp16(uint32_t dst, const void* src) {
    asm volatile("cp.async.cg.shared.global [%0], [%1], 16;" :: "r"(dst), "l"(src));
}
__device__ __forceinline__ void mma_f16(float c[4], const unsigned a[4], const unsigned b[2]) {
    asm volatile("mma.sync.aligned.m16n8k16.row.col.f32.f16.f16.f32 "
                 "{%0,%1,%2,%3}, {%4,%5,%6,%7}, {%8,%9}, {%0,%1,%2,%3};"
                 : "+f"(c[0]), "+f"(c[1]), "+f"(c[2]), "+f"(c[3])
                 : "r"(a[0]), "r"(a[1]), "r"(a[2]), "r"(a[3]),
                   "r"(b[0]), "r"(b[1]));
}
__device__ __forceinline__ void mma_tf32(float c[4], const unsigned a[4], const unsigned b[2]) {
    asm volatile("mma.sync.aligned.m16n8k8.row.col.f32.tf32.tf32.f32 "
                 "{%0,%1,%2,%3}, {%4,%5,%6,%7}, {%8,%9}, {%0,%1,%2,%3};"
                 : "+f"(c[0]), "+f"(c[1]), "+f"(c[2]), "+f"(c[3])
                 : "r"(a[0]), "r"(a[1]), "r"(a[2]), "r"(a[3]),
                   "r"(b[0]), "r"(b[1]));
}

// ---------------- weight prep: W[K][N] fp32 -> WT[n][k] fp16 ----------------
__global__ __launch_bounds__(256) void k_wprep(const float* __restrict__ src,
                                               __half* __restrict__ dst, int K, int N) {
    __shared__ float t[32][33];
    int tx = threadIdx.x & 31, ty = threadIdx.x >> 5;
    int n0 = blockIdx.x * 32, k0 = blockIdx.y * 32;
    #pragma unroll
    for (int j = 0; j < 32; j += 8)
        t[ty + j][tx] = src[(size_t)(k0 + ty + j) * N + n0 + tx];
    __syncthreads();
    #pragma unroll
    for (int j = 0; j < 32; j += 8)
        dst[(size_t)(n0 + ty + j) * K + k0 + tx] = __float2half_rn(t[tx][ty + j]);
}

// ---------------- warp-per-row LN (+optional gather), half output ----------
template<int GATHER>
__global__ __launch_bounds__(128) void k_ln(const float* __restrict__ x,
                                            const float* __restrict__ w,
                                            const float* __restrict__ b,
                                            __half* __restrict__ dst_all) {
    int warp = threadIdx.x >> 5, lane = threadIdx.x & 31;
    int m = blockIdx.x * 4 + warp;
    const float* src;
    if (GATHER) {
        int win = m / NTOK, n = m % NTOK;
        int bb = win >> 6, wi = win & 63;
        int wr = wi >> 3, wc = wi & 7;
        int rs = wr * 7 + n / 7, cs = wc * 7 + n % 7;
        int r = (rs + SHIFT) % HIMG, c = (cs + SHIFT) % HIMG;
        src = x + ((size_t)bb * (HIMG * HIMG) + r * HIMG + c) * CDIM;
    } else {
        src = x + (size_t)m * CDIM;
    }
    float4 v[3];
    #pragma unroll
    for (int i = 0; i < 3; i++) v[i] = *(const float4*)(src + i * 128 + lane * 4);
    float s = 0.f, s2 = 0.f;
    #pragma unroll
    for (int i = 0; i < 3; i++) {
        s  += v[i].x + v[i].y + v[i].z + v[i].w;
        s2 += v[i].x * v[i].x + v[i].y * v[i].y + v[i].z * v[i].z + v[i].w * v[i].w;
    }
    #pragma unroll
    for (int o = 16; o > 0; o >>= 1) {
        s  += __shfl_xor_sync(0xffffffffu, s, o);
        s2 += __shfl_xor_sync(0xffffffffu, s2, o);
    }
    float mean = s * (1.f / CDIM);
    float rstd = rsqrtf(s2 * (1.f / CDIM) - mean * mean + 1e-5f);
    __half* dst = dst_all + (size_t)m * CDIM;
    #pragma unroll
    for (int i = 0; i < 3; i++) {
        float4 wv = *(const float4*)(w + i * 128 + lane * 4);
        float4 bv = *(const float4*)(b + i * 128 + lane * 4);
        int c0 = i * 128 + lane * 4;
        __half2 h0 = __floats2half2_rn((v[i].x - mean) * rstd * wv.x + bv.x,
                                       (v[i].y - mean) * rstd * wv.y + bv.y);
        __half2 h1 = __floats2half2_rn((v[i].z - mean) * rstd * wv.z + bv.z,
                                       (v[i].w - mean) * rstd * wv.w + bv.w);
        *(__half2*)(dst + c0)     = h0;
        *(__half2*)(dst + c0 + 2) = h1;
    }
}

// ---------------- FP16 mma.sync GEMM: 128x128, warp 64x32, 4-stage ----------
// A[M][K] half, BT[N][K] half. C = A @ BT^T + bias (+epilogue)
// EPI: 0=bias(half out), 1=bias+gelu(half out), 2=bias+reverse+res(f32 out),
//      3=bias+res(f32 out)
#define HSTR 40                         // halves per smem row (80B, 16B-aligned)
#define A_ST (128 * HSTR)               // halves
#define NSTG 4
#define DSMEM_BYTES (NSTG * 2 * A_ST * 2)

template<int EPI>
__global__ __launch_bounds__(256, 2) void k_mma(const __half* __restrict__ A,
                                                const __half* __restrict__ BT,
                                                const float* __restrict__ bias,
                                                void* __restrict__ CoutV,
                                                int K, int N,
                                                const float* __restrict__ res) {
    extern __shared__ __half smemh[];
    __half* sA = smemh;                   // [NSTG][128][HSTR]
    __half* sB = smemh + NSTG * A_ST;
    uint32_t uA = s2u(sA), uB = s2u(sB);

    int tid = threadIdx.x, wid = tid >> 5, lane = tid & 31;
    int gid = lane >> 2, tig = lane & 3;
    int mW = (wid >> 2) * 64;
    int nW = (wid & 3) * 32;

    size_t rowBase = (size_t)blockIdx.y * 128;
    int colB = blockIdx.x * 128;
    const __half* Ab = A + rowBase * K;
    const __half* Bb = BT + (size_t)colB * K;

    float acc[4][4][4];
    #pragma unroll
    for (int mi = 0; mi < 4; mi++)
        #pragma unroll
        for (int ni = 0; ni < 4; ni++)
            #pragma unroll
            for (int r = 0; r < 4; r++) acc[mi][ni][r] = 0.f;

    int S = K >> 4;   // 16 k per stage

    // per stage: A tile 128x16 halves (32B/row = 2 chunks), 256 chunks, 1/thread
    #define ISSUE(s, buf) { int k0 = (s) << 4; \
        { int r = tid >> 1, c = tid & 1; \
          cp16(uA + (buf) * A_ST * 2 + r * (HSTR * 2) + c * 16, \
               Ab + (size_t)r * K + k0 + c * 8); \
          cp16(uB + (buf) * A_ST * 2 + r * (HSTR * 2) + c * 16, \
               Bb + (size_t)r * K + k0 + c * 8); } \
        asm volatile("cp.async.commit_group;" ::: "memory"); }

    ISSUE(0, 0); ISSUE(1, 1); ISSUE(2, 2);

    for (int s = 0; s < S; s++) {
        int buf = s & (NSTG - 1);
        asm volatile("cp.async.wait_group 2;" ::: "memory");
        __syncthreads();
        if (s + 3 < S) { ISSUE(s + 3, (s + 3) & (NSTG - 1)); }
        else { asm volatile("cp.async.commit_group;" ::: "memory"); }

        const uint32_t* A32 = (const uint32_t*)(sA + buf * A_ST);
        const uint32_t* B32 = (const uint32_t*)(sB + buf * A_ST);
        unsigned bfr[4][2], afr[4][4];
        #pragma unroll
        for (int ni = 0; ni < 4; ni++) {
            int r = nW + ni * 8 + gid;
            bfr[ni][0] = B32[r * (HSTR / 2) + tig];
            bfr[ni][1] = B32[r * (HSTR / 2) + tig + 4];
        }
        #pragma unroll
        for (int mi = 0; mi < 4; mi++) {
            int r = mW + mi * 16 + gid;
            afr[mi][0] = A32[r * (HSTR / 2) + tig];
            afr[mi][1] = A32[(r + 8) * (HSTR / 2) + tig];
            afr[mi][2] = A32[r * (HSTR / 2) + tig + 4];
            afr[mi][3] = A32[(r + 8) * (HSTR / 2) + tig + 4];
        }
        #pragma unroll
        for (int mi = 0; mi < 4; mi++)
            #pragma unroll
            for (int ni = 0; ni < 4; ni++)
                mma_f16(acc[mi][ni], afr[mi], bfr[ni]);
    }
    #undef ISSUE
    asm volatile("cp.async.wait_group 0;" ::: "memory");

    // ---------------- epilogue ----------------
    float2 bb2[4];
    #pragma unroll
    for (int ni = 0; ni < 4; ni++)
        bb2[ni] = *(const float2*)(bias + colB + nW + ni * 8 + 2 * tig);

    #pragma unroll
    for (int mi = 0; mi < 4; mi++) {
        #pragma unroll
        for (int half_ = 0; half_ < 2; half_++) {
            size_t row = rowBase + mW + mi * 16 + gid + half_ * 8;
            size_t dstRow = 0;
            if (EPI == 2) {
                int win = (int)(row / NTOK), n = (int)(row % NTOK);
                int bbt = win >> 6, wi = win & 63;
                int wr = wi >> 3, wc = wi & 7;
                int rs = wr * 7 + n / 7, cs = wc * 7 + n % 7;
                int rr = (rs + SHIFT) % HIMG, cg = (cs + SHIFT) % HIMG;
                dstRow = ((size_t)bbt * (HIMG * HIMG) + rr * HIMG + cg) * CDIM;
            }
            #pragma unroll
            for (int ni = 0; ni < 4; ni++) {
                int col = colB + nW + ni * 8 + 2 * tig;
                float v0 = acc[mi][ni][half_ * 2]     + bb2[ni].x;
                float v1 = acc[mi][ni][half_ * 2 + 1] + bb2[ni].y;
                if (EPI == 0) {
                    __half* hC = (__half*)CoutV;
                    *(__half2*)(&hC[row * N + col]) = __floats2half2_rn(v0, v1);
                } else if (EPI == 1) {
                    v0 = 0.5f * v0 * (1.0f + erff(v0 * 0.70710678118654752f));
                    v1 = 0.5f * v1 * (1.0f + erff(v1 * 0.70710678118654752f));
                    __half* hC = (__half*)CoutV;
                    *(__half2*)(&hC[row * N + col]) = __floats2half2_rn(v0, v1);
                } else if (EPI == 2) {
                    float* fC = (float*)CoutV;
                    float2 rv = *(const float2*)(&res[dstRow + col]);
                    *(float2*)(&fC[dstRow + col]) = make_float2(rv.x + v0, rv.y + v1);
                } else {
                    float* fC = (float*)CoutV;
                    size_t o = row * N + col;
                    float2 rv = *(const float2*)(&res[o]);
                    *(float2*)(&fC[o]) = make_float2(rv.x + v0, rv.y + v1);
                }
            }
        }
    }
}

// ---------------- windowed attention (tf32 mma, half I/O) -------------------
#define PAD 36
#define PS 57
__global__ __launch_bounds__(128) void k_attn(const __half* __restrict__ qkv,
                                              const float* __restrict__ rpb,
                                              __half* __restrict__ out) {
    __shared__ __align__(16) float qs[64][PAD];
    __shared__ __align__(16) float ks[56][PAD];
    __shared__ __align__(16) float vv[56][PAD];
    __shared__ float ps[64][PS];
    __shared__ float sbias[169];

    int w = blockIdx.x, h = blockIdx.y, tid = threadIdx.x;
    int wid = tid >> 5, lane = tid & 31;
    int gid = lane >> 2, tig = lane & 3;
    const float scale = 0.17677669529663689f;

    size_t base = (size_t)w * NTOK * C3 + h * HD;
    for (int idx = tid; idx < NTOK * 8; idx += 128) {
        int n = idx >> 3, t4 = (idx & 7) * 4;
        const __half* rbq = qkv + base + (size_t)n * C3 + t4;
        float2 q0 = __half22float2(*(const __half2*)rbq);
        float2 q1 = __half22float2(*(const __half2*)(rbq + 2));
        qs[n][t4]     = q0.x * scale; qs[n][t4 + 1] = q0.y * scale;
        qs[n][t4 + 2] = q1.x * scale; qs[n][t4 + 3] = q1.y * scale;
        float2 k0 = __half22float2(*(const __half2*)(rbq + CDIM));
        float2 k1 = __half22float2(*(const __half2*)(rbq + CDIM + 2));
        ks[n][t4] = k0.x; ks[n][t4 + 1] = k0.y; ks[n][t4 + 2] = k1.x; ks[n][t4 + 3] = k1.y;
        float2 v0 = __half22float2(*(const __half2*)(rbq + 2 * CDIM));
        float2 v1 = __half22float2(*(const __half2*)(rbq + 2 * CDIM + 2));
        vv[n][t4] = v0.x; vv[n][t4 + 1] = v0.y; vv[n][t4 + 2] = v1.x; vv[n][t4 + 3] = v1.y;
    }
    for (int idx = tid; idx < 15 * 8; idx += 128) {
        int n = 49 + (idx >> 3), t4 = (idx & 7) * 4;
        *(float4*)&qs[n][t4] = make_float4(0.f, 0.f, 0.f, 0.f);
        if (n < 56) {
            *(float4*)&ks[n][t4] = make_float4(0.f, 0.f, 0.f, 0.f);
            *(float4*)&vv[n][t4] = make_float4(0.f, 0.f, 0.f, 0.f);
        }
    }
    for (int i = tid; i < 169; i += 128) sbias[i] = rpb[i * HEADS + h];
    __syncthreads();

    int m0 = wid * 16;
    float acc[7][4];
    #pragma unroll
    for (int ni = 0; ni < 7; ni++)
        #pragma unroll
        for (int r = 0; r < 4; r++) acc[ni][r] = 0.f;

    #pragma unroll
    for (int kk4 = 0; kk4 < 4; kk4++) {
        int k0 = kk4 * 8;
        unsigned a[4];
        a[0] = __float_as_uint(qs[m0 + gid][k0 + tig]);
        a[1] = __float_as_uint(qs[m0 + gid + 8][k0 + tig]);
        a[2] = __float_as_uint(qs[m0 + gid][k0 + tig + 4]);
        a[3] = __float_as_uint(qs[m0 + gid + 8][k0 + tig + 4]);
        #pragma unroll
        for (int ni = 0; ni < 7; ni++) {
            unsigned b[2];
            b[0] = __float_as_uint(ks[ni * 8 + gid][k0 + tig]);
            b[1] = __float_as_uint(ks[ni * 8 + gid][k0 + tig + 4]);
            mma_tf32(acc[ni], a, b);
        }
    }

    int wi = w & 63, wr = wi >> 3, wc = wi & 7;
    int r1 = m0 + gid, r2 = r1 + 8;
    int ri1 = r1 / 7, ci1 = r1 % 7, ri2 = r2 / 7, ci2 = r2 % 7;
    int rs1 = wr * 7 + ri1, cs1 = wc * 7 + ci1;
    int rs2 = wr * 7 + ri2, cs2 = wc * 7 + ci2;
    int lab1 = ((rs1 < HIMG - 7) ? 0 : ((rs1 < HIMG - SHIFT) ? 1 : 2)) * 3
             + ((cs1 < HIMG - 7) ? 0 : ((cs1 < HIMG - SHIFT) ? 1 : 2));
    int lab2 = ((rs2 < HIMG - 7) ? 0 : ((rs2 < HIMG - SHIFT) ? 1 : 2)) * 3
             + ((cs2 < HIMG - 7) ? 0 : ((cs2 < HIMG - SHIFT) ? 1 : 2));

    float v1[14], v2[14];
    float mx1 = -1e30f, mx2 = -1e30f;
    #pragma unroll
    for (int ni = 0; ni < 7; ni++) {
        #pragma unroll
        for (int bb = 0; bb < 2; bb++) {
            int j = ni * 8 + 2 * tig + bb;
            float t1 = -1e30f, t2 = -1e30f;
            if (j < NTOK) {
                int rj = j / 7, cj = j % 7;
                int rsj = wr * 7 + rj, csj = wc * 7 + cj;
                int labj = ((rsj < HIMG - 7) ? 0 : ((rsj < HIMG - SHIFT) ? 1 : 2)) * 3
                         + ((csj < HIMG - 7) ? 0 : ((csj < HIMG - SHIFT) ? 1 : 2));
                if (r1 < NTOK) {
                    t1 = acc[ni][bb] + sbias[(ri1 - rj + 6) * 13 + (ci1 - cj + 6)];
                    if (lab1 != labj) t1 -= 100.0f;
                }
                if (r2 < NTOK) {
                    t2 = acc[ni][2 + bb] + sbias[(ri2 - rj + 6) * 13 + (ci2 - cj + 6)];
                    if (lab2 != labj) t2 -= 100.0f;
                }
            }
            v1[ni * 2 + bb] = t1; v2[ni * 2 + bb] = t2;
            mx1 = fmaxf(mx1, t1); mx2 = fmaxf(mx2, t2);
        }
    }
    #pragma unroll
    for (int o = 1; o < 4; o <<= 1) {
        mx1 = fmaxf(mx1, __shfl_xor_sync(0xffffffffu, mx1, o));
        mx2 = fmaxf(mx2, __shfl_xor_sync(0xffffffffu, mx2, o));
    }
    float s1 = 0.f, s2 = 0.f;
    #pragma unroll
    for (int t = 0; t < 14; t++) {
        v1[t] = __expf(v1[t] - mx1); s1 += v1[t];
        v2[t] = __expf(v2[t] - mx2); s2 += v2[t];
    }
    #pragma unroll
    for (int o = 1; o < 4; o <<= 1) {
        s1 += __shfl_xor_sync(0xffffffffu, s1, o);
        s2 += __shfl_xor_sync(0xffffffffu, s2, o);
    }
    float inv1 = 1.f / s1, inv2 = 1.f / s2;
    #pragma unroll
    for (int ni = 0; ni < 7; ni++) {
        int j = ni * 8 + 2 * tig;
        ps[r1][j]     = v1[ni * 2]     * inv1;
        ps[r1][j + 1] = v1[ni * 2 + 1] * inv1;
        ps[r2][j]     = v2[ni * 2]     * inv2;
        ps[r2][j + 1] = v2[ni * 2 + 1] * inv2;
    }
    __syncwarp();

    float oacc[4][4];
    #pragma unroll
    for (int ni = 0; ni < 4; ni++)
        #pragma unroll
        for (int r = 0; r < 4; r++) oacc[ni][r] = 0.f;

    #pragma unroll
    for (int kk7 = 0; kk7 < 7; kk7++) {
        int k0 = kk7 * 8;
        unsigned a[4];
        a[0] = f2tf(ps[m0 + gid][k0 + tig]);
        a[1] = f2tf(ps[m0 + gid + 8][k0 + tig]);
        a[2] = f2tf(ps[m0 + gid][k0 + tig + 4]);
        a[3] = f2tf(ps[m0 + gid + 8][k0 + tig + 4]);
        #pragma unroll
        for (int ni = 0; ni < 4; ni++) {
            unsigned b[2];
            b[0] = __float_as_uint(vv[k0 + tig][ni * 8 + gid]);
            b[1] = __float_as_uint(vv[k0 + tig + 4][ni * 8 + gid]);
            mma_tf32(oacc[ni], a, b);
        }
    }

    #pragma unroll
    for (int half_ = 0; half_ < 2; half_++) {
        int r = (half_ == 0) ? r1 : r2;
        if (r < NTOK) {
            __half* op = out + ((size_t)w * NTOK + r) * CDIM + h * HD;
            #pragma unroll
            for (int ni = 0; ni < 4; ni++) {
                *(__half2*)(op + ni * 8 + 2 * tig) =
                    __floats2half2_rn(oacc[ni][half_ * 2], oacc[ni][half_ * 2 + 1]);
            }
        }
    }
}

// ---------------- launch ----------------
extern "C" void kernel_launch(void* const* d_in, const int* in_sizes, int n_in,
                              void* d_out, int out_size) {
    const float* x     = (const float*)d_in[0];
    const float* n1w   = (const float*)d_in[1];
    const float* n1b   = (const float*)d_in[2];
    const float* qkvw  = (const float*)d_in[3];
    const float* qkvb  = (const float*)d_in[4];
    const float* rpb   = (const float*)d_in[5];
    const float* projw = (const float*)d_in[6];
    const float* projb = (const float*)d_in[7];
    const float* n2w   = (const float*)d_in[8];
    const float* n2b   = (const float*)d_in[9];
    const float* fc1w  = (const float*)d_in[10];
    const float* fc1b  = (const float*)d_in[11];
    const float* fc2w  = (const float*)d_in[12];
    const float* fc2b  = (const float*)d_in[13];
    float* out = (float*)d_out;

    __half *p_xw, *p_qkv, *p_att, *p_xn2, *p_hid, *p_wt;
    cudaGetSymbolAddress((void**)&p_xw,  g_xw);
    cudaGetSymbolAddress((void**)&p_qkv, g_qkv);
    cudaGetSymbolAddress((void**)&p_att, g_att);
    cudaGetSymbolAddress((void**)&p_xn2, g_xn2);
    cudaGetSymbolAddress((void**)&p_hid, g_hid);
    cudaGetSymbolAddress((void**)&p_wt,  g_wt);

    cudaFuncSetAttribute(k_mma<0>, cudaFuncAttributeMaxDynamicSharedMemorySize, DSMEM_BYTES);
    cudaFuncSetAttribute(k_mma<1>, cudaFuncAttributeMaxDynamicSharedMemorySize, DSMEM_BYTES);
    cudaFuncSetAttribute(k_mma<2>, cudaFuncAttributeMaxDynamicSharedMemorySize, DSMEM_BYTES);
    cudaFuncSetAttribute(k_mma<3>, cudaFuncAttributeMaxDynamicSharedMemorySize, DSMEM_BYTES);

    // 0) weight prep: transpose + fp16
    k_wprep<<<dim3(C3 / 32, CDIM / 32), 256>>>(qkvw, p_wt + WT_QKV, CDIM, C3);
    k_wprep<<<dim3(CDIM / 32, CDIM / 32), 256>>>(projw, p_wt + WT_PROJ, CDIM, CDIM);
    k_wprep<<<dim3(HIDD / 32, CDIM / 32), 256>>>(fc1w, p_wt + WT_FC1, CDIM, HIDD);
    k_wprep<<<dim3(CDIM / 32, HIDD / 32), 256>>>(fc2w, p_wt + WT_FC2, HIDD, CDIM);

    // 1) LN1 + shift + partition (half out)
    k_ln<1><<<NROWS / 4, 128>>>(x, n1w, n1b, p_xw);
    // 2) qkv (half out)
    k_mma<0><<<dim3(C3 / 128, NROWS / 128), 256, DSMEM_BYTES>>>(
        p_xw, p_wt + WT_QKV, qkvb, p_qkv, CDIM, C3, nullptr);
    // 3) attention (half in/out)
    k_attn<<<dim3(NROWS / NTOK, HEADS), 128>>>(p_qkv, rpb, p_att);
    // 4) proj + reverse/unshift + residual -> out (fp32)
    k_mma<2><<<dim3(CDIM / 128, NROWS / 128), 256, DSMEM_BYTES>>>(
        p_att, p_wt + WT_PROJ, projb, out, CDIM, CDIM, x);
    // 5) LN2 (half out)
    k_ln<0><<<NROWS / 4, 128>>>(out, n2w, n2b, p_xn2);
    // 6) fc1 + gelu (half out)
    k_mma<1><<<dim3(HIDD / 128, NROWS / 128), 256, DSMEM_BYTES>>>(
        p_xn2, p_wt + WT_FC1, fc1b, p_hid, CDIM, HIDD, nullptr);
    // 7) fc2 + residual (fp32 final)
    k_mma<3><<<dim3(CDIM / 128, NROWS / 128), 256, DSMEM_BYTES>>>(
        p_hid, p_wt + WT_FC2, fc2b, out, HIDD, CDIM, out);
}

// round 14
// speedup vs baseline: 5.9006x; 1.1884x over previous
#include <cuda_runtime.h>
#include <cuda_fp16.h>
#include <math.h>
#include <stdint.h>

// ---------------- problem constants ----------------
#define BATCH 32
#define HIMG  56
#define CDIM  384
#define NTOK  49
#define NWIN  64
#define NROWS 100352
#define C3    1152
#define HIDD  1536
#define HEADS 12
#define HD    32
#define SHIFT 3

// ---------------- scratch (half activations) ----------------
__device__ __half g_xw [(size_t)NROWS * CDIM];
__device__ __half g_qkv[(size_t)NROWS * C3];
__device__ __half g_att[(size_t)NROWS * CDIM];
__device__ __half g_xn2[(size_t)NROWS * CDIM];
__device__ __half g_hid[(size_t)NROWS * HIDD];
__device__ __half g_wt [1769472];            // weights [n][k], fp16

#define WT_QKV 0
#define WT_PROJ 442368
#define WT_FC1 589824
#define WT_FC2 1179648

// ---------------- helpers ----------------
__device__ __forceinline__ uint32_t s2u(const void* p) {
    uint32_t a;
    asm("{ .reg .u64 t; cvta.to.shared.u64 t, %1; cvt.u32.u64 %0, t; }" : "=r"(a) : "l"(p));
    return a;
}
__device__ __forceinline__ void cp16(uint32_t dst, const void* src) {
    asm volatile("cp.async.cg.shared.global [%0], [%1], 16;" :: "r"(dst), "l"(src));
}
__device__ __forceinline__ void mma_f16(float c[4], const unsigned a[4], const unsigned b[2]) {
    asm volatile("mma.sync.aligned.m16n8k16.row.col.f32.f16.f16.f32 "
                 "{%0,%1,%2,%3}, {%4,%5,%6,%7}, {%8,%9}, {%0,%1,%2,%3};"
                 : "+f"(c[0]), "+f"(c[1]), "+f"(c[2]), "+f"(c[3])
                 : "r"(a[0]), "r"(a[1]), "r"(a[2]), "r"(a[3]),
                   "r"(b[0]), "r"(b[1]));
}

// ---------------- weight prep: W[K][N] fp32 -> WT[n][k] fp16 ----------------
__global__ __launch_bounds__(256) void k_wprep(const float* __restrict__ src,
                                               __half* __restrict__ dst, int K, int N) {
    __shared__ float t[32][33];
    int tx = threadIdx.x & 31, ty = threadIdx.x >> 5;
    int n0 = blockIdx.x * 32, k0 = blockIdx.y * 32;
    #pragma unroll
    for (int j = 0; j < 32; j += 8)
        t[ty + j][tx] = src[(size_t)(k0 + ty + j) * N + n0 + tx];
    __syncthreads();
    #pragma unroll
    for (int j = 0; j < 32; j += 8)
        dst[(size_t)(n0 + ty + j) * K + k0 + tx] = __float2half_rn(t[tx][ty + j]);
}

// ---------------- warp-per-row LN (+optional gather), half output ----------
template<int GATHER>
__global__ __launch_bounds__(128) void k_ln(const float* __restrict__ x,
                                            const float* __restrict__ w,
                                            const float* __restrict__ b,
                                            __half* __restrict__ dst_all) {
    int warp = threadIdx.x >> 5, lane = threadIdx.x & 31;
    int m = blockIdx.x * 4 + warp;
    const float* src;
    if (GATHER) {
        int win = m / NTOK, n = m % NTOK;
        int bb = win >> 6, wi = win & 63;
        int wr = wi >> 3, wc = wi & 7;
        int rs = wr * 7 + n / 7, cs = wc * 7 + n % 7;
        int r = (rs + SHIFT) % HIMG, c = (cs + SHIFT) % HIMG;
        src = x + ((size_t)bb * (HIMG * HIMG) + r * HIMG + c) * CDIM;
    } else {
        src = x + (size_t)m * CDIM;
    }
    float4 v[3];
    #pragma unroll
    for (int i = 0; i < 3; i++) v[i] = *(const float4*)(src + i * 128 + lane * 4);
    float s = 0.f, s2 = 0.f;
    #pragma unroll
    for (int i = 0; i < 3; i++) {
        s  += v[i].x + v[i].y + v[i].z + v[i].w;
        s2 += v[i].x * v[i].x + v[i].y * v[i].y + v[i].z * v[i].z + v[i].w * v[i].w;
    }
    #pragma unroll
    for (int o = 16; o > 0; o >>= 1) {
        s  += __shfl_xor_sync(0xffffffffu, s, o);
        s2 += __shfl_xor_sync(0xffffffffu, s2, o);
    }
    float mean = s * (1.f / CDIM);
    float rstd = rsqrtf(s2 * (1.f / CDIM) - mean * mean + 1e-5f);
    __half* dst = dst_all + (size_t)m * CDIM;
    #pragma unroll
    for (int i = 0; i < 3; i++) {
        float4 wv = *(const float4*)(w + i * 128 + lane * 4);
        float4 bv = *(const float4*)(b + i * 128 + lane * 4);
        int c0 = i * 128 + lane * 4;
        *(__half2*)(dst + c0)     = __floats2half2_rn((v[i].x - mean) * rstd * wv.x + bv.x,
                                                      (v[i].y - mean) * rstd * wv.y + bv.y);
        *(__half2*)(dst + c0 + 2) = __floats2half2_rn((v[i].z - mean) * rstd * wv.z + bv.z,
                                                      (v[i].w - mean) * rstd * wv.w + bv.w);
    }
}

// ---------------- FP16 GEMM: 128x128, warp 64x32, 32-k stages, 2 CTA/SM -----
#define HSTR 40                         // halves per smem row (80B): 64B data + 16B pad
#define A_ST (128 * HSTR)               // halves per tile stage
#define NSTG 4
#define DSMEM_BYTES (NSTG * 2 * A_ST * 2)

template<int EPI>
__global__ __launch_bounds__(256, 2) void k_mma(const __half* __restrict__ A,
                                                const __half* __restrict__ BT,
                                                const float* __restrict__ bias,
                                                void* __restrict__ CoutV,
                                                int K, int N,
                                                const float* __restrict__ res) {
    extern __shared__ __half smemh[];
    __half* sA = smemh;                   // [NSTG][128][HSTR]
    __half* sB = smemh + NSTG * A_ST;
    uint32_t uA = s2u(sA), uB = s2u(sB);

    int tid = threadIdx.x, wid = tid >> 5, lane = tid & 31;
    int gid = lane >> 2, tig = lane & 3;
    int mW = (wid >> 2) * 64;
    int nW = (wid & 3) * 32;

    size_t rowBase = (size_t)blockIdx.y * 128;
    int colB = blockIdx.x * 128;
    const __half* Ab = A + rowBase * K;
    const __half* Bb = BT + (size_t)colB * K;

    float acc[4][4][4];
    #pragma unroll
    for (int mi = 0; mi < 4; mi++)
        #pragma unroll
        for (int ni = 0; ni < 4; ni++)
            #pragma unroll
            for (int r = 0; r < 4; r++) acc[mi][ni][r] = 0.f;

    int S = K >> 5;   // 32 k per stage (64B/row)

    #define ISSUE(s, buf) { int k0 = (s) << 5; \
        _Pragma("unroll") for (int i = 0; i < 2; i++) { \
            int ch = tid + i * 256; int r = ch >> 2, c = ch & 3; \
            cp16(uA + (buf) * A_ST * 2 + r * (HSTR * 2) + c * 16, \
                 Ab + (size_t)r * K + k0 + c * 8); } \
        _Pragma("unroll") for (int i = 0; i < 2; i++) { \
            int ch = tid + i * 256; int r = ch >> 2, c = ch & 3; \
            cp16(uB + (buf) * A_ST * 2 + r * (HSTR * 2) + c * 16, \
                 Bb + (size_t)r * K + k0 + c * 8); } \
        asm volatile("cp.async.commit_group;" ::: "memory"); }

    ISSUE(0, 0); ISSUE(1, 1); ISSUE(2, 2);

    for (int s = 0; s < S; s++) {
        int buf = s & (NSTG - 1);
        asm volatile("cp.async.wait_group 2;" ::: "memory");
        __syncthreads();
        if (s + 3 < S) { ISSUE(s + 3, (s + 3) & (NSTG - 1)); }
        else { asm volatile("cp.async.commit_group;" ::: "memory"); }

        const uint32_t* A32 = (const uint32_t*)(sA + buf * A_ST);
        const uint32_t* B32 = (const uint32_t*)(sB + buf * A_ST);
        #pragma unroll
        for (int kh = 0; kh < 2; kh++) {
            int kb = kh * 8;   // word offset of the 16-k chunk
            unsigned bfr[4][2], afr[4][4];
            #pragma unroll
            for (int ni = 0; ni < 4; ni++) {
                int r = nW + ni * 8 + gid;
                bfr[ni][0] = B32[r * (HSTR / 2) + kb + tig];
                bfr[ni][1] = B32[r * (HSTR / 2) + kb + 4 + tig];
            }
            #pragma unroll
            for (int mi = 0; mi < 4; mi++) {
                int r = mW + mi * 16 + gid;
                afr[mi][0] = A32[r * (HSTR / 2) + kb + tig];
                afr[mi][1] = A32[(r + 8) * (HSTR / 2) + kb + tig];
                afr[mi][2] = A32[r * (HSTR / 2) + kb + 4 + tig];
                afr[mi][3] = A32[(r + 8) * (HSTR / 2) + kb + 4 + tig];
            }
            #pragma unroll
            for (int mi = 0; mi < 4; mi++)
                #pragma unroll
                for (int ni = 0; ni < 4; ni++)
                    mma_f16(acc[mi][ni], afr[mi], bfr[ni]);
        }
    }
    #undef ISSUE
    asm volatile("cp.async.wait_group 0;" ::: "memory");

    // ---------------- epilogue ----------------
    float2 bb2[4];
    #pragma unroll
    for (int ni = 0; ni < 4; ni++)
        bb2[ni] = *(const float2*)(bias + colB + nW + ni * 8 + 2 * tig);

    #pragma unroll
    for (int mi = 0; mi < 4; mi++) {
        #pragma unroll
        for (int half_ = 0; half_ < 2; half_++) {
            size_t row = rowBase + mW + mi * 16 + gid + half_ * 8;
            size_t dstRow = 0;
            if (EPI == 2) {
                int win = (int)(row / NTOK), n = (int)(row % NTOK);
                int bbt = win >> 6, wi = win & 63;
                int wr = wi >> 3, wc = wi & 7;
                int rs = wr * 7 + n / 7, cs = wc * 7 + n % 7;
                int rr = (rs + SHIFT) % HIMG, cg = (cs + SHIFT) % HIMG;
                dstRow = ((size_t)bbt * (HIMG * HIMG) + rr * HIMG + cg) * CDIM;
            }
            #pragma unroll
            for (int ni = 0; ni < 4; ni++) {
                int col = colB + nW + ni * 8 + 2 * tig;
                float v0 = acc[mi][ni][half_ * 2]     + bb2[ni].x;
                float v1 = acc[mi][ni][half_ * 2 + 1] + bb2[ni].y;
                if (EPI == 0) {
                    __half* hC = (__half*)CoutV;
                    *(__half2*)(&hC[row * N + col]) = __floats2half2_rn(v0, v1);
                } else if (EPI == 1) {
                    v0 = 0.5f * v0 * (1.0f + erff(v0 * 0.70710678118654752f));
                    v1 = 0.5f * v1 * (1.0f + erff(v1 * 0.70710678118654752f));
                    __half* hC = (__half*)CoutV;
                    *(__half2*)(&hC[row * N + col]) = __floats2half2_rn(v0, v1);
                } else if (EPI == 2) {
                    float* fC = (float*)CoutV;
                    float2 rv = *(const float2*)(&res[dstRow + col]);
                    *(float2*)(&fC[dstRow + col]) = make_float2(rv.x + v0, rv.y + v1);
                } else {
                    float* fC = (float*)CoutV;
                    size_t o = row * N + col;
                    float2 rv = *(const float2*)(&res[o]);
                    *(float2*)(&fC[o]) = make_float2(rv.x + v0, rv.y + v1);
                }
            }
        }
    }
}

// ---------------- windowed attention: fp16 mma everywhere -------------------
// qs/ks rows 40 halves (20 words), vt/ps rows 88 halves (44 words)
#define QPAD 40
#define VPAD 88
__global__ __launch_bounds__(128) void k_attn(const __half* __restrict__ qkv,
                                              const float* __restrict__ rpb,
                                              __half* __restrict__ out) {
    __shared__ __align__(16) __half qs[64][QPAD];
    __shared__ __align__(16) __half ks[56][QPAD];
    __shared__ __align__(16) __half vt[32][VPAD];   // V transposed [d][token]
    __shared__ __align__(16) __half ps[64][VPAD];   // P [query][key]
    __shared__ float sbias[169];

    int w = blockIdx.x, h = blockIdx.y, tid = threadIdx.x;
    int wid = tid >> 5, lane = tid & 31;
    int gid = lane >> 2, tig = lane & 3;

    // zero vt fully (padded token cols must be exact zeros, no NaN garbage)
    for (int i = tid; i < 32 * (VPAD / 8); i += 128)
        ((uint4*)vt)[i] = make_uint4(0, 0, 0, 0);
    // zero ps cols 56..63 (k-padding read by PV)
    if (tid < 64) *(uint4*)&ps[tid][56] = make_uint4(0, 0, 0, 0);

    size_t base = (size_t)w * NTOK * C3 + h * HD;
    const __half2 scl2 = __floats2half2_rn(0.17677669529663689f, 0.17677669529663689f);
    // load q (scaled) and k rows; 4 chunks of 8 halves per row
    for (int idx = tid; idx < NTOK * 4; idx += 128) {
        int n = idx >> 2, c8 = (idx & 3) * 8;
        const __half* rbq = qkv + base + (size_t)n * C3 + c8;
        __half2 q4[4];
        #pragma unroll
        for (int j = 0; j < 4; j++) q4[j] = __hmul2(*(const __half2*)(rbq + 2 * j), scl2);
        *(uint4*)&qs[n][c8] = *(uint4*)q4;
        *(uint4*)&ks[n][c8] = *(const uint4*)(rbq + CDIM);
    }
    // V transpose: vt[d][n]
    for (int idx = tid; idx < NTOK * 32; idx += 128) {
        int n = idx >> 5, d = idx & 31;
        vt[d][n] = qkv[base + (size_t)n * C3 + 2 * CDIM + d];
    }
    for (int i = tid; i < 169; i += 128) sbias[i] = rpb[i * HEADS + h];
    __syncthreads();

    // ---- S = Q @ K^T : fp16 m16n8k16, K=32 (2 chunks), N=56 (7 tiles) ----
    int m0 = wid * 16;
    const uint32_t* qsW = (const uint32_t*)qs;
    const uint32_t* ksW = (const uint32_t*)ks;
    float acc[7][4];
    #pragma unroll
    for (int ni = 0; ni < 7; ni++)
        #pragma unroll
        for (int r = 0; r < 4; r++) acc[ni][r] = 0.f;

    #pragma unroll
    for (int kh = 0; kh < 2; kh++) {
        int kb = kh * 8;
        unsigned a[4];
        int r = m0 + gid;
        a[0] = qsW[r * (QPAD / 2) + kb + tig];
        a[1] = qsW[(r + 8) * (QPAD / 2) + kb + tig];
        a[2] = qsW[r * (QPAD / 2) + kb + 4 + tig];
        a[3] = qsW[(r + 8) * (QPAD / 2) + kb + 4 + tig];
        #pragma unroll
        for (int ni = 0; ni < 7; ni++) {
            int j = ni * 8 + gid;
            unsigned b[2];
            b[0] = ksW[j * (QPAD / 2) + kb + tig];
            b[1] = ksW[j * (QPAD / 2) + kb + 4 + tig];
            mma_f16(acc[ni], a, b);
        }
    }

    // ---- bias + mask + softmax in fragments (fp32) ----
    int wi = w & 63, wr = wi >> 3, wc = wi & 7;
    int r1 = m0 + gid, r2 = r1 + 8;
    int ri1 = r1 / 7, ci1 = r1 % 7, ri2 = r2 / 7, ci2 = r2 % 7;
    int rs1 = wr * 7 + ri1, cs1 = wc * 7 + ci1;
    int rs2 = wr * 7 + ri2, cs2 = wc * 7 + ci2;
    int lab1 = ((rs1 < HIMG - 7) ? 0 : ((rs1 < HIMG - SHIFT) ? 1 : 2)) * 3
             + ((cs1 < HIMG - 7) ? 0 : ((cs1 < HIMG - SHIFT) ? 1 : 2));
    int lab2 = ((rs2 < HIMG - 7) ? 0 : ((rs2 < HIMG - SHIFT) ? 1 : 2)) * 3
             + ((cs2 < HIMG - 7) ? 0 : ((cs2 < HIMG - SHIFT) ? 1 : 2));

    float v1[14], v2[14];
    float mx1 = -1e30f, mx2 = -1e30f;
    #pragma unroll
    for (int ni = 0; ni < 7; ni++) {
        #pragma unroll
        for (int bb = 0; bb < 2; bb++) {
            int j = ni * 8 + 2 * tig + bb;
            float t1 = -1e30f, t2 = -1e30f;
            if (j < NTOK) {
                int rj = j / 7, cj = j % 7;
                int rsj = wr * 7 + rj, csj = wc * 7 + cj;
                int labj = ((rsj < HIMG - 7) ? 0 : ((rsj < HIMG - SHIFT) ? 1 : 2)) * 3
                         + ((csj < HIMG - 7) ? 0 : ((csj < HIMG - SHIFT) ? 1 : 2));
                if (r1 < NTOK) {
                    t1 = acc[ni][bb] + sbias[(ri1 - rj + 6) * 13 + (ci1 - cj + 6)];
                    if (lab1 != labj) t1 -= 100.0f;
                }
                if (r2 < NTOK) {
                    t2 = acc[ni][2 + bb] + sbias[(ri2 - rj + 6) * 13 + (ci2 - cj + 6)];
                    if (lab2 != labj) t2 -= 100.0f;
                }
            }
            v1[ni * 2 + bb] = t1; v2[ni * 2 + bb] = t2;
            mx1 = fmaxf(mx1, t1); mx2 = fmaxf(mx2, t2);
        }
    }
    #pragma unroll
    for (int o = 1; o < 4; o <<= 1) {
        mx1 = fmaxf(mx1, __shfl_xor_sync(0xffffffffu, mx1, o));
        mx2 = fmaxf(mx2, __shfl_xor_sync(0xffffffffu, mx2, o));
    }
    float s1 = 0.f, s2 = 0.f;
    #pragma unroll
    for (int t = 0; t < 14; t++) {
        v1[t] = __expf(v1[t] - mx1); s1 += v1[t];
        v2[t] = __expf(v2[t] - mx2); s2 += v2[t];
    }
    #pragma unroll
    for (int o = 1; o < 4; o <<= 1) {
        s1 += __shfl_xor_sync(0xffffffffu, s1, o);
        s2 += __shfl_xor_sync(0xffffffffu, s2, o);
    }
    float inv1 = 1.f / s1, inv2 = 1.f / s2;
    #pragma unroll
    for (int ni = 0; ni < 7; ni++) {
        int j = ni * 8 + 2 * tig;
        *(__half2*)&ps[r1][j] = __floats2half2_rn(v1[ni * 2] * inv1, v1[ni * 2 + 1] * inv1);
        *(__half2*)&ps[r2][j] = __floats2half2_rn(v2[ni * 2] * inv2, v2[ni * 2 + 1] * inv2);
    }
    __syncwarp();

    // ---- O = P @ V : fp16 m16n8k16, K=64 (4 chunks), N=32 (4 tiles) ----
    const uint32_t* psW = (const uint32_t*)ps;
    const uint32_t* vtW = (const uint32_t*)vt;
    float oacc[4][4];
    #pragma unroll
    for (int ni = 0; ni < 4; ni++)
        #pragma unroll
        for (int r = 0; r < 4; r++) oacc[ni][r] = 0.f;

    #pragma unroll
    for (int kc = 0; kc < 4; kc++) {
        int kb = kc * 8;
        unsigned a[4];
        a[0] = psW[r1 * (VPAD / 2) + kb + tig];
        a[1] = psW[r2 * (VPAD / 2) + kb + tig];
        a[2] = psW[r1 * (VPAD / 2) + kb + 4 + tig];
        a[3] = psW[r2 * (VPAD / 2) + kb + 4 + tig];
        #pragma unroll
        for (int ni = 0; ni < 4; ni++) {
            int d = ni * 8 + gid;
            unsigned b[2];
            b[0] = vtW[d * (VPAD / 2) + kb + tig];
            b[1] = vtW[d * (VPAD / 2) + kb + 4 + tig];
            mma_f16(oacc[ni], a, b);
        }
    }

    #pragma unroll
    for (int half_ = 0; half_ < 2; half_++) {
        int r = (half_ == 0) ? r1 : r2;
        if (r < NTOK) {
            __half* op = out + ((size_t)w * NTOK + r) * CDIM + h * HD;
            #pragma unroll
            for (int ni = 0; ni < 4; ni++)
                *(__half2*)(op + ni * 8 + 2 * tig) =
                    __floats2half2_rn(oacc[ni][half_ * 2], oacc[ni][half_ * 2 + 1]);
        }
    }
}

// ---------------- launch ----------------
extern "C" void kernel_launch(void* const* d_in, const int* in_sizes, int n_in,
                              void* d_out, int out_size) {
    const float* x     = (const float*)d_in[0];
    const float* n1w   = (const float*)d_in[1];
    const float* n1b   = (const float*)d_in[2];
    const float* qkvw  = (const float*)d_in[3];
    const float* qkvb  = (const float*)d_in[4];
    const float* rpb   = (const float*)d_in[5];
    const float* projw = (const float*)d_in[6];
    const float* projb = (const float*)d_in[7];
    const float* n2w   = (const float*)d_in[8];
    const float* n2b   = (const float*)d_in[9];
    const float* fc1w  = (const float*)d_in[10];
    const float* fc1b  = (const float*)d_in[11];
    const float* fc2w  = (const float*)d_in[12];
    const float* fc2b  = (const float*)d_in[13];
    float* out = (float*)d_out;

    __half *p_xw, *p_qkv, *p_att, *p_xn2, *p_hid, *p_wt;
    cudaGetSymbolAddress((void**)&p_xw,  g_xw);
    cudaGetSymbolAddress((void**)&p_qkv, g_qkv);
    cudaGetSymbolAddress((void**)&p_att, g_att);
    cudaGetSymbolAddress((void**)&p_xn2, g_xn2);
    cudaGetSymbolAddress((void**)&p_hid, g_hid);
    cudaGetSymbolAddress((void**)&p_wt,  g_wt);

    cudaFuncSetAttribute(k_mma<0>, cudaFuncAttributeMaxDynamicSharedMemorySize, DSMEM_BYTES);
    cudaFuncSetAttribute(k_mma<1>, cudaFuncAttributeMaxDynamicSharedMemorySize, DSMEM_BYTES);
    cudaFuncSetAttribute(k_mma<2>, cudaFuncAttributeMaxDynamicSharedMemorySize, DSMEM_BYTES);
    cudaFuncSetAttribute(k_mma<3>, cudaFuncAttributeMaxDynamicSharedMemorySize, DSMEM_BYTES);

    // 0) weight prep
    k_wprep<<<dim3(C3 / 32, CDIM / 32), 256>>>(qkvw, p_wt + WT_QKV, CDIM, C3);
    k_wprep<<<dim3(CDIM / 32, CDIM / 32), 256>>>(projw, p_wt + WT_PROJ, CDIM, CDIM);
    k_wprep<<<dim3(HIDD / 32, CDIM / 32), 256>>>(fc1w, p_wt + WT_FC1, CDIM, HIDD);
    k_wprep<<<dim3(CDIM / 32, HIDD / 32), 256>>>(fc2w, p_wt + WT_FC2, HIDD, CDIM);

    // 1) LN1 + shift + partition (half out)
    k_ln<1><<<NROWS / 4, 128>>>(x, n1w, n1b, p_xw);
    // 2) qkv (half out)
    k_mma<0><<<dim3(C3 / 128, NROWS / 128), 256, DSMEM_BYTES>>>(
        p_xw, p_wt + WT_QKV, qkvb, p_qkv, CDIM, C3, nullptr);
    // 3) attention (fp16 mma)
    k_attn<<<dim3(NROWS / NTOK, HEADS), 128>>>(p_qkv, rpb, p_att);
    // 4) proj + reverse/unshift + residual -> out (fp32)
    k_mma<2><<<dim3(CDIM / 128, NROWS / 128), 256, DSMEM_BYTES>>>(
        p_att, p_wt + WT_PROJ, projb, out, CDIM, CDIM, x);
    // 5) LN2 (half out)
    k_ln<0><<<NROWS / 4, 128>>>(out, n2w, n2b, p_xn2);
    // 6) fc1 + gelu (half out)
    k_mma<1><<<dim3(HIDD / 128, NROWS / 128), 256, DSMEM_BYTES>>>(
        p_xn2, p_wt + WT_FC1, fc1b, p_hid, CDIM, HIDD, nullptr);
    // 7) fc2 + residual (fp32 final)
    k_mma<3><<<dim3(CDIM / 128, NROWS / 128), 256, DSMEM_BYTES>>>(
        p_hid, p_wt + WT_FC2, fc2b, out, HIDD, CDIM, out);
}

// round 16
// speedup vs baseline: 5.9245x; 1.0040x over previous
#include <cuda_runtime.h>
#include <cuda_fp16.h>
#include <math.h>
#include <stdint.h>

// ---------------- problem constants ----------------
#define BATCH 32
#define HIMG  56
#define CDIM  384
#define NTOK  49
#define NWIN  64
#define NROWS 100352
#define C3    1152
#define HIDD  1536
#define HEADS 12
#define HD    32
#define SHIFT 3

// ---------------- scratch (half activations) ----------------
__device__ __half g_xw [(size_t)NROWS * CDIM];
__device__ __half g_qkv[(size_t)NROWS * C3];
__device__ __half g_att[(size_t)NROWS * CDIM];
__device__ __half g_xn2[(size_t)NROWS * CDIM];
__device__ __half g_hid[(size_t)NROWS * HIDD];
__device__ __half g_wt [1769472];            // weights [n][k], fp16

#define WT_QKV 0
#define WT_PROJ 442368
#define WT_FC1 589824
#define WT_FC2 1179648

// ---------------- helpers ----------------
__device__ __forceinline__ uint32_t s2u(const void* p) {
    uint32_t a;
    asm("{ .reg .u64 t; cvta.to.shared.u64 t, %1; cvt.u32.u64 %0, t; }" : "=r"(a) : "l"(p));
    return a;
}
__device__ __forceinline__ void cp16(uint32_t dst, const void* src) {
    asm volatile("cp.async.cg.shared.global [%0], [%1], 16;" :: "r"(dst), "l"(src));
}
__device__ __forceinline__ void mma_f16(float c[4], const unsigned a[4], const unsigned b[2]) {
    asm volatile("mma.sync.aligned.m16n8k16.row.col.f32.f16.f16.f32 "
                 "{%0,%1,%2,%3}, {%4,%5,%6,%7}, {%8,%9}, {%0,%1,%2,%3};"
                 : "+f"(c[0]), "+f"(c[1]), "+f"(c[2]), "+f"(c[3])
                 : "r"(a[0]), "r"(a[1]), "r"(a[2]), "r"(a[3]),
                   "r"(b[0]), "r"(b[1]));
}

// ---------------- merged weight prep: 4 matrices, one launch ----------------
// flattened blocks: [0,432) qkv (36x12), [432,576) proj (12x12),
//                   [576,1152) fc1 (48x12), [1152,1728) fc2 (12x48)
__global__ __launch_bounds__(256) void k_wprep4(const float* __restrict__ qkvw,
                                                const float* __restrict__ projw,
                                                const float* __restrict__ fc1w,
                                                const float* __restrict__ fc2w,
                                                __half* __restrict__ dstAll) {
    __shared__ float t[32][33];
    int bid = blockIdx.x;
    const float* src; __half* dst; int K, N, bx, by;
    if (bid < 432)        { src = qkvw; dst = dstAll + WT_QKV;  K = CDIM; N = C3;
                            bx = bid % 36;  by = bid / 36; }
    else if (bid < 576)   { int i = bid - 432; src = projw; dst = dstAll + WT_PROJ; K = CDIM; N = CDIM;
                            bx = i % 12;  by = i / 12; }
    else if (bid < 1152)  { int i = bid - 576; src = fc1w; dst = dstAll + WT_FC1; K = CDIM; N = HIDD;
                            bx = i % 48;  by = i / 48; }
    else                  { int i = bid - 1152; src = fc2w; dst = dstAll + WT_FC2; K = HIDD; N = CDIM;
                            bx = i % 12;  by = i / 12; }
    int tx = threadIdx.x & 31, ty = threadIdx.x >> 5;
    int n0 = bx * 32, k0 = by * 32;
    #pragma unroll
    for (int j = 0; j < 32; j += 8)
        t[ty + j][tx] = src[(size_t)(k0 + ty + j) * N + n0 + tx];
    __syncthreads();
    #pragma unroll
    for (int j = 0; j < 32; j += 8)
        dst[(size_t)(n0 + ty + j) * K + k0 + tx] = __float2half_rn(t[tx][ty + j]);
}

// ---------------- warp-per-row LN (+optional gather), half output ----------
// 256 thr = 8 warps = 8 rows per block
template<int GATHER>
__global__ __launch_bounds__(256) void k_ln(const float* __restrict__ x,
                                            const float* __restrict__ w,
                                            const float* __restrict__ b,
                                            __half* __restrict__ dst_all) {
    int warp = threadIdx.x >> 5, lane = threadIdx.x & 31;
    int m = blockIdx.x * 8 + warp;
    const float* src;
    if (GATHER) {
        int win = m / NTOK, n = m % NTOK;
        int bb = win >> 6, wi = win & 63;
        int wr = wi >> 3, wc = wi & 7;
        int rs = wr * 7 + n / 7, cs = wc * 7 + n % 7;
        int r = (rs + SHIFT) % HIMG, c = (cs + SHIFT) % HIMG;
        src = x + ((size_t)bb * (HIMG * HIMG) + r * HIMG + c) * CDIM;
    } else {
        src = x + (size_t)m * CDIM;
    }
    float4 v[3];
    #pragma unroll
    for (int i = 0; i < 3; i++) v[i] = *(const float4*)(src + i * 128 + lane * 4);
    float s = 0.f, s2 = 0.f;
    #pragma unroll
    for (int i = 0; i < 3; i++) {
        s  += v[i].x + v[i].y + v[i].z + v[i].w;
        s2 += v[i].x * v[i].x + v[i].y * v[i].y + v[i].z * v[i].z + v[i].w * v[i].w;
    }
    #pragma unroll
    for (int o = 16; o > 0; o >>= 1) {
        s  += __shfl_xor_sync(0xffffffffu, s, o);
        s2 += __shfl_xor_sync(0xffffffffu, s2, o);
    }
    float mean = s * (1.f / CDIM);
    float rstd = rsqrtf(s2 * (1.f / CDIM) - mean * mean + 1e-5f);
    __half* dst = dst_all + (size_t)m * CDIM;
    #pragma unroll
    for (int i = 0; i < 3; i++) {
        float4 wv = *(const float4*)(w + i * 128 + lane * 4);
        float4 bv = *(const float4*)(b + i * 128 + lane * 4);
        int c0 = i * 128 + lane * 4;
        *(__half2*)(dst + c0)     = __floats2half2_rn((v[i].x - mean) * rstd * wv.x + bv.x,
                                                      (v[i].y - mean) * rstd * wv.y + bv.y);
        *(__half2*)(dst + c0 + 2) = __floats2half2_rn((v[i].z - mean) * rstd * wv.z + bv.z,
                                                      (v[i].w - mean) * rstd * wv.w + bv.w);
    }
}

// ---------------- FP16 GEMM: 128x128, warp 64x32, 32-k stages, 2 CTA/SM -----
#define HSTR 40
#define A_ST (128 * HSTR)
#define NSTG 4
#define DSMEM_BYTES (NSTG * 2 * A_ST * 2)

template<int EPI>
__global__ __launch_bounds__(256, 2) void k_mma(const __half* __restrict__ A,
                                                const __half* __restrict__ BT,
                                                const float* __restrict__ bias,
                                                void* __restrict__ CoutV,
                                                int K, int N,
                                                const float* __restrict__ res) {
    extern __shared__ __half smemh[];
    __half* sA = smemh;
    __half* sB = smemh + NSTG * A_ST;
    uint32_t uA = s2u(sA), uB = s2u(sB);

    int tid = threadIdx.x, wid = tid >> 5, lane = tid & 31;
    int gid = lane >> 2, tig = lane & 3;
    int mW = (wid >> 2) * 64;
    int nW = (wid & 3) * 32;

    size_t rowBase = (size_t)blockIdx.y * 128;
    int colB = blockIdx.x * 128;
    const __half* Ab = A + rowBase * K;
    const __half* Bb = BT + (size_t)colB * K;

    float acc[4][4][4];
    #pragma unroll
    for (int mi = 0; mi < 4; mi++)
        #pragma unroll
        for (int ni = 0; ni < 4; ni++)
            #pragma unroll
            for (int r = 0; r < 4; r++) acc[mi][ni][r] = 0.f;

    int S = K >> 5;

    #define ISSUE(s, buf) { int k0 = (s) << 5; \
        _Pragma("unroll") for (int i = 0; i < 2; i++) { \
            int ch = tid + i * 256; int r = ch >> 2, c = ch & 3; \
            cp16(uA + (buf) * A_ST * 2 + r * (HSTR * 2) + c * 16, \
                 Ab + (size_t)r * K + k0 + c * 8); } \
        _Pragma("unroll") for (int i = 0; i < 2; i++) { \
            int ch = tid + i * 256; int r = ch >> 2, c = ch & 3; \
            cp16(uB + (buf) * A_ST * 2 + r * (HSTR * 2) + c * 16, \
                 Bb + (size_t)r * K + k0 + c * 8); } \
        asm volatile("cp.async.commit_group;" ::: "memory"); }

    ISSUE(0, 0); ISSUE(1, 1); ISSUE(2, 2);

    for (int s = 0; s < S; s++) {
        int buf = s & (NSTG - 1);
        asm volatile("cp.async.wait_group 2;" ::: "memory");
        __syncthreads();
        if (s + 3 < S) { ISSUE(s + 3, (s + 3) & (NSTG - 1)); }
        else { asm volatile("cp.async.commit_group;" ::: "memory"); }

        const uint32_t* A32 = (const uint32_t*)(sA + buf * A_ST);
        const uint32_t* B32 = (const uint32_t*)(sB + buf * A_ST);
        #pragma unroll
        for (int kh = 0; kh < 2; kh++) {
            int kb = kh * 8;
            unsigned bfr[4][2], afr[4][4];
            #pragma unroll
            for (int ni = 0; ni < 4; ni++) {
                int r = nW + ni * 8 + gid;
                bfr[ni][0] = B32[r * (HSTR / 2) + kb + tig];
                bfr[ni][1] = B32[r * (HSTR / 2) + kb + 4 + tig];
            }
            #pragma unroll
            for (int mi = 0; mi < 4; mi++) {
                int r = mW + mi * 16 + gid;
                afr[mi][0] = A32[r * (HSTR / 2) + kb + tig];
                afr[mi][1] = A32[(r + 8) * (HSTR / 2) + kb + tig];
                afr[mi][2] = A32[r * (HSTR / 2) + kb + 4 + tig];
                afr[mi][3] = A32[(r + 8) * (HSTR / 2) + kb + 4 + tig];
            }
            #pragma unroll
            for (int mi = 0; mi < 4; mi++)
                #pragma unroll
                for (int ni = 0; ni < 4; ni++)
                    mma_f16(acc[mi][ni], afr[mi], bfr[ni]);
        }
    }
    #undef ISSUE
    asm volatile("cp.async.wait_group 0;" ::: "memory");

    // ---------------- epilogue ----------------
    float2 bb2[4];
    #pragma unroll
    for (int ni = 0; ni < 4; ni++)
        bb2[ni] = *(const float2*)(bias + colB + nW + ni * 8 + 2 * tig);

    #pragma unroll
    for (int mi = 0; mi < 4; mi++) {
        #pragma unroll
        for (int half_ = 0; half_ < 2; half_++) {
            size_t row = rowBase + mW + mi * 16 + gid + half_ * 8;
            size_t dstRow = 0;
            if (EPI == 2) {
                int win = (int)(row / NTOK), n = (int)(row % NTOK);
                int bbt = win >> 6, wi = win & 63;
                int wr = wi >> 3, wc = wi & 7;
                int rs = wr * 7 + n / 7, cs = wc * 7 + n % 7;
                int rr = (rs + SHIFT) % HIMG, cg = (cs + SHIFT) % HIMG;
                dstRow = ((size_t)bbt * (HIMG * HIMG) + rr * HIMG + cg) * CDIM;
            }
            #pragma unroll
            for (int ni = 0; ni < 4; ni++) {
                int col = colB + nW + ni * 8 + 2 * tig;
                float v0 = acc[mi][ni][half_ * 2]     + bb2[ni].x;
                float v1 = acc[mi][ni][half_ * 2 + 1] + bb2[ni].y;
                if (EPI == 0) {
                    __half* hC = (__half*)CoutV;
                    *(__half2*)(&hC[row * N + col]) = __floats2half2_rn(v0, v1);
                } else if (EPI == 1) {
                    v0 = 0.5f * v0 * (1.0f + erff(v0 * 0.70710678118654752f));
                    v1 = 0.5f * v1 * (1.0f + erff(v1 * 0.70710678118654752f));
                    __half* hC = (__half*)CoutV;
                    *(__half2*)(&hC[row * N + col]) = __floats2half2_rn(v0, v1);
                } else if (EPI == 2) {
                    float* fC = (float*)CoutV;
                    float2 rv = *(const float2*)(&res[dstRow + col]);
                    *(float2*)(&fC[dstRow + col]) = make_float2(rv.x + v0, rv.y + v1);
                } else {
                    float* fC = (float*)CoutV;
                    size_t o = row * N + col;
                    float2 rv = *(const float2*)(&res[o]);
                    *(float2*)(&fC[o]) = make_float2(rv.x + v0, rv.y + v1);
                }
            }
        }
    }
}

// ---------------- windowed attention: fp16 mma everywhere -------------------
#define QPAD 40
#define VPAD 72
__global__ __launch_bounds__(128) void k_attn(const __half* __restrict__ qkv,
                                              const float* __restrict__ rpb,
                                              __half* __restrict__ out) {
    __shared__ __align__(16) __half qs[64][QPAD];
    __shared__ __align__(16) __half ks[56][QPAD];
    __shared__ __align__(16) __half vt[32][VPAD];   // V transposed [d][token]
    __shared__ __align__(16) __half ps[64][VPAD];   // P [query][key]
    __shared__ float sbias[169];

    int w = blockIdx.x, h = blockIdx.y, tid = threadIdx.x;
    int wid = tid >> 5, lane = tid & 31;
    int gid = lane >> 2, tig = lane & 3;

    // zero vt fully; zero ps k-pad cols 56..63
    for (int i = tid; i < 32 * (VPAD / 8); i += 128)
        ((uint4*)vt)[i] = make_uint4(0, 0, 0, 0);
    if (tid < 64) *(uint4*)&ps[tid][56] = make_uint4(0, 0, 0, 0);

    size_t base = (size_t)w * NTOK * C3 + h * HD;
    const __half2 scl2 = __floats2half2_rn(0.17677669529663689f, 0.17677669529663689f);
    for (int idx = tid; idx < NTOK * 4; idx += 128) {
        int n = idx >> 2, c8 = (idx & 3) * 8;
        const __half* rbq = qkv + base + (size_t)n * C3 + c8;
        __half2 q4[4];
        #pragma unroll
        for (int j = 0; j < 4; j++) q4[j] = __hmul2(*(const __half2*)(rbq + 2 * j), scl2);
        *(uint4*)&qs[n][c8] = *(uint4*)q4;
        *(uint4*)&ks[n][c8] = *(const uint4*)(rbq + CDIM);
    }
    for (int idx = tid; idx < NTOK * 32; idx += 128) {
        int n = idx >> 5, d = idx & 31;
        vt[d][n] = qkv[base + (size_t)n * C3 + 2 * CDIM + d];
    }
    for (int i = tid; i < 169; i += 128) sbias[i] = rpb[i * HEADS + h];
    __syncthreads();

    // ---- S = Q @ K^T ----
    int m0 = wid * 16;
    const uint32_t* qsW = (const uint32_t*)qs;
    const uint32_t* ksW = (const uint32_t*)ks;
    float acc[7][4];
    #pragma unroll
    for (int ni = 0; ni < 7; ni++)
        #pragma unroll
        for (int r = 0; r < 4; r++) acc[ni][r] = 0.f;

    #pragma unroll
    for (int kh = 0; kh < 2; kh++) {
        int kb = kh * 8;
        unsigned a[4];
        int r = m0 + gid;
        a[0] = qsW[r * (QPAD / 2) + kb + tig];
        a[1] = qsW[(r + 8) * (QPAD / 2) + kb + tig];
        a[2] = qsW[r * (QPAD / 2) + kb + 4 + tig];
        a[3] = qsW[(r + 8) * (QPAD / 2) + kb + 4 + tig];
        #pragma unroll
        for (int ni = 0; ni < 7; ni++) {
            int j = ni * 8 + gid;
            unsigned b[2];
            b[0] = ksW[j * (QPAD / 2) + kb + tig];
            b[1] = ksW[j * (QPAD / 2) + kb + 4 + tig];
            mma_f16(acc[ni], a, b);
        }
    }

    // ---- bias + mask + softmax in fragments (fp32) ----
    int wi = w & 63, wr = wi >> 3, wc = wi & 7;
    int r1 = m0 + gid, r2 = r1 + 8;
    int ri1 = r1 / 7, ci1 = r1 % 7, ri2 = r2 / 7, ci2 = r2 % 7;
    int rs1 = wr * 7 + ri1, cs1 = wc * 7 + ci1;
    int rs2 = wr * 7 + ri2, cs2 = wc * 7 + ci2;
    int lab1 = ((rs1 < HIMG - 7) ? 0 : ((rs1 < HIMG - SHIFT) ? 1 : 2)) * 3
             + ((cs1 < HIMG - 7) ? 0 : ((cs1 < HIMG - SHIFT) ? 1 : 2));
    int lab2 = ((rs2 < HIMG - 7) ? 0 : ((rs2 < HIMG - SHIFT) ? 1 : 2)) * 3
             + ((cs2 < HIMG - 7) ? 0 : ((cs2 < HIMG - SHIFT) ? 1 : 2));

    float v1[14], v2[14];
    float mx1 = -1e30f, mx2 = -1e30f;
    #pragma unroll
    for (int ni = 0; ni < 7; ni++) {
        #pragma unroll
        for (int bb = 0; bb < 2; bb++) {
            int j = ni * 8 + 2 * tig + bb;
            float t1 = -1e30f, t2 = -1e30f;
            if (j < NTOK) {
                int rj = j / 7, cj = j % 7;
                int rsj = wr * 7 + rj, csj = wc * 7 + cj;
                int labj = ((rsj < HIMG - 7) ? 0 : ((rsj < HIMG - SHIFT) ? 1 : 2)) * 3
                         + ((csj < HIMG - 7) ? 0 : ((csj < HIMG - SHIFT) ? 1 : 2));
                if (r1 < NTOK) {
                    t1 = acc[ni][bb] + sbias[(ri1 - rj + 6) * 13 + (ci1 - cj + 6)];
                    if (lab1 != labj) t1 -= 100.0f;
                }
                if (r2 < NTOK) {
                    t2 = acc[ni][2 + bb] + sbias[(ri2 - rj + 6) * 13 + (ci2 - cj + 6)];
                    if (lab2 != labj) t2 -= 100.0f;
                }
            }
            v1[ni * 2 + bb] = t1; v2[ni * 2 + bb] = t2;
            mx1 = fmaxf(mx1, t1); mx2 = fmaxf(mx2, t2);
        }
    }
    #pragma unroll
    for (int o = 1; o < 4; o <<= 1) {
        mx1 = fmaxf(mx1, __shfl_xor_sync(0xffffffffu, mx1, o));
        mx2 = fmaxf(mx2, __shfl_xor_sync(0xffffffffu, mx2, o));
    }
    float s1 = 0.f, s2 = 0.f;
    #pragma unroll
    for (int t = 0; t < 14; t++) {
        v1[t] = __expf(v1[t] - mx1); s1 += v1[t];
        v2[t] = __expf(v2[t] - mx2); s2 += v2[t];
    }
    #pragma unroll
    for (int o = 1; o < 4; o <<= 1) {
        s1 += __shfl_xor_sync(0xffffffffu, s1, o);
        s2 += __shfl_xor_sync(0xffffffffu, s2, o);
    }
    float inv1 = 1.f / s1, inv2 = 1.f / s2;
    #pragma unroll
    for (int ni = 0; ni < 7; ni++) {
        int j = ni * 8 + 2 * tig;
        *(__half2*)&ps[r1][j] = __floats2half2_rn(v1[ni * 2] * inv1, v1[ni * 2 + 1] * inv1);
        *(__half2*)&ps[r2][j] = __floats2half2_rn(v2[ni * 2] * inv2, v2[ni * 2 + 1] * inv2);
    }
    __syncwarp();

    // ---- O = P @ V ----
    const uint32_t* psW = (const uint32_t*)ps;
    const uint32_t* vtW = (const uint32_t*)vt;
    float oacc[4][4];
    #pragma unroll
    for (int ni = 0; ni < 4; ni++)
        #pragma unroll
        for (int r = 0; r < 4; r++) oacc[ni][r] = 0.f;

    #pragma unroll
    for (int kc = 0; kc < 4; kc++) {
        int kb = kc * 8;
        unsigned a[4];
        a[0] = psW[r1 * (VPAD / 2) + kb + tig];
        a[1] = psW[r2 * (VPAD / 2) + kb + tig];
        a[2] = psW[r1 * (VPAD / 2) + kb + 4 + tig];
        a[3] = psW[r2 * (VPAD / 2) + kb + 4 + tig];
        #pragma unroll
        for (int ni = 0; ni < 4; ni++) {
            int d = ni * 8 + gid;
            unsigned b[2];
            b[0] = vtW[d * (VPAD / 2) + kb + tig];
            b[1] = vtW[d * (VPAD / 2) + kb + 4 + tig];
            mma_f16(oacc[ni], a, b);
        }
    }

    #pragma unroll
    for (int half_ = 0; half_ < 2; half_++) {
        int r = (half_ == 0) ? r1 : r2;
        if (r < NTOK) {
            __half* op = out + ((size_t)w * NTOK + r) * CDIM + h * HD;
            #pragma unroll
            for (int ni = 0; ni < 4; ni++)
                *(__half2*)(op + ni * 8 + 2 * tig) =
                    __floats2half2_rn(oacc[ni][half_ * 2], oacc[ni][half_ * 2 + 1]);
        }
    }
}

// ---------------- launch ----------------
extern "C" void kernel_launch(void* const* d_in, const int* in_sizes, int n_in,
                              void* d_out, int out_size) {
    const float* x     = (const float*)d_in[0];
    const float* n1w   = (const float*)d_in[1];
    const float* n1b   = (const float*)d_in[2];
    const float* qkvw  = (const float*)d_in[3];
    const float* qkvb  = (const float*)d_in[4];
    const float* rpb   = (const float*)d_in[5];
    const float* projw = (const float*)d_in[6];
    const float* projb = (const float*)d_in[7];
    const float* n2w   = (const float*)d_in[8];
    const float* n2b   = (const float*)d_in[9];
    const float* fc1w  = (const float*)d_in[10];
    const float* fc1b  = (const float*)d_in[11];
    const float* fc2w  = (const float*)d_in[12];
    const float* fc2b  = (const float*)d_in[13];
    float* out = (float*)d_out;

    __half *p_xw, *p_qkv, *p_att, *p_xn2, *p_hid, *p_wt;
    cudaGetSymbolAddress((void**)&p_xw,  g_xw);
    cudaGetSymbolAddress((void**)&p_qkv, g_qkv);
    cudaGetSymbolAddress((void**)&p_att, g_att);
    cudaGetSymbolAddress((void**)&p_xn2, g_xn2);
    cudaGetSymbolAddress((void**)&p_hid, g_hid);
    cudaGetSymbolAddress((void**)&p_wt,  g_wt);

    cudaFuncSetAttribute(k_mma<0>, cudaFuncAttributeMaxDynamicSharedMemorySize, DSMEM_BYTES);
    cudaFuncSetAttribute(k_mma<1>, cudaFuncAttributeMaxDynamicSharedMemorySize, DSMEM_BYTES);
    cudaFuncSetAttribute(k_mma<2>, cudaFuncAttributeMaxDynamicSharedMemorySize, DSMEM_BYTES);
    cudaFuncSetAttribute(k_mma<3>, cudaFuncAttributeMaxDynamicSharedMemorySize, DSMEM_BYTES);

    // 0) weight prep (single launch)
    k_wprep4<<<1728, 256>>>(qkvw, projw, fc1w, fc2w, p_wt);
    // 1) LN1 + shift + partition (half out)
    k_ln<1><<<NROWS / 8, 256>>>(x, n1w, n1b, p_xw);
    // 2) qkv (half out)
    k_mma<0><<<dim3(C3 / 128, NROWS / 128), 256, DSMEM_BYTES>>>(
        p_xw, p_wt + WT_QKV, qkvb, p_qkv, CDIM, C3, nullptr);
    // 3) attention (fp16 mma)
    k_attn<<<dim3(NROWS / NTOK, HEADS), 128>>>(p_qkv, rpb, p_att);
    // 4) proj + reverse/unshift + residual -> out (fp32)
    k_mma<2><<<dim3(CDIM / 128, NROWS / 128), 256, DSMEM_BYTES>>>(
        p_att, p_wt + WT_PROJ, projb, out, CDIM, CDIM, x);
    // 5) LN2 (half out)
    k_ln<0><<<NROWS / 8, 256>>>(out, n2w, n2b, p_xn2);
    // 6) fc1 + gelu (half out)
    k_mma<1><<<dim3(HIDD / 128, NROWS / 128), 256, DSMEM_BYTES>>>(
        p_xn2, p_wt + WT_FC1, fc1b, p_hid, CDIM, HIDD, nullptr);
    // 7) fc2 + residual (fp32 final)
    k_mma<3><<<dim3(CDIM / 128, NROWS / 128), 256, DSMEM_BYTES>>>(
        p_hid, p_wt + WT_FC2, fc2b, out, HIDD, CDIM, out);
}

// round 17
// speedup vs baseline: 5.9390x; 1.0024x over previous
#include <cuda_runtime.h>
#include <cuda_fp16.h>
#include <math.h>
#include <stdint.h>

// ---------------- problem constants ----------------
#define BATCH 32
#define HIMG  56
#define CDIM  384
#define NTOK  49
#define NWIN  64
#define NROWS 100352
#define C3    1152
#define HIDD  1536
#define HEADS 12
#define HD    32
#define SHIFT 3

// ---------------- scratch (half activations) ----------------
__device__ __half g_xw [(size_t)NROWS * CDIM];
__device__ __half g_qkv[(size_t)NROWS * C3];
__device__ __half g_att[(size_t)NROWS * CDIM];
__device__ __half g_xn2[(size_t)NROWS * CDIM];
__device__ __half g_hid[(size_t)NROWS * HIDD];
__device__ __half g_wt [1769472];            // weights [n][k], fp16

#define WT_QKV 0
#define WT_PROJ 442368
#define WT_FC1 589824
#define WT_FC2 1179648

// ---------------- helpers ----------------
__device__ __forceinline__ uint32_t s2u(const void* p) {
    uint32_t a;
    asm("{ .reg .u64 t; cvta.to.shared.u64 t, %1; cvt.u32.u64 %0, t; }" : "=r"(a) : "l"(p));
    return a;
}
__device__ __forceinline__ void cp16(uint32_t dst, const void* src) {
    asm volatile("cp.async.cg.shared.global [%0], [%1], 16;" :: "r"(dst), "l"(src));
}
__device__ __forceinline__ void mma_f16(float c[4], const unsigned a[4], const unsigned b[2]) {
    asm volatile("mma.sync.aligned.m16n8k16.row.col.f32.f16.f16.f32 "
                 "{%0,%1,%2,%3}, {%4,%5,%6,%7}, {%8,%9}, {%0,%1,%2,%3};"
                 : "+f"(c[0]), "+f"(c[1]), "+f"(c[2]), "+f"(c[3])
                 : "r"(a[0]), "r"(a[1]), "r"(a[2]), "r"(a[3]),
                   "r"(b[0]), "r"(b[1]));
}

// ---------------- merged weight prep: 4 matrices, one launch ----------------
__global__ __launch_bounds__(256) void k_wprep4(const float* __restrict__ qkvw,
                                                const float* __restrict__ projw,
                                                const float* __restrict__ fc1w,
                                                const float* __restrict__ fc2w,
                                                __half* __restrict__ dstAll) {
    __shared__ float t[32][33];
    int bid = blockIdx.x;
    const float* src; __half* dst; int K, N, bx, by;
    if (bid < 432)        { src = qkvw; dst = dstAll + WT_QKV;  K = CDIM; N = C3;
                            bx = bid % 36;  by = bid / 36; }
    else if (bid < 576)   { int i = bid - 432; src = projw; dst = dstAll + WT_PROJ; K = CDIM; N = CDIM;
                            bx = i % 12;  by = i / 12; }
    else if (bid < 1152)  { int i = bid - 576; src = fc1w; dst = dstAll + WT_FC1; K = CDIM; N = HIDD;
                            bx = i % 48;  by = i / 48; }
    else                  { int i = bid - 1152; src = fc2w; dst = dstAll + WT_FC2; K = HIDD; N = CDIM;
                            bx = i % 12;  by = i / 12; }
    int tx = threadIdx.x & 31, ty = threadIdx.x >> 5;
    int n0 = bx * 32, k0 = by * 32;
    #pragma unroll
    for (int j = 0; j < 32; j += 8)
        t[ty + j][tx] = src[(size_t)(k0 + ty + j) * N + n0 + tx];
    __syncthreads();
    #pragma unroll
    for (int j = 0; j < 32; j += 8)
        dst[(size_t)(n0 + ty + j) * K + k0 + tx] = __float2half_rn(t[tx][ty + j]);
}

// ---------------- warp-per-row LN (+optional gather), half output ----------
template<int GATHER>
__global__ __launch_bounds__(256) void k_ln(const float* __restrict__ x,
                                            const float* __restrict__ w,
                                            const float* __restrict__ b,
                                            __half* __restrict__ dst_all) {
    int warp = threadIdx.x >> 5, lane = threadIdx.x & 31;
    int m = blockIdx.x * 8 + warp;
    const float* src;
    if (GATHER) {
        int win = m / NTOK, n = m % NTOK;
        int bb = win >> 6, wi = win & 63;
        int wr = wi >> 3, wc = wi & 7;
        int rs = wr * 7 + n / 7, cs = wc * 7 + n % 7;
        int r = (rs + SHIFT) % HIMG, c = (cs + SHIFT) % HIMG;
        src = x + ((size_t)bb * (HIMG * HIMG) + r * HIMG + c) * CDIM;
    } else {
        src = x + (size_t)m * CDIM;
    }
    float4 v[3];
    #pragma unroll
    for (int i = 0; i < 3; i++) v[i] = *(const float4*)(src + i * 128 + lane * 4);
    float s = 0.f, s2 = 0.f;
    #pragma unroll
    for (int i = 0; i < 3; i++) {
        s  += v[i].x + v[i].y + v[i].z + v[i].w;
        s2 += v[i].x * v[i].x + v[i].y * v[i].y + v[i].z * v[i].z + v[i].w * v[i].w;
    }
    #pragma unroll
    for (int o = 16; o > 0; o >>= 1) {
        s  += __shfl_xor_sync(0xffffffffu, s, o);
        s2 += __shfl_xor_sync(0xffffffffu, s2, o);
    }
    float mean = s * (1.f / CDIM);
    float rstd = rsqrtf(s2 * (1.f / CDIM) - mean * mean + 1e-5f);
    __half* dst = dst_all + (size_t)m * CDIM;
    #pragma unroll
    for (int i = 0; i < 3; i++) {
        float4 wv = *(const float4*)(w + i * 128 + lane * 4);
        float4 bv = *(const float4*)(b + i * 128 + lane * 4);
        int c0 = i * 128 + lane * 4;
        *(__half2*)(dst + c0)     = __floats2half2_rn((v[i].x - mean) * rstd * wv.x + bv.x,
                                                      (v[i].y - mean) * rstd * wv.y + bv.y);
        *(__half2*)(dst + c0 + 2) = __floats2half2_rn((v[i].z - mean) * rstd * wv.z + bv.z,
                                                      (v[i].w - mean) * rstd * wv.w + bv.w);
    }
}

// ---------------- FP16 GEMM: 128x128, warp 64x32, 32-k stages, 2 CTA/SM -----
#define HSTR 40
#define A_ST (128 * HSTR)
#define NSTG 4
#define DSMEM_BYTES (NSTG * 2 * A_ST * 2)

template<int EPI>
__global__ __launch_bounds__(256, 2) void k_mma(const __half* __restrict__ A,
                                                const __half* __restrict__ BT,
                                                const float* __restrict__ bias,
                                                void* __restrict__ CoutV,
                                                int K, int N,
                                                const float* __restrict__ res) {
    extern __shared__ __half smemh[];
    __half* sA = smemh;
    __half* sB = smemh + NSTG * A_ST;
    uint32_t uA = s2u(sA), uB = s2u(sB);

    int tid = threadIdx.x, wid = tid >> 5, lane = tid & 31;
    int gid = lane >> 2, tig = lane & 3;
    int mW = (wid >> 2) * 64;
    int nW = (wid & 3) * 32;

    size_t rowBase = (size_t)blockIdx.y * 128;
    int colB = blockIdx.x * 128;
    const __half* Ab = A + rowBase * K;
    const __half* Bb = BT + (size_t)colB * K;

    float acc[4][4][4];
    #pragma unroll
    for (int mi = 0; mi < 4; mi++)
        #pragma unroll
        for (int ni = 0; ni < 4; ni++)
            #pragma unroll
            for (int r = 0; r < 4; r++) acc[mi][ni][r] = 0.f;

    int S = K >> 5;

    #define ISSUE(s, buf) { int k0 = (s) << 5; \
        _Pragma("unroll") for (int i = 0; i < 2; i++) { \
            int ch = tid + i * 256; int r = ch >> 2, c = ch & 3; \
            cp16(uA + (buf) * A_ST * 2 + r * (HSTR * 2) + c * 16, \
                 Ab + (size_t)r * K + k0 + c * 8); } \
        _Pragma("unroll") for (int i = 0; i < 2; i++) { \
            int ch = tid + i * 256; int r = ch >> 2, c = ch & 3; \
            cp16(uB + (buf) * A_ST * 2 + r * (HSTR * 2) + c * 16, \
                 Bb + (size_t)r * K + k0 + c * 8); } \
        asm volatile("cp.async.commit_group;" ::: "memory"); }

    ISSUE(0, 0); ISSUE(1, 1); ISSUE(2, 2);

    for (int s = 0; s < S; s++) {
        int buf = s & (NSTG - 1);
        asm volatile("cp.async.wait_group 2;" ::: "memory");
        __syncthreads();
        if (s + 3 < S) { ISSUE(s + 3, (s + 3) & (NSTG - 1)); }
        else { asm volatile("cp.async.commit_group;" ::: "memory"); }

        const uint32_t* A32 = (const uint32_t*)(sA + buf * A_ST);
        const uint32_t* B32 = (const uint32_t*)(sB + buf * A_ST);
        #pragma unroll
        for (int kh = 0; kh < 2; kh++) {
            int kb = kh * 8;
            unsigned bfr[4][2], afr[4][4];
            #pragma unroll
            for (int ni = 0; ni < 4; ni++) {
                int r = nW + ni * 8 + gid;
                bfr[ni][0] = B32[r * (HSTR / 2) + kb + tig];
                bfr[ni][1] = B32[r * (HSTR / 2) + kb + 4 + tig];
            }
            #pragma unroll
            for (int mi = 0; mi < 4; mi++) {
                int r = mW + mi * 16 + gid;
                afr[mi][0] = A32[r * (HSTR / 2) + kb + tig];
                afr[mi][1] = A32[(r + 8) * (HSTR / 2) + kb + tig];
                afr[mi][2] = A32[r * (HSTR / 2) + kb + 4 + tig];
                afr[mi][3] = A32[(r + 8) * (HSTR / 2) + kb + 4 + tig];
            }
            #pragma unroll
            for (int mi = 0; mi < 4; mi++)
                #pragma unroll
                for (int ni = 0; ni < 4; ni++)
                    mma_f16(acc[mi][ni], afr[mi], bfr[ni]);
        }
    }
    #undef ISSUE
    asm volatile("cp.async.wait_group 0;" ::: "memory");

    // ---------------- epilogue ----------------
    float2 bb2[4];
    #pragma unroll
    for (int ni = 0; ni < 4; ni++)
        bb2[ni] = *(const float2*)(bias + colB + nW + ni * 8 + 2 * tig);

    #pragma unroll
    for (int mi = 0; mi < 4; mi++) {
        #pragma unroll
        for (int half_ = 0; half_ < 2; half_++) {
            size_t row = rowBase + mW + mi * 16 + gid + half_ * 8;
            size_t dstRow = 0;
            if (EPI == 2) {
                int win = (int)(row / NTOK), n = (int)(row % NTOK);
                int bbt = win >> 6, wi = win & 63;
                int wr = wi >> 3, wc = wi & 7;
                int rs = wr * 7 + n / 7, cs = wc * 7 + n % 7;
                int rr = (rs + SHIFT) % HIMG, cg = (cs + SHIFT) % HIMG;
                dstRow = ((size_t)bbt * (HIMG * HIMG) + rr * HIMG + cg) * CDIM;
            }
            #pragma unroll
            for (int ni = 0; ni < 4; ni++) {
                int col = colB + nW + ni * 8 + 2 * tig;
                float v0 = acc[mi][ni][half_ * 2]     + bb2[ni].x;
                float v1 = acc[mi][ni][half_ * 2 + 1] + bb2[ni].y;
                if (EPI == 0) {
                    __half* hC = (__half*)CoutV;
                    *(__half2*)(&hC[row * N + col]) = __floats2half2_rn(v0, v1);
                } else if (EPI == 1) {
                    v0 = 0.5f * v0 * (1.0f + erff(v0 * 0.70710678118654752f));
                    v1 = 0.5f * v1 * (1.0f + erff(v1 * 0.70710678118654752f));
                    __half* hC = (__half*)CoutV;
                    *(__half2*)(&hC[row * N + col]) = __floats2half2_rn(v0, v1);
                } else if (EPI == 2) {
                    float* fC = (float*)CoutV;
                    float2 rv = *(const float2*)(&res[dstRow + col]);
                    *(float2*)(&fC[dstRow + col]) = make_float2(rv.x + v0, rv.y + v1);
                } else {
                    float* fC = (float*)CoutV;
                    size_t o = row * N + col;
                    float2 rv = *(const float2*)(&res[o]);
                    *(float2*)(&fC[o]) = make_float2(rv.x + v0, rv.y + v1);
                }
            }
        }
    }
}

// ---------------- windowed attention: fp16 mma, j-table score fixup ---------
#define QPAD 40
#define VPAD 72
__global__ __launch_bounds__(128) void k_attn(const __half* __restrict__ qkv,
                                              const float* __restrict__ rpb,
                                              __half* __restrict__ out) {
    __shared__ __align__(16) __half qs[64][QPAD];
    __shared__ __align__(16) __half ks[56][QPAD];
    __shared__ __align__(16) __half vt[32][VPAD];
    __shared__ __align__(16) __half ps[64][VPAD];
    __shared__ float sbias[169];
    __shared__ int jinfo[56];   // (rj*13+cj)<<4 | (labj+1); 0 = invalid key

    int w = blockIdx.x, h = blockIdx.y, tid = threadIdx.x;
    int wid = tid >> 5, lane = tid & 31;
    int gid = lane >> 2, tig = lane & 3;

    int wi = w & 63, wr = wi >> 3, wc = wi & 7;

    // zero vt fully; zero ps k-pad cols 56..63
    for (int i = tid; i < 32 * (VPAD / 8); i += 128)
        ((uint4*)vt)[i] = make_uint4(0, 0, 0, 0);
    if (tid < 64) *(uint4*)&ps[tid][56] = make_uint4(0, 0, 0, 0);
    // j-tables (once per block)
    if (tid < 56) {
        int j = tid;
        int info = 0;
        if (j < NTOK) {
            int rj = j / 7, cj = j % 7;
            int rsj = wr * 7 + rj, csj = wc * 7 + cj;
            int labj = ((rsj < HIMG - 7) ? 0 : ((rsj < HIMG - SHIFT) ? 1 : 2)) * 3
                     + ((csj < HIMG - 7) ? 0 : ((csj < HIMG - SHIFT) ? 1 : 2));
            info = ((rj * 13 + cj) << 4) | (labj + 1);
        }
        jinfo[j] = info;
    }

    size_t base = (size_t)w * NTOK * C3 + h * HD;
    const __half2 scl2 = __floats2half2_rn(0.17677669529663689f, 0.17677669529663689f);
    for (int idx = tid; idx < NTOK * 4; idx += 128) {
        int n = idx >> 2, c8 = (idx & 3) * 8;
        const __half* rbq = qkv + base + (size_t)n * C3 + c8;
        __half2 q4[4];
        #pragma unroll
        for (int j = 0; j < 4; j++) q4[j] = __hmul2(*(const __half2*)(rbq + 2 * j), scl2);
        *(uint4*)&qs[n][c8] = *(uint4*)q4;
        *(uint4*)&ks[n][c8] = *(const uint4*)(rbq + CDIM);
    }
    for (int idx = tid; idx < NTOK * 32; idx += 128) {
        int n = idx >> 5, d = idx & 31;
        vt[d][n] = qkv[base + (size_t)n * C3 + 2 * CDIM + d];
    }
    for (int i = tid; i < 169; i += 128) sbias[i] = rpb[i * HEADS + h];
    __syncthreads();

    // ---- S = Q @ K^T ----
    int m0 = wid * 16;
    const uint32_t* qsW = (const uint32_t*)qs;
    const uint32_t* ksW = (const uint32_t*)ks;
    float acc[7][4];
    #pragma unroll
    for (int ni = 0; ni < 7; ni++)
        #pragma unroll
        for (int r = 0; r < 4; r++) acc[ni][r] = 0.f;

    #pragma unroll
    for (int kh = 0; kh < 2; kh++) {
        int kb = kh * 8;
        unsigned a[4];
        int r = m0 + gid;
        a[0] = qsW[r * (QPAD / 2) + kb + tig];
        a[1] = qsW[(r + 8) * (QPAD / 2) + kb + tig];
        a[2] = qsW[r * (QPAD / 2) + kb + 4 + tig];
        a[3] = qsW[(r + 8) * (QPAD / 2) + kb + 4 + tig];
        #pragma unroll
        for (int ni = 0; ni < 7; ni++) {
            int j = ni * 8 + gid;
            unsigned b[2];
            b[0] = ksW[j * (QPAD / 2) + kb + tig];
            b[1] = ksW[j * (QPAD / 2) + kb + 4 + tig];
            mma_f16(acc[ni], a, b);
        }
    }

    // ---- bias + mask + softmax in fragments (fp32, j-table) ----
    int r1 = m0 + gid, r2 = r1 + 8;
    int ri1 = r1 / 7, ci1 = r1 % 7, ri2 = r2 / 7, ci2 = r2 % 7;
    int rs1 = wr * 7 + ri1, cs1 = wc * 7 + ci1;
    int rs2 = wr * 7 + ri2, cs2 = wc * 7 + ci2;
    int lab1p = (((rs1 < HIMG - 7) ? 0 : ((rs1 < HIMG - SHIFT) ? 1 : 2)) * 3
              + ((cs1 < HIMG - 7) ? 0 : ((cs1 < HIMG - SHIFT) ? 1 : 2))) + 1;
    int lab2p = (((rs2 < HIMG - 7) ? 0 : ((rs2 < HIMG - SHIFT) ? 1 : 2)) * 3
              + ((cs2 < HIMG - 7) ? 0 : ((cs2 < HIMG - SHIFT) ? 1 : 2))) + 1;
    int base1 = (ri1 + 6) * 13 + (ci1 + 6);
    int base2 = (ri2 + 6) * 13 + (ci2 + 6);
    bool ok1 = (r1 < NTOK), ok2 = (r2 < NTOK);

    float v1[14], v2[14];
    float mx1 = -1e30f, mx2 = -1e30f;
    #pragma unroll
    for (int ni = 0; ni < 7; ni++) {
        #pragma unroll
        for (int bb = 0; bb < 2; bb++) {
            int j = ni * 8 + 2 * tig + bb;
            int info = jinfo[j];
            int labj = info & 15, joff = info >> 4;
            float t1 = -1e30f, t2 = -1e30f;
            if (labj) {
                if (ok1) {
                    t1 = acc[ni][bb] + sbias[base1 - joff];
                    if (lab1p != labj) t1 -= 100.0f;
                }
                if (ok2) {
                    t2 = acc[ni][2 + bb] + sbias[base2 - joff];
                    if (lab2p != labj) t2 -= 100.0f;
                }
            }
            v1[ni * 2 + bb] = t1; v2[ni * 2 + bb] = t2;
            mx1 = fmaxf(mx1, t1); mx2 = fmaxf(mx2, t2);
        }
    }
    #pragma unroll
    for (int o = 1; o < 4; o <<= 1) {
        mx1 = fmaxf(mx1, __shfl_xor_sync(0xffffffffu, mx1, o));
        mx2 = fmaxf(mx2, __shfl_xor_sync(0xffffffffu, mx2, o));
    }
    float s1 = 0.f, s2 = 0.f;
    #pragma unroll
    for (int t = 0; t < 14; t++) {
        v1[t] = __expf(v1[t] - mx1); s1 += v1[t];
        v2[t] = __expf(v2[t] - mx2); s2 += v2[t];
    }
    #pragma unroll
    for (int o = 1; o < 4; o <<= 1) {
        s1 += __shfl_xor_sync(0xffffffffu, s1, o);
        s2 += __shfl_xor_sync(0xffffffffu, s2, o);
    }
    float inv1 = 1.f / s1, inv2 = 1.f / s2;
    #pragma unroll
    for (int ni = 0; ni < 7; ni++) {
        int j = ni * 8 + 2 * tig;
        *(__half2*)&ps[r1][j] = __floats2half2_rn(v1[ni * 2] * inv1, v1[ni * 2 + 1] * inv1);
        *(__half2*)&ps[r2][j] = __floats2half2_rn(v2[ni * 2] * inv2, v2[ni * 2 + 1] * inv2);
    }
    __syncwarp();

    // ---- O = P @ V ----
    const uint32_t* psW = (const uint32_t*)ps;
    const uint32_t* vtW = (const uint32_t*)vt;
    float oacc[4][4];
    #pragma unroll
    for (int ni = 0; ni < 4; ni++)
        #pragma unroll
        for (int r = 0; r < 4; r++) oacc[ni][r] = 0.f;

    #pragma unroll
    for (int kc = 0; kc < 4; kc++) {
        int kb = kc * 8;
        unsigned a[4];
        a[0] = psW[r1 * (VPAD / 2) + kb + tig];
        a[1] = psW[r2 * (VPAD / 2) + kb + tig];
        a[2] = psW[r1 * (VPAD / 2) + kb + 4 + tig];
        a[3] = psW[r2 * (VPAD / 2) + kb + 4 + tig];
        #pragma unroll
        for (int ni = 0; ni < 4; ni++) {
            int d = ni * 8 + gid;
            unsigned b[2];
            b[0] = vtW[d * (VPAD / 2) + kb + tig];
            b[1] = vtW[d * (VPAD / 2) + kb + 4 + tig];
            mma_f16(oacc[ni], a, b);
        }
    }

    #pragma unroll
    for (int half_ = 0; half_ < 2; half_++) {
        int r = (half_ == 0) ? r1 : r2;
        if (r < NTOK) {
            __half* op = out + ((size_t)w * NTOK + r) * CDIM + h * HD;
            #pragma unroll
            for (int ni = 0; ni < 4; ni++)
                *(__half2*)(op + ni * 8 + 2 * tig) =
                    __floats2half2_rn(oacc[ni][half_ * 2], oacc[ni][half_ * 2 + 1]);
        }
    }
}

// ---------------- launch ----------------
extern "C" void kernel_launch(void* const* d_in, const int* in_sizes, int n_in,
                              void* d_out, int out_size) {
    const float* x     = (const float*)d_in[0];
    const float* n1w   = (const float*)d_in[1];
    const float* n1b   = (const float*)d_in[2];
    const float* qkvw  = (const float*)d_in[3];
    const float* qkvb  = (const float*)d_in[4];
    const float* rpb   = (const float*)d_in[5];
    const float* projw = (const float*)d_in[6];
    const float* projb = (const float*)d_in[7];
    const float* n2w   = (const float*)d_in[8];
    const float* n2b   = (const float*)d_in[9];
    const float* fc1w  = (const float*)d_in[10];
    const float* fc1b  = (const float*)d_in[11];
    const float* fc2w  = (const float*)d_in[12];
    const float* fc2b  = (const float*)d_in[13];
    float* out = (float*)d_out;

    __half *p_xw, *p_qkv, *p_att, *p_xn2, *p_hid, *p_wt;
    cudaGetSymbolAddress((void**)&p_xw,  g_xw);
    cudaGetSymbolAddress((void**)&p_qkv, g_qkv);
    cudaGetSymbolAddress((void**)&p_att, g_att);
    cudaGetSymbolAddress((void**)&p_xn2, g_xn2);
    cudaGetSymbolAddress((void**)&p_hid, g_hid);
    cudaGetSymbolAddress((void**)&p_wt,  g_wt);

    cudaFuncSetAttribute(k_mma<0>, cudaFuncAttributeMaxDynamicSharedMemorySize, DSMEM_BYTES);
    cudaFuncSetAttribute(k_mma<1>, cudaFuncAttributeMaxDynamicSharedMemorySize, DSMEM_BYTES);
    cudaFuncSetAttribute(k_mma<2>, cudaFuncAttributeMaxDynamicSharedMemorySize, DSMEM_BYTES);
    cudaFuncSetAttribute(k_mma<3>, cudaFuncAttributeMaxDynamicSharedMemorySize, DSMEM_BYTES);

    // 0) weight prep (single launch)
    k_wprep4<<<1728, 256>>>(qkvw, projw, fc1w, fc2w, p_wt);
    // 1) LN1 + shift + partition (half out)
    k_ln<1><<<NROWS / 8, 256>>>(x, n1w, n1b, p_xw);
    // 2) qkv (half out)
    k_mma<0><<<dim3(C3 / 128, NROWS / 128), 256, DSMEM_BYTES>>>(
        p_xw, p_wt + WT_QKV, qkvb, p_qkv, CDIM, C3, nullptr);
    // 3) attention (fp16 mma)
    k_attn<<<dim3(NROWS / NTOK, HEADS), 128>>>(p_qkv, rpb, p_att);
    // 4) proj + reverse/unshift + residual -> out (fp32)
    k_mma<2><<<dim3(CDIM / 128, NROWS / 128), 256, DSMEM_BYTES>>>(
        p_att, p_wt + WT_PROJ, projb, out, CDIM, CDIM, x);
    // 5) LN2 (half out)
    k_ln<0><<<NROWS / 8, 256>>>(out, n2w, n2b, p_xn2);
    // 6) fc1 + gelu (half out)
    k_mma<1><<<dim3(HIDD / 128, NROWS / 128), 256, DSMEM_BYTES>>>(
        p_xn2, p_wt + WT_FC1, fc1b, p_hid, CDIM, HIDD, nullptr);
    // 7) fc2 + residual (fp32 final)
    k_mma<3><<<dim3(CDIM / 128, NROWS / 128), 256, DSMEM_BYTES>>>(
        p_hid, p_wt + WT_FC2, fc2b, out, HIDD, CDIM, out);
}